// round 4
// baseline (speedup 1.0000x reference)
#include <cuda_runtime.h>

#define NA 100000
#define NC 150000
#define NE 500000

// ---- device scratch (allocation-free rule: static __device__ globals) ----
__device__ float g_qc[NA * 128];   // per-agent: relu(gn(agts@W_q)) @ W_c1[128:256]
__device__ float g_cc[NC * 128];   // per-ctx:   ctx @ W_c1[256:384]
__device__ float g_acc[NA * 128];  // agts@W_agt + scatter-add of edge messages

// GroupNorm(1,128) stats for 4 rows held across a 128-thread slot.
// Block = 256 threads = 2 slots. Contains two __syncthreads (uniform across block).
__device__ __forceinline__ void gn_stats4(const float* v, float* sred, int slot, int wslot,
                                          float* mu, float* rs) {
    float s[4], q[4];
#pragma unroll
    for (int e = 0; e < 4; e++) { s[e] = v[e]; q[e] = v[e] * v[e]; }
#pragma unroll
    for (int o = 16; o > 0; o >>= 1) {
#pragma unroll
        for (int e = 0; e < 4; e++) {
            s[e] += __shfl_xor_sync(0xffffffffu, s[e], o);
            q[e] += __shfl_xor_sync(0xffffffffu, q[e], o);
        }
    }
    if ((threadIdx.x & 31) == 0) {
#pragma unroll
        for (int e = 0; e < 4; e++) {
            sred[((slot * 4 + e) * 4 + wslot) * 2 + 0] = s[e];
            sred[((slot * 4 + e) * 4 + wslot) * 2 + 1] = q[e];
        }
    }
    __syncthreads();
#pragma unroll
    for (int e = 0; e < 4; e++) {
        float ts = 0.f, tq = 0.f;
#pragma unroll
        for (int wv = 0; wv < 4; wv++) {
            ts += sred[((slot * 4 + e) * 4 + wv) * 2 + 0];
            tq += sred[((slot * 4 + e) * 4 + wv) * 2 + 1];
        }
        float m = ts * 0.0078125f;
        float var = tq * 0.0078125f - m * m;
        mu[e] = m;
        rs[e] = rsqrtf(var + 1e-5f);
    }
    __syncthreads();
}

// ================= K1: per-agent precompute =================
// t = agts@W_q ; q = relu(gn(t)) ; g_qc = q@W_mid ; g_acc = agts@W_agt
__global__ __launch_bounds__(256, 1) void k_agent(
    const float* __restrict__ agts,
    const float* __restrict__ Wq, const float* __restrict__ gq, const float* __restrict__ bq,
    const float* __restrict__ Wmid, const float* __restrict__ Wagt)
{
    extern __shared__ float sm[];
    float* sWq = sm;                 // 16384
    float* sWa = sm + 16384;         // 16384
    float* sWm = sm + 32768;         // 16384
    float* sgq = sm + 49152;         // 128
    float* sbq = sm + 49280;         // 128
    float* sx  = sm + 49408;         // 1024 (2 slots * 4 rows * 128)
    float* sred = sm + 50432;        // 64
    int tid = threadIdx.x;
    for (int i = tid; i < 16384; i += 256) { sWq[i] = Wq[i]; sWa[i] = Wagt[i]; sWm[i] = Wmid[i]; }
    if (tid < 128) { sgq[tid] = gq[tid]; sbq[tid] = bq[tid]; }
    __syncthreads();

    int slot = tid >> 7, j = tid & 127, wslot = (tid >> 5) & 3;
    float* xs = sx + slot * 4 * 128;

    for (int base = blockIdx.x * 8; base < NA; base += gridDim.x * 8) {
        int r0 = base + slot * 4;
#pragma unroll
        for (int e = 0; e < 4; e++) {
            int row = r0 + e;
            xs[e * 128 + j] = (row < NA) ? agts[row * 128 + j] : 0.f;
        }
        __syncthreads();
        float t[4] = {0, 0, 0, 0}, a[4] = {0, 0, 0, 0};
#pragma unroll 2
        for (int k = 0; k < 128; k += 4) {
            float q0 = sWq[(k + 0) * 128 + j], q1 = sWq[(k + 1) * 128 + j];
            float q2 = sWq[(k + 2) * 128 + j], q3 = sWq[(k + 3) * 128 + j];
            float a0 = sWa[(k + 0) * 128 + j], a1 = sWa[(k + 1) * 128 + j];
            float a2 = sWa[(k + 2) * 128 + j], a3 = sWa[(k + 3) * 128 + j];
#pragma unroll
            for (int e = 0; e < 4; e++) {
                float4 xv = *(const float4*)(xs + e * 128 + k);
                t[e] = fmaf(xv.x, q0, t[e]); t[e] = fmaf(xv.y, q1, t[e]);
                t[e] = fmaf(xv.z, q2, t[e]); t[e] = fmaf(xv.w, q3, t[e]);
                a[e] = fmaf(xv.x, a0, a[e]); a[e] = fmaf(xv.y, a1, a[e]);
                a[e] = fmaf(xv.z, a2, a[e]); a[e] = fmaf(xv.w, a3, a[e]);
            }
        }
        float mu[4], rsd[4];
        gn_stats4(t, sred, slot, wslot, mu, rsd);
#pragma unroll
        for (int e = 0; e < 4; e++)
            xs[e * 128 + j] = fmaxf((t[e] - mu[e]) * rsd[e] * sgq[j] + sbq[j], 0.f);
        __syncthreads();
        float qc[4] = {0, 0, 0, 0};
#pragma unroll 2
        for (int k = 0; k < 128; k += 4) {
            float w0 = sWm[(k + 0) * 128 + j], w1 = sWm[(k + 1) * 128 + j];
            float w2 = sWm[(k + 2) * 128 + j], w3 = sWm[(k + 3) * 128 + j];
#pragma unroll
            for (int e = 0; e < 4; e++) {
                float4 xv = *(const float4*)(xs + e * 128 + k);
                qc[e] = fmaf(xv.x, w0, qc[e]); qc[e] = fmaf(xv.y, w1, qc[e]);
                qc[e] = fmaf(xv.z, w2, qc[e]); qc[e] = fmaf(xv.w, w3, qc[e]);
            }
        }
#pragma unroll
        for (int e = 0; e < 4; e++) {
            int row = r0 + e;
            if (row < NA) { g_qc[row * 128 + j] = qc[e]; g_acc[row * 128 + j] = a[e]; }
        }
        __syncthreads();
    }
}

// ================= K2: per-ctx precompute: g_cc = ctx @ W_c1[256:384] =================
__global__ __launch_bounds__(256) void k_ctx(
    const float* __restrict__ ctx, const float* __restrict__ Wctx)
{
    extern __shared__ float sm[];
    float* sW = sm;          // 16384
    float* sx = sm + 16384;  // 1024
    int tid = threadIdx.x;
    for (int i = tid; i < 16384; i += 256) sW[i] = Wctx[i];
    __syncthreads();
    int slot = tid >> 7, j = tid & 127;
    float* xs = sx + slot * 4 * 128;
    for (int base = blockIdx.x * 8; base < NC; base += gridDim.x * 8) {
        int r0 = base + slot * 4;
#pragma unroll
        for (int e = 0; e < 4; e++) {
            int row = r0 + e;
            xs[e * 128 + j] = (row < NC) ? ctx[row * 128 + j] : 0.f;
        }
        __syncthreads();
        float v[4] = {0, 0, 0, 0};
#pragma unroll 2
        for (int k = 0; k < 128; k += 4) {
            float w0 = sW[(k + 0) * 128 + j], w1 = sW[(k + 1) * 128 + j];
            float w2 = sW[(k + 2) * 128 + j], w3 = sW[(k + 3) * 128 + j];
#pragma unroll
            for (int e = 0; e < 4; e++) {
                float4 xv = *(const float4*)(xs + e * 128 + k);
                v[e] = fmaf(xv.x, w0, v[e]); v[e] = fmaf(xv.y, w1, v[e]);
                v[e] = fmaf(xv.z, w2, v[e]); v[e] = fmaf(xv.w, w3, v[e]);
            }
        }
#pragma unroll
        for (int e = 0; e < 4; e++) {
            int row = r0 + e;
            if (row < NC) g_cc[row * 128 + j] = v[e];
        }
        __syncthreads();
    }
}

// ================= K3: per-edge fused MLP chain + scatter =================
__global__ __launch_bounds__(256, 1) void k_edge(
    const float* __restrict__ actr, const float* __restrict__ cctr,
    const int* __restrict__ hi, const int* __restrict__ wi,
    const float* __restrict__ W1, const float* __restrict__ b1,
    const float* __restrict__ W2, const float* __restrict__ gd, const float* __restrict__ bd,
    const float* __restrict__ Wc1d, const float* __restrict__ gc1, const float* __restrict__ bc1,
    const float* __restrict__ Wc2)
{
    extern __shared__ float sm[];
    float* sW2 = sm;               // 16384 (W_dist2)
    float* sWc = sm + 16384;       // 16384 (W_c1[0:128])
    float* sWo = sm + 32768;       // 16384 (W_c2)
    float* sW1 = sm + 49152;       // 256
    float* sb1 = sm + 49408;       // 128
    float* sgd = sm + 49536;       // 128
    float* sbd = sm + 49664;       // 128
    float* sgc = sm + 49792;       // 128
    float* sbc = sm + 49920;       // 128
    float* sx  = sm + 50048;       // 1024
    float* sred = sm + 51072;      // 64
    int tid = threadIdx.x;
    for (int i = tid; i < 16384; i += 256) { sW2[i] = W2[i]; sWc[i] = Wc1d[i]; sWo[i] = Wc2[i]; }
    sW1[tid] = W1[tid];
    if (tid < 128) {
        sb1[tid] = b1[tid]; sgd[tid] = gd[tid]; sbd[tid] = bd[tid];
        sgc[tid] = gc1[tid]; sbc[tid] = bc1[tid];
    }
    __syncthreads();

    int slot = tid >> 7, j = tid & 127, wslot = (tid >> 5) & 3;
    float* xs = sx + slot * 4 * 128;

    for (int base = blockIdx.x * 8; base < NE; base += gridDim.x * 8) {
        int h[4], w[4];
#pragma unroll
        for (int e = 0; e < 4; e++) {
            int idx = base + slot * 4 + e;
            if (idx < NE) { h[e] = hi[idx]; w[e] = wi[idx]; } else { h[e] = -1; w[e] = 0; }
            float t = 0.f;
            if (h[e] >= 0) {
                float dx = actr[2 * h[e]] - cctr[2 * w[e]];
                float dy = actr[2 * h[e] + 1] - cctr[2 * w[e] + 1];
                t = fmaxf(fmaf(dx, sW1[j], fmaf(dy, sW1[128 + j], sb1[j])), 0.f);
            }
            xs[e * 128 + j] = t;
        }
        __syncthreads();

        // u = xs @ W_dist2
        float u[4] = {0, 0, 0, 0};
#pragma unroll 2
        for (int k = 0; k < 128; k += 4) {
            float w0 = sW2[(k + 0) * 128 + j], w1 = sW2[(k + 1) * 128 + j];
            float w2 = sW2[(k + 2) * 128 + j], w3 = sW2[(k + 3) * 128 + j];
#pragma unroll
            for (int e = 0; e < 4; e++) {
                float4 xv = *(const float4*)(xs + e * 128 + k);
                u[e] = fmaf(xv.x, w0, u[e]); u[e] = fmaf(xv.y, w1, u[e]);
                u[e] = fmaf(xv.z, w2, u[e]); u[e] = fmaf(xv.w, w3, u[e]);
            }
        }
        float mu[4], rsd[4];
        gn_stats4(u, sred, slot, wslot, mu, rsd);
#pragma unroll
        for (int e = 0; e < 4; e++)
            xs[e * 128 + j] = fmaxf((u[e] - mu[e]) * rsd[e] * sgd[j] + sbd[j], 0.f);
        __syncthreads();

        // v = d@W_c1_d + qc[hi] + cc[wi]
        float v[4];
#pragma unroll
        for (int e = 0; e < 4; e++)
            v[e] = (h[e] >= 0) ? (g_qc[h[e] * 128 + j] + g_cc[w[e] * 128 + j]) : 0.f;
#pragma unroll 2
        for (int k = 0; k < 128; k += 4) {
            float w0 = sWc[(k + 0) * 128 + j], w1 = sWc[(k + 1) * 128 + j];
            float w2 = sWc[(k + 2) * 128 + j], w3 = sWc[(k + 3) * 128 + j];
#pragma unroll
            for (int e = 0; e < 4; e++) {
                float4 xv = *(const float4*)(xs + e * 128 + k);
                v[e] = fmaf(xv.x, w0, v[e]); v[e] = fmaf(xv.y, w1, v[e]);
                v[e] = fmaf(xv.z, w2, v[e]); v[e] = fmaf(xv.w, w3, v[e]);
            }
        }
        gn_stats4(v, sred, slot, wslot, mu, rsd);
#pragma unroll
        for (int e = 0; e < 4; e++)
            xs[e * 128 + j] = fmaxf((v[e] - mu[e]) * rsd[e] * sgc[j] + sbc[j], 0.f);
        __syncthreads();

        // m = w @ W_c2 ; scatter
        float m[4] = {0, 0, 0, 0};
#pragma unroll 2
        for (int k = 0; k < 128; k += 4) {
            float w0 = sWo[(k + 0) * 128 + j], w1 = sWo[(k + 1) * 128 + j];
            float w2 = sWo[(k + 2) * 128 + j], w3 = sWo[(k + 3) * 128 + j];
#pragma unroll
            for (int e = 0; e < 4; e++) {
                float4 xv = *(const float4*)(xs + e * 128 + k);
                m[e] = fmaf(xv.x, w0, m[e]); m[e] = fmaf(xv.y, w1, m[e]);
                m[e] = fmaf(xv.z, w2, m[e]); m[e] = fmaf(xv.w, w3, m[e]);
            }
        }
#pragma unroll
        for (int e = 0; e < 4; e++)
            if (h[e] >= 0) atomicAdd(&g_acc[h[e] * 128 + j], m[e]);
        __syncthreads();
    }
}

// ================= K4: final per-agent =================
__global__ __launch_bounds__(256) void k_final(
    const float* __restrict__ agts,
    const float* __restrict__ gnw, const float* __restrict__ bnw,
    const float* __restrict__ Wlin, const float* __restrict__ gl, const float* __restrict__ bl,
    float* __restrict__ out)
{
    extern __shared__ float sm[];
    float* sW  = sm;           // 16384
    float* sgn = sm + 16384;   // 128
    float* sbn = sm + 16512;
    float* sgl = sm + 16640;
    float* sbl = sm + 16768;
    float* sx  = sm + 16896;   // 1024
    float* sred = sm + 17920;  // 64
    int tid = threadIdx.x;
    for (int i = tid; i < 16384; i += 256) sW[i] = Wlin[i];
    if (tid < 128) { sgn[tid] = gnw[tid]; sbn[tid] = bnw[tid]; sgl[tid] = gl[tid]; sbl[tid] = bl[tid]; }
    __syncthreads();

    int slot = tid >> 7, j = tid & 127, wslot = (tid >> 5) & 3;
    float* xs = sx + slot * 4 * 128;

    for (int base = blockIdx.x * 8; base < NA; base += gridDim.x * 8) {
        int r0 = base + slot * 4;
        float a[4];
#pragma unroll
        for (int e = 0; e < 4; e++) {
            int row = r0 + e;
            a[e] = (row < NA) ? g_acc[row * 128 + j] : 0.f;
        }
        float mu[4], rsd[4];
        gn_stats4(a, sred, slot, wslot, mu, rsd);
#pragma unroll
        for (int e = 0; e < 4; e++)
            xs[e * 128 + j] = fmaxf((a[e] - mu[e]) * rsd[e] * sgn[j] + sbn[j], 0.f);
        __syncthreads();
        float y[4] = {0, 0, 0, 0};
#pragma unroll 2
        for (int k = 0; k < 128; k += 4) {
            float w0 = sW[(k + 0) * 128 + j], w1 = sW[(k + 1) * 128 + j];
            float w2 = sW[(k + 2) * 128 + j], w3 = sW[(k + 3) * 128 + j];
#pragma unroll
            for (int e = 0; e < 4; e++) {
                float4 xv = *(const float4*)(xs + e * 128 + k);
                y[e] = fmaf(xv.x, w0, y[e]); y[e] = fmaf(xv.y, w1, y[e]);
                y[e] = fmaf(xv.z, w2, y[e]); y[e] = fmaf(xv.w, w3, y[e]);
            }
        }
        gn_stats4(y, sred, slot, wslot, mu, rsd);
#pragma unroll
        for (int e = 0; e < 4; e++) {
            int row = r0 + e;
            if (row < NA) {
                float yy = (y[e] - mu[e]) * rsd[e] * sgl[j] + sbl[j];
                out[row * 128 + j] = fmaxf(yy + agts[row * 128 + j], 0.f);
            }
        }
        __syncthreads();
    }
}

// ================= host =================
extern "C" void kernel_launch(void* const* d_in, const int* in_sizes, int n_in,
                              void* d_out, int out_size)
{
    const float* agts    = (const float*)d_in[0];
    const float* ctx     = (const float*)d_in[1];
    const float* actr    = (const float*)d_in[2];
    const float* cctr    = (const float*)d_in[3];
    const float* W_dist1 = (const float*)d_in[4];
    const float* b_dist1 = (const float*)d_in[5];
    const float* W_dist2 = (const float*)d_in[6];
    const float* g_dist  = (const float*)d_in[7];
    const float* b_dist  = (const float*)d_in[8];
    const float* W_q     = (const float*)d_in[9];
    const float* g_q     = (const float*)d_in[10];
    const float* b_q     = (const float*)d_in[11];
    const float* W_c1    = (const float*)d_in[12];
    const float* g_c1    = (const float*)d_in[13];
    const float* b_c1    = (const float*)d_in[14];
    const float* W_c2    = (const float*)d_in[15];
    const float* W_agt   = (const float*)d_in[16];
    const float* g_n     = (const float*)d_in[17];
    const float* b_n     = (const float*)d_in[18];
    const float* W_lin   = (const float*)d_in[19];
    const float* g_lin   = (const float*)d_in[20];
    const float* b_lin   = (const float*)d_in[21];
    const int*   hi      = (const int*)d_in[22];
    const int*   wi      = (const int*)d_in[23];
    float* out = (float*)d_out;

    const int S1 = 50496 * 4;  // k_agent
    const int S2 = 17408 * 4;  // k_ctx
    const int S3 = 51136 * 4;  // k_edge
    const int S4 = 17984 * 4;  // k_final
    cudaFuncSetAttribute(k_agent, cudaFuncAttributeMaxDynamicSharedMemorySize, S1);
    cudaFuncSetAttribute(k_ctx,   cudaFuncAttributeMaxDynamicSharedMemorySize, S2);
    cudaFuncSetAttribute(k_edge,  cudaFuncAttributeMaxDynamicSharedMemorySize, S3);
    cudaFuncSetAttribute(k_final, cudaFuncAttributeMaxDynamicSharedMemorySize, S4);

    k_agent<<<152, 256, S1>>>(agts, W_q, g_q, b_q, W_c1 + 128 * 128, W_agt);
    k_ctx  <<<444, 256, S2>>>(ctx, W_c1 + 256 * 128);
    k_edge <<<152, 256, S3>>>(actr, cctr, hi, wi,
                              W_dist1, b_dist1, W_dist2, g_dist, b_dist,
                              W_c1, g_c1, b_c1, W_c2);
    k_final<<<444, 256, S4>>>(agts, g_n, b_n, W_lin, g_lin, b_lin, out);
}

// round 5
// speedup vs baseline: 2.2876x; 2.2876x over previous
#include <cuda_runtime.h>
#include <cuda_bf16.h>

typedef unsigned int uint;

#define NA 100000
#define NC 150000
#define NE 500000

// ---- device scratch ----
__device__ float g_qc[NA * 128];
__device__ float g_cc[NC * 128];
__device__ float g_acc[NA * 128];

// ============================================================
// bf16 split helpers
// ============================================================
__device__ __forceinline__ unsigned short bfb(__nv_bfloat16 h) {
    return ((__nv_bfloat16_raw)h).x;
}

// split (a,b) fp32 pair into hi/lo bf16x2 words and store
__device__ __forceinline__ void split_store(uint* xh, uint* xl, int idx, float a, float b) {
    __nv_bfloat16 ah = __float2bfloat16(a), bh = __float2bfloat16(b);
    float ra = a - __bfloat162float(ah);
    float rb = b - __bfloat162float(bh);
    __nv_bfloat16 al = __float2bfloat16(ra), bl = __float2bfloat16(rb);
    xh[idx] = (uint)bfb(ah) | ((uint)bfb(bh) << 16);
    xl[idx] = (uint)bfb(al) | ((uint)bfb(bl) << 16);
}

__device__ __forceinline__ void mma16816(float c[4], uint a0, uint a1, uint a2, uint a3,
                                         uint b0, uint b1) {
    asm volatile(
        "mma.sync.aligned.m16n8k16.row.col.f32.bf16.bf16.f32 "
        "{%0,%1,%2,%3}, {%4,%5,%6,%7}, {%8,%9}, {%0,%1,%2,%3};\n"
        : "+f"(c[0]), "+f"(c[1]), "+f"(c[2]), "+f"(c[3])
        : "r"(a0), "r"(a1), "r"(a2), "r"(a3), "r"(b0), "r"(b1));
}

// D[64 x 128] += X[64 x 128] @ W[128 x 128], bf16-split (hi*hi + hi*lo + lo*hi)
// This warp: rows r0..r0+7, r0+8..r0+15 ; cols nbase .. nbase+63
__device__ __forceinline__ void gemm_bf16split(
    const uint* __restrict__ xh, const uint* __restrict__ xl,
    const uint* __restrict__ wh, const uint* __restrict__ wl,
    float acc[8][4], int r0, int g, int tg, int nbase)
{
    const int g4 = g << 2;
    const int ra = r0 * 64, rb = (r0 + 8) * 64;
#pragma unroll
    for (int ks = 0; ks < 8; ks++) {
        int kz0 = (tg + 8 * ks) ^ g4;
        int kz1 = kz0 ^ 4;
        uint ah0 = xh[ra + kz0], ah1 = xh[rb + kz0], ah2 = xh[ra + kz1], ah3 = xh[rb + kz1];
        uint al0 = xl[ra + kz0], al1 = xl[rb + kz0], al2 = xl[ra + kz1], al3 = xl[rb + kz1];
#pragma unroll
        for (int t = 0; t < 8; t++) {
            int nw = (nbase + 8 * t + g) * 64;
            uint bh0 = wh[nw + kz0], bh1 = wh[nw + kz1];
            uint bl0 = wl[nw + kz0], bl1 = wl[nw + kz1];
            mma16816(acc[t], ah0, ah1, ah2, ah3, bh0, bh1);
            mma16816(acc[t], ah0, ah1, ah2, ah3, bl0, bl1);
            mma16816(acc[t], al0, al1, al2, al3, bh0, bh1);
        }
    }
}

// GroupNorm(1,128) over fragment rows + relu + split-store back to X smem.
// Contains 2 __syncthreads (uniform across block).
__device__ __forceinline__ void gn_relu_split_store(
    float acc[8][4], uint* xh, uint* xl, float* sred,
    const float* __restrict__ gamma, const float* __restrict__ beta,
    int r0, int g, int tg, int cb)
{
    float s0 = 0, q0 = 0, s1 = 0, q1 = 0;
#pragma unroll
    for (int t = 0; t < 8; t++) {
        s0 += acc[t][0] + acc[t][1];
        q0 += acc[t][0] * acc[t][0] + acc[t][1] * acc[t][1];
        s1 += acc[t][2] + acc[t][3];
        q1 += acc[t][2] * acc[t][2] + acc[t][3] * acc[t][3];
    }
#pragma unroll
    for (int o = 1; o <= 2; o <<= 1) {
        s0 += __shfl_xor_sync(0xffffffffu, s0, o);
        q0 += __shfl_xor_sync(0xffffffffu, q0, o);
        s1 += __shfl_xor_sync(0xffffffffu, s1, o);
        q1 += __shfl_xor_sync(0xffffffffu, q1, o);
    }
    if (tg == 0) {
        sred[r0 * 4 + cb * 2 + 0] = s0;
        sred[r0 * 4 + cb * 2 + 1] = q0;
        sred[(r0 + 8) * 4 + cb * 2 + 0] = s1;
        sred[(r0 + 8) * 4 + cb * 2 + 1] = q1;
    }
    __syncthreads();
    float sa = sred[r0 * 4 + 0] + sred[r0 * 4 + 2];
    float qa = sred[r0 * 4 + 1] + sred[r0 * 4 + 3];
    float sb = sred[(r0 + 8) * 4 + 0] + sred[(r0 + 8) * 4 + 2];
    float qb = sred[(r0 + 8) * 4 + 1] + sred[(r0 + 8) * 4 + 3];
    float mu0 = sa * 0.0078125f;
    float rs0 = rsqrtf(qa * 0.0078125f - mu0 * mu0 + 1e-5f);
    float mu1 = sb * 0.0078125f;
    float rs1 = rsqrtf(qb * 0.0078125f - mu1 * mu1 + 1e-5f);
    const int g4 = g << 2;
#pragma unroll
    for (int t = 0; t < 8; t++) {
        int col0 = 64 * cb + 8 * t + 2 * tg;
        float ga = __ldg(gamma + col0), gb = __ldg(gamma + col0 + 1);
        float ba = __ldg(beta + col0), bb = __ldg(beta + col0 + 1);
        float e0 = fmaxf((acc[t][0] - mu0) * rs0 * ga + ba, 0.f);
        float e1 = fmaxf((acc[t][1] - mu0) * rs0 * gb + bb, 0.f);
        float e2 = fmaxf((acc[t][2] - mu1) * rs1 * ga + ba, 0.f);
        float e3 = fmaxf((acc[t][3] - mu1) * rs1 * gb + bb, 0.f);
        int cw = 32 * cb + 4 * t + tg;
        split_store(xh, xl, r0 * 64 + (cw ^ g4), e0, e1);
        split_store(xh, xl, (r0 + 8) * 64 + (cw ^ g4), e2, e3);
    }
    __syncthreads();
}

// ============================================================
// K3 (MMA): per-edge fused 3-layer MLP + scatter
// ============================================================
// smem word layout:
//   [0)      W_dist2 hi   8192 words   (Wp[n][kw] XOR-swizzled)
//   [8192)   W_dist2 lo   8192
//   [16384)  W_c1d  hi    8192
//   [24576)  W_c1d  lo    8192
//   [32768)  W_c2   hi    8192
//   [40960)  W_c2   lo    8192
//   [49152)  X hi         4096  (64 rows x 64 words)
//   [53248)  X lo         4096
//   [57344)  sred         256 f32
//   [57600)  sh           64 int
//   [57664)  sw           64 int
//   [57728)  sdx          64 f32
//   [57792)  sdy          64 f32     -> total 57856 words = 231424 B
__global__ __launch_bounds__(256, 1) void k_edge_mma(
    const float* __restrict__ actr, const float* __restrict__ cctr,
    const int* __restrict__ hi, const int* __restrict__ wi,
    const float* __restrict__ W1, const float* __restrict__ b1,
    const float* __restrict__ W2, const float* __restrict__ gd, const float* __restrict__ bd,
    const float* __restrict__ Wc1d, const float* __restrict__ gc1, const float* __restrict__ bc1,
    const float* __restrict__ Wc2)
{
    extern __shared__ uint usm[];
    uint* xh = usm + 49152;
    uint* xl = usm + 53248;
    float* sred = (float*)(usm + 57344);
    int* sh = (int*)(usm + 57600);
    int* sw = (int*)(usm + 57664);
    float* sdx = (float*)(usm + 57728);
    float* sdy = (float*)(usm + 57792);

    const int tid = threadIdx.x;

    // ---- one-time: transpose + bf16-split weights into smem ----
    {
        const float* srcs[3] = { W2, Wc1d, Wc2 };
#pragma unroll 1
        for (int m = 0; m < 3; m++) {
            const float* S = srcs[m];
            uint* dh = usm + m * 16384;
            uint* dl = dh + 8192;
            for (int idx = tid; idx < 8192; idx += 256) {
                int kp = idx >> 7, n = idx & 127;
                float w0 = S[(2 * kp) * 128 + n];
                float w1 = S[(2 * kp + 1) * 128 + n];
                split_store(dh, dl, n * 64 + (kp ^ ((n & 7) << 2)), w0, w1);
            }
        }
    }
    __syncthreads();

    const int lane = tid & 31;
    const int wid = tid >> 5;
    const int g = lane >> 2;       // fragment group id (row/col within 8)
    const int tg = lane & 3;       // thread-in-group
    const int stripe = wid >> 1;   // 0..3 -> rows 16*stripe
    const int cb = wid & 1;        // col half
    const int r0 = 16 * stripe + g;

    const int NT = (NE + 63) / 64;
    for (int tile = blockIdx.x; tile < NT; tile += gridDim.x) {
        const int base = tile * 64;

        // ---- stage edge indices + center deltas ----
        if (tid < 64) {
            int eg = base + tid;
            if (eg < NE) {
                int h = hi[eg], w = wi[eg];
                sh[tid] = h; sw[tid] = w;
                sdx[tid] = actr[2 * h] - cctr[2 * w];
                sdy[tid] = actr[2 * h + 1] - cctr[2 * w + 1];
            } else {
                sh[tid] = -1; sw[tid] = 0; sdx[tid] = 0.f; sdy[tid] = 0.f;
            }
        }
        __syncthreads();

        // ---- build X1 = relu(dist @ W1 + b1), split to bf16 hi/lo ----
        for (int idx = tid; idx < 4096; idx += 256) {
            int e = idx >> 6, kw = idx & 63;
            float v0 = 0.f, v1 = 0.f;
            if (sh[e] >= 0) {
                int j0 = kw * 2;
                float dx = sdx[e], dy = sdy[e];
                v0 = fmaxf(fmaf(dx, __ldg(W1 + j0), fmaf(dy, __ldg(W1 + 128 + j0), __ldg(b1 + j0))), 0.f);
                v1 = fmaxf(fmaf(dx, __ldg(W1 + j0 + 1), fmaf(dy, __ldg(W1 + 128 + j0 + 1), __ldg(b1 + j0 + 1))), 0.f);
            }
            split_store(xh, xl, e * 64 + (kw ^ ((e & 7) << 2)), v0, v1);
        }
        __syncthreads();

        float acc[8][4];

        // ---- GEMM1: U = X1 @ W_dist2 ; GN(g_dist) + relu -> X ----
#pragma unroll
        for (int t = 0; t < 8; t++) { acc[t][0] = acc[t][1] = acc[t][2] = acc[t][3] = 0.f; }
        gemm_bf16split(xh, xl, usm + 0, usm + 8192, acc, r0, g, tg, 64 * cb);
        gn_relu_split_store(acc, xh, xl, sred, gd, bd, r0, g, tg, cb);

        // ---- GEMM2: V = D @ W_c1d + qc[hi] + cc[wi] ; GN(g_c1) + relu -> X ----
        {
            int h0 = sh[r0], w0i = sw[r0];
            int h1 = sh[r0 + 8], w1i = sw[r0 + 8];
#pragma unroll
            for (int t = 0; t < 8; t++) {
                int col0 = 64 * cb + 8 * t + 2 * tg;
                if (h0 >= 0) {
                    acc[t][0] = g_qc[h0 * 128 + col0] + g_cc[w0i * 128 + col0];
                    acc[t][1] = g_qc[h0 * 128 + col0 + 1] + g_cc[w0i * 128 + col0 + 1];
                } else { acc[t][0] = acc[t][1] = 0.f; }
                if (h1 >= 0) {
                    acc[t][2] = g_qc[h1 * 128 + col0] + g_cc[w1i * 128 + col0];
                    acc[t][3] = g_qc[h1 * 128 + col0 + 1] + g_cc[w1i * 128 + col0 + 1];
                } else { acc[t][2] = acc[t][3] = 0.f; }
            }
        }
        gemm_bf16split(xh, xl, usm + 16384, usm + 24576, acc, r0, g, tg, 64 * cb);
        gn_relu_split_store(acc, xh, xl, sred, gc1, bc1, r0, g, tg, cb);

        // ---- GEMM3: M = W @ W_c2 ; scatter-add into g_acc ----
#pragma unroll
        for (int t = 0; t < 8; t++) { acc[t][0] = acc[t][1] = acc[t][2] = acc[t][3] = 0.f; }
        gemm_bf16split(xh, xl, usm + 32768, usm + 40960, acc, r0, g, tg, 64 * cb);
        {
            int h0 = sh[r0], h1 = sh[r0 + 8];
#pragma unroll
            for (int t = 0; t < 8; t++) {
                int col0 = 64 * cb + 8 * t + 2 * tg;
                if (h0 >= 0) {
                    atomicAdd(g_acc + h0 * 128 + col0, acc[t][0]);
                    atomicAdd(g_acc + h0 * 128 + col0 + 1, acc[t][1]);
                }
                if (h1 >= 0) {
                    atomicAdd(g_acc + h1 * 128 + col0, acc[t][2]);
                    atomicAdd(g_acc + h1 * 128 + col0 + 1, acc[t][3]);
                }
            }
        }
        __syncthreads();  // protect sh/sdx/X before next tile overwrites
    }
}

// ============================================================
// SIMT kernels (unchanged from passing round): K1, K2, K4
// ============================================================
__device__ __forceinline__ void gn_stats4(const float* v, float* sred, int slot, int wslot,
                                          float* mu, float* rs) {
    float s[4], q[4];
#pragma unroll
    for (int e = 0; e < 4; e++) { s[e] = v[e]; q[e] = v[e] * v[e]; }
#pragma unroll
    for (int o = 16; o > 0; o >>= 1) {
#pragma unroll
        for (int e = 0; e < 4; e++) {
            s[e] += __shfl_xor_sync(0xffffffffu, s[e], o);
            q[e] += __shfl_xor_sync(0xffffffffu, q[e], o);
        }
    }
    if ((threadIdx.x & 31) == 0) {
#pragma unroll
        for (int e = 0; e < 4; e++) {
            sred[((slot * 4 + e) * 4 + wslot) * 2 + 0] = s[e];
            sred[((slot * 4 + e) * 4 + wslot) * 2 + 1] = q[e];
        }
    }
    __syncthreads();
#pragma unroll
    for (int e = 0; e < 4; e++) {
        float ts = 0.f, tq = 0.f;
#pragma unroll
        for (int wv = 0; wv < 4; wv++) {
            ts += sred[((slot * 4 + e) * 4 + wv) * 2 + 0];
            tq += sred[((slot * 4 + e) * 4 + wv) * 2 + 1];
        }
        float m = ts * 0.0078125f;
        float var = tq * 0.0078125f - m * m;
        mu[e] = m;
        rs[e] = rsqrtf(var + 1e-5f);
    }
    __syncthreads();
}

__global__ __launch_bounds__(256, 1) void k_agent(
    const float* __restrict__ agts,
    const float* __restrict__ Wq, const float* __restrict__ gq, const float* __restrict__ bq,
    const float* __restrict__ Wmid, const float* __restrict__ Wagt)
{
    extern __shared__ float sm[];
    float* sWq = sm;
    float* sWa = sm + 16384;
    float* sWm = sm + 32768;
    float* sgq = sm + 49152;
    float* sbq = sm + 49280;
    float* sx  = sm + 49408;
    float* sred = sm + 50432;
    int tid = threadIdx.x;
    for (int i = tid; i < 16384; i += 256) { sWq[i] = Wq[i]; sWa[i] = Wagt[i]; sWm[i] = Wmid[i]; }
    if (tid < 128) { sgq[tid] = gq[tid]; sbq[tid] = bq[tid]; }
    __syncthreads();

    int slot = tid >> 7, j = tid & 127, wslot = (tid >> 5) & 3;
    float* xs = sx + slot * 4 * 128;

    for (int base = blockIdx.x * 8; base < NA; base += gridDim.x * 8) {
        int r0 = base + slot * 4;
#pragma unroll
        for (int e = 0; e < 4; e++) {
            int row = r0 + e;
            xs[e * 128 + j] = (row < NA) ? agts[row * 128 + j] : 0.f;
        }
        __syncthreads();
        float t[4] = {0, 0, 0, 0}, a[4] = {0, 0, 0, 0};
#pragma unroll 2
        for (int k = 0; k < 128; k += 4) {
            float q0 = sWq[(k + 0) * 128 + j], q1 = sWq[(k + 1) * 128 + j];
            float q2 = sWq[(k + 2) * 128 + j], q3 = sWq[(k + 3) * 128 + j];
            float a0 = sWa[(k + 0) * 128 + j], a1 = sWa[(k + 1) * 128 + j];
            float a2 = sWa[(k + 2) * 128 + j], a3 = sWa[(k + 3) * 128 + j];
#pragma unroll
            for (int e = 0; e < 4; e++) {
                float4 xv = *(const float4*)(xs + e * 128 + k);
                t[e] = fmaf(xv.x, q0, t[e]); t[e] = fmaf(xv.y, q1, t[e]);
                t[e] = fmaf(xv.z, q2, t[e]); t[e] = fmaf(xv.w, q3, t[e]);
                a[e] = fmaf(xv.x, a0, a[e]); a[e] = fmaf(xv.y, a1, a[e]);
                a[e] = fmaf(xv.z, a2, a[e]); a[e] = fmaf(xv.w, a3, a[e]);
            }
        }
        float mu[4], rsd[4];
        gn_stats4(t, sred, slot, wslot, mu, rsd);
#pragma unroll
        for (int e = 0; e < 4; e++)
            xs[e * 128 + j] = fmaxf((t[e] - mu[e]) * rsd[e] * sgq[j] + sbq[j], 0.f);
        __syncthreads();
        float qc[4] = {0, 0, 0, 0};
#pragma unroll 2
        for (int k = 0; k < 128; k += 4) {
            float w0 = sWm[(k + 0) * 128 + j], w1 = sWm[(k + 1) * 128 + j];
            float w2 = sWm[(k + 2) * 128 + j], w3 = sWm[(k + 3) * 128 + j];
#pragma unroll
            for (int e = 0; e < 4; e++) {
                float4 xv = *(const float4*)(xs + e * 128 + k);
                qc[e] = fmaf(xv.x, w0, qc[e]); qc[e] = fmaf(xv.y, w1, qc[e]);
                qc[e] = fmaf(xv.z, w2, qc[e]); qc[e] = fmaf(xv.w, w3, qc[e]);
            }
        }
#pragma unroll
        for (int e = 0; e < 4; e++) {
            int row = r0 + e;
            if (row < NA) { g_qc[row * 128 + j] = qc[e]; g_acc[row * 128 + j] = a[e]; }
        }
        __syncthreads();
    }
}

__global__ __launch_bounds__(256) void k_ctx(
    const float* __restrict__ ctx, const float* __restrict__ Wctx)
{
    extern __shared__ float sm[];
    float* sW = sm;
    float* sx = sm + 16384;
    int tid = threadIdx.x;
    for (int i = tid; i < 16384; i += 256) sW[i] = Wctx[i];
    __syncthreads();
    int slot = tid >> 7, j = tid & 127;
    float* xs = sx + slot * 4 * 128;
    for (int base = blockIdx.x * 8; base < NC; base += gridDim.x * 8) {
        int r0 = base + slot * 4;
#pragma unroll
        for (int e = 0; e < 4; e++) {
            int row = r0 + e;
            xs[e * 128 + j] = (row < NC) ? ctx[row * 128 + j] : 0.f;
        }
        __syncthreads();
        float v[4] = {0, 0, 0, 0};
#pragma unroll 2
        for (int k = 0; k < 128; k += 4) {
            float w0 = sW[(k + 0) * 128 + j], w1 = sW[(k + 1) * 128 + j];
            float w2 = sW[(k + 2) * 128 + j], w3 = sW[(k + 3) * 128 + j];
#pragma unroll
            for (int e = 0; e < 4; e++) {
                float4 xv = *(const float4*)(xs + e * 128 + k);
                v[e] = fmaf(xv.x, w0, v[e]); v[e] = fmaf(xv.y, w1, v[e]);
                v[e] = fmaf(xv.z, w2, v[e]); v[e] = fmaf(xv.w, w3, v[e]);
            }
        }
#pragma unroll
        for (int e = 0; e < 4; e++) {
            int row = r0 + e;
            if (row < NC) g_cc[row * 128 + j] = v[e];
        }
        __syncthreads();
    }
}

__global__ __launch_bounds__(256) void k_final(
    const float* __restrict__ agts,
    const float* __restrict__ gnw, const float* __restrict__ bnw,
    const float* __restrict__ Wlin, const float* __restrict__ gl, const float* __restrict__ bl,
    float* __restrict__ out)
{
    extern __shared__ float sm[];
    float* sW  = sm;
    float* sgn = sm + 16384;
    float* sbn = sm + 16512;
    float* sgl = sm + 16640;
    float* sbl = sm + 16768;
    float* sx  = sm + 16896;
    float* sred = sm + 17920;
    int tid = threadIdx.x;
    for (int i = tid; i < 16384; i += 256) sW[i] = Wlin[i];
    if (tid < 128) { sgn[tid] = gnw[tid]; sbn[tid] = bnw[tid]; sgl[tid] = gl[tid]; sbl[tid] = bl[tid]; }
    __syncthreads();

    int slot = tid >> 7, j = tid & 127, wslot = (tid >> 5) & 3;
    float* xs = sx + slot * 4 * 128;

    for (int base = blockIdx.x * 8; base < NA; base += gridDim.x * 8) {
        int r0 = base + slot * 4;
        float a[4];
#pragma unroll
        for (int e = 0; e < 4; e++) {
            int row = r0 + e;
            a[e] = (row < NA) ? g_acc[row * 128 + j] : 0.f;
        }
        float mu[4], rsd[4];
        gn_stats4(a, sred, slot, wslot, mu, rsd);
#pragma unroll
        for (int e = 0; e < 4; e++)
            xs[e * 128 + j] = fmaxf((a[e] - mu[e]) * rsd[e] * sgn[j] + sbn[j], 0.f);
        __syncthreads();
        float y[4] = {0, 0, 0, 0};
#pragma unroll 2
        for (int k = 0; k < 128; k += 4) {
            float w0 = sW[(k + 0) * 128 + j], w1 = sW[(k + 1) * 128 + j];
            float w2 = sW[(k + 2) * 128 + j], w3 = sW[(k + 3) * 128 + j];
#pragma unroll
            for (int e = 0; e < 4; e++) {
                float4 xv = *(const float4*)(xs + e * 128 + k);
                y[e] = fmaf(xv.x, w0, y[e]); y[e] = fmaf(xv.y, w1, y[e]);
                y[e] = fmaf(xv.z, w2, y[e]); y[e] = fmaf(xv.w, w3, y[e]);
            }
        }
        gn_stats4(y, sred, slot, wslot, mu, rsd);
#pragma unroll
        for (int e = 0; e < 4; e++) {
            int row = r0 + e;
            if (row < NA) {
                float yy = (y[e] - mu[e]) * rsd[e] * sgl[j] + sbl[j];
                out[row * 128 + j] = fmaxf(yy + agts[row * 128 + j], 0.f);
            }
        }
        __syncthreads();
    }
}

// ================= host =================
extern "C" void kernel_launch(void* const* d_in, const int* in_sizes, int n_in,
                              void* d_out, int out_size)
{
    const float* agts    = (const float*)d_in[0];
    const float* ctx     = (const float*)d_in[1];
    const float* actr    = (const float*)d_in[2];
    const float* cctr    = (const float*)d_in[3];
    const float* W_dist1 = (const float*)d_in[4];
    const float* b_dist1 = (const float*)d_in[5];
    const float* W_dist2 = (const float*)d_in[6];
    const float* g_dist  = (const float*)d_in[7];
    const float* b_dist  = (const float*)d_in[8];
    const float* W_q     = (const float*)d_in[9];
    const float* g_q     = (const float*)d_in[10];
    const float* b_q     = (const float*)d_in[11];
    const float* W_c1    = (const float*)d_in[12];
    const float* g_c1    = (const float*)d_in[13];
    const float* b_c1    = (const float*)d_in[14];
    const float* W_c2    = (const float*)d_in[15];
    const float* W_agt   = (const float*)d_in[16];
    const float* g_n     = (const float*)d_in[17];
    const float* b_n     = (const float*)d_in[18];
    const float* W_lin   = (const float*)d_in[19];
    const float* g_lin   = (const float*)d_in[20];
    const float* b_lin   = (const float*)d_in[21];
    const int*   hi      = (const int*)d_in[22];
    const int*   wi      = (const int*)d_in[23];
    float* out = (float*)d_out;

    const int S1 = 50496 * 4;   // k_agent
    const int S2 = 17408 * 4;   // k_ctx
    const int S3 = 231424;      // k_edge_mma
    const int S4 = 17984 * 4;   // k_final
    cudaFuncSetAttribute(k_agent,    cudaFuncAttributeMaxDynamicSharedMemorySize, S1);
    cudaFuncSetAttribute(k_ctx,      cudaFuncAttributeMaxDynamicSharedMemorySize, S2);
    cudaFuncSetAttribute(k_edge_mma, cudaFuncAttributeMaxDynamicSharedMemorySize, S3);
    cudaFuncSetAttribute(k_final,    cudaFuncAttributeMaxDynamicSharedMemorySize, S4);

    k_agent<<<152, 256, S1>>>(agts, W_q, g_q, b_q, W_c1 + 128 * 128, W_agt);
    k_ctx  <<<444, 256, S2>>>(ctx, W_c1 + 256 * 128);
    k_edge_mma<<<152, 256, S3>>>(actr, cctr, hi, wi,
                                 W_dist1, b_dist1, W_dist2, g_dist, b_dist,
                                 W_c1, g_c1, b_c1, W_c2);
    k_final<<<444, 256, S4>>>(agts, g_n, b_n, W_lin, g_lin, b_lin, out);
}

// round 9
// speedup vs baseline: 3.5754x; 1.5630x over previous
#include <cuda_runtime.h>
#include <cuda_bf16.h>

typedef unsigned int uint;

#define NA 100000
#define NC 150000
#define NE 500000

// ---- device scratch ----
__device__ float g_qc[NA * 128];
__device__ float g_cc[NC * 128];
__device__ float g_acc[NA * 128];

// ============================================================
// bf16 split helpers
// ============================================================
__device__ __forceinline__ unsigned short bfb(__nv_bfloat16 h) {
    return ((__nv_bfloat16_raw)h).x;
}

// split (a,b) fp32 pair into hi/lo bf16x2 words and store
__device__ __forceinline__ void split_store(uint* xh, uint* xl, int idx, float a, float b) {
    __nv_bfloat16 ah = __float2bfloat16(a), bh = __float2bfloat16(b);
    float ra = a - __bfloat162float(ah);
    float rb = b - __bfloat162float(bh);
    __nv_bfloat16 al = __float2bfloat16(ra), bl = __float2bfloat16(rb);
    xh[idx] = (uint)bfb(ah) | ((uint)bfb(bh) << 16);
    xl[idx] = (uint)bfb(al) | ((uint)bfb(bl) << 16);
}

__device__ __forceinline__ void mma16816(float c[4], uint a0, uint a1, uint a2, uint a3,
                                         uint b0, uint b1) {
    asm volatile(
        "mma.sync.aligned.m16n8k16.row.col.f32.bf16.bf16.f32 "
        "{%0,%1,%2,%3}, {%4,%5,%6,%7}, {%8,%9}, {%0,%1,%2,%3};\n"
        : "+f"(c[0]), "+f"(c[1]), "+f"(c[2]), "+f"(c[3])
        : "r"(a0), "r"(a1), "r"(a2), "r"(a3), "r"(b0), "r"(b1));
}

// D[64 x 128] += X[64 x 128] @ W[128 x 128], bf16-split (hi*hi + hi*lo + lo*hi)
// This warp: rows r0..r0+7, r0+8..r0+15 ; cols nbase .. nbase+63
__device__ __forceinline__ void gemm_bf16split(
    const uint* __restrict__ xh, const uint* __restrict__ xl,
    const uint* __restrict__ wh, const uint* __restrict__ wl,
    float acc[8][4], int r0, int g, int tg, int nbase)
{
    const int g4 = g << 2;
    const int ra = r0 * 64, rb = (r0 + 8) * 64;
#pragma unroll
    for (int ks = 0; ks < 8; ks++) {
        int kz0 = (tg + 8 * ks) ^ g4;
        int kz1 = kz0 ^ 4;
        uint ah0 = xh[ra + kz0], ah1 = xh[rb + kz0], ah2 = xh[ra + kz1], ah3 = xh[rb + kz1];
        uint al0 = xl[ra + kz0], al1 = xl[rb + kz0], al2 = xl[ra + kz1], al3 = xl[rb + kz1];
#pragma unroll
        for (int t = 0; t < 8; t++) {
            int nw = (nbase + 8 * t + g) * 64;
            uint bh0 = wh[nw + kz0], bh1 = wh[nw + kz1];
            uint bl0 = wl[nw + kz0], bl1 = wl[nw + kz1];
            mma16816(acc[t], ah0, ah1, ah2, ah3, bh0, bh1);
            mma16816(acc[t], ah0, ah1, ah2, ah3, bl0, bl1);
            mma16816(acc[t], al0, al1, al2, al3, bh0, bh1);
        }
    }
}

// One-time: transpose + bf16-split a 128x128 weight matrix into smem (XOR swizzled)
__device__ __forceinline__ void load_weight(const float* __restrict__ S, uint* dh, uint* dl, int tid) {
    for (int idx = tid; idx < 8192; idx += 256) {
        int kp = idx >> 7, n = idx & 127;
        split_store(dh, dl, n * 64 + (kp ^ ((n & 7) << 2)),
                    S[(2 * kp) * 128 + n], S[(2 * kp + 1) * 128 + n]);
    }
}

// Load 64 contiguous rows [row0, row0+64) of src[limit x 128] into split X smem
__device__ __forceinline__ void load_split_rows(const float* __restrict__ src, int row0, int limit,
                                                uint* xh, uint* xl, int tid) {
    for (int idx = tid; idx < 4096; idx += 256) {
        int e = idx >> 6, kw = idx & 63;
        int row = row0 + e;
        float2 v = make_float2(0.f, 0.f);
        if (row < limit) v = __ldg((const float2*)(src + (size_t)row * 128) + kw);
        split_store(xh, xl, e * 64 + (kw ^ ((e & 7) << 2)), v.x, v.y);
    }
}

// GroupNorm(1,128) over fragment rows + relu + split-store back to X smem.
// Contains 2 __syncthreads (uniform across block).
__device__ __forceinline__ void gn_relu_split_store(
    float acc[8][4], uint* xh, uint* xl, float* sred,
    const float* __restrict__ gamma, const float* __restrict__ beta,
    int r0, int g, int tg, int cb)
{
    float s0 = 0, q0 = 0, s1 = 0, q1 = 0;
#pragma unroll
    for (int t = 0; t < 8; t++) {
        s0 += acc[t][0] + acc[t][1];
        q0 += acc[t][0] * acc[t][0] + acc[t][1] * acc[t][1];
        s1 += acc[t][2] + acc[t][3];
        q1 += acc[t][2] * acc[t][2] + acc[t][3] * acc[t][3];
    }
#pragma unroll
    for (int o = 1; o <= 2; o <<= 1) {
        s0 += __shfl_xor_sync(0xffffffffu, s0, o);
        q0 += __shfl_xor_sync(0xffffffffu, q0, o);
        s1 += __shfl_xor_sync(0xffffffffu, s1, o);
        q1 += __shfl_xor_sync(0xffffffffu, q1, o);
    }
    if (tg == 0) {
        sred[r0 * 4 + cb * 2 + 0] = s0;
        sred[r0 * 4 + cb * 2 + 1] = q0;
        sred[(r0 + 8) * 4 + cb * 2 + 0] = s1;
        sred[(r0 + 8) * 4 + cb * 2 + 1] = q1;
    }
    __syncthreads();
    float sa = sred[r0 * 4 + 0] + sred[r0 * 4 + 2];
    float qa = sred[r0 * 4 + 1] + sred[r0 * 4 + 3];
    float sb = sred[(r0 + 8) * 4 + 0] + sred[(r0 + 8) * 4 + 2];
    float qb = sred[(r0 + 8) * 4 + 1] + sred[(r0 + 8) * 4 + 3];
    float mu0 = sa * 0.0078125f;
    float rs0 = rsqrtf(qa * 0.0078125f - mu0 * mu0 + 1e-5f);
    float mu1 = sb * 0.0078125f;
    float rs1 = rsqrtf(qb * 0.0078125f - mu1 * mu1 + 1e-5f);
    const int g4 = g << 2;
#pragma unroll
    for (int t = 0; t < 8; t++) {
        int col0 = 64 * cb + 8 * t + 2 * tg;
        float ga = __ldg(gamma + col0), gb = __ldg(gamma + col0 + 1);
        float ba = __ldg(beta + col0), bb = __ldg(beta + col0 + 1);
        float e0 = fmaxf((acc[t][0] - mu0) * rs0 * ga + ba, 0.f);
        float e1 = fmaxf((acc[t][1] - mu0) * rs0 * gb + bb, 0.f);
        float e2 = fmaxf((acc[t][2] - mu1) * rs1 * ga + ba, 0.f);
        float e3 = fmaxf((acc[t][3] - mu1) * rs1 * gb + bb, 0.f);
        int cw = 32 * cb + 4 * t + tg;
        split_store(xh, xl, r0 * 64 + (cw ^ g4), e0, e1);
        split_store(xh, xl, (r0 + 8) * 64 + (cw ^ g4), e2, e3);
    }
    __syncthreads();
}

// Store fragment accumulators (raw fp32) to dst rows [row0g-based], guarded.
__device__ __forceinline__ void store_frag(float* __restrict__ dst, float acc[8][4],
                                           int row0g, int limit, int r0, int tg, int cb) {
    int rowA = row0g + r0, rowB = row0g + r0 + 8;
#pragma unroll
    for (int t = 0; t < 8; t++) {
        int col0 = 64 * cb + 8 * t + 2 * tg;
        if (rowA < limit)
            *(float2*)(dst + (size_t)rowA * 128 + col0) = make_float2(acc[t][0], acc[t][1]);
        if (rowB < limit)
            *(float2*)(dst + (size_t)rowB * 128 + col0) = make_float2(acc[t][2], acc[t][3]);
    }
}

// ============================================================
// K3 (MMA): per-edge fused 3-layer MLP + scatter  (R5 proven + float2 gathers)
// ============================================================
__global__ __launch_bounds__(256, 1) void k_edge_mma(
    const float* __restrict__ actr, const float* __restrict__ cctr,
    const int* __restrict__ hi, const int* __restrict__ wi,
    const float* __restrict__ W1, const float* __restrict__ b1,
    const float* __restrict__ W2, const float* __restrict__ gd, const float* __restrict__ bd,
    const float* __restrict__ Wc1d, const float* __restrict__ gc1, const float* __restrict__ bc1,
    const float* __restrict__ Wc2)
{
    extern __shared__ uint usm[];
    uint* xh = usm + 49152;
    uint* xl = usm + 53248;
    float* sred = (float*)(usm + 57344);
    int* sh = (int*)(usm + 57600);
    int* sw = (int*)(usm + 57664);
    float* sdx = (float*)(usm + 57728);
    float* sdy = (float*)(usm + 57792);

    const int tid = threadIdx.x;

    load_weight(W2,   usm + 0,     usm + 8192,  tid);
    load_weight(Wc1d, usm + 16384, usm + 24576, tid);
    load_weight(Wc2,  usm + 32768, usm + 40960, tid);
    __syncthreads();

    const int lane = tid & 31;
    const int wid = tid >> 5;
    const int g = lane >> 2;
    const int tg = lane & 3;
    const int stripe = wid >> 1;
    const int cb = wid & 1;
    const int r0 = 16 * stripe + g;

    const int NT = (NE + 63) / 64;
    for (int tile = blockIdx.x; tile < NT; tile += gridDim.x) {
        const int base = tile * 64;

        if (tid < 64) {
            int eg = base + tid;
            if (eg < NE) {
                int h = hi[eg], w = wi[eg];
                sh[tid] = h; sw[tid] = w;
                sdx[tid] = actr[2 * h] - cctr[2 * w];
                sdy[tid] = actr[2 * h + 1] - cctr[2 * w + 1];
            } else {
                sh[tid] = -1; sw[tid] = 0; sdx[tid] = 0.f; sdy[tid] = 0.f;
            }
        }
        __syncthreads();

        // X1 = relu(dist @ W1 + b1)
        for (int idx = tid; idx < 4096; idx += 256) {
            int e = idx >> 6, kw = idx & 63;
            float v0 = 0.f, v1 = 0.f;
            if (sh[e] >= 0) {
                int j0 = kw * 2;
                float dx = sdx[e], dy = sdy[e];
                v0 = fmaxf(fmaf(dx, __ldg(W1 + j0), fmaf(dy, __ldg(W1 + 128 + j0), __ldg(b1 + j0))), 0.f);
                v1 = fmaxf(fmaf(dx, __ldg(W1 + j0 + 1), fmaf(dy, __ldg(W1 + 128 + j0 + 1), __ldg(b1 + j0 + 1))), 0.f);
            }
            split_store(xh, xl, e * 64 + (kw ^ ((e & 7) << 2)), v0, v1);
        }
        __syncthreads();

        float acc[8][4];

        // GEMM1 + GN(g_dist)
#pragma unroll
        for (int t = 0; t < 8; t++) { acc[t][0] = acc[t][1] = acc[t][2] = acc[t][3] = 0.f; }
        gemm_bf16split(xh, xl, usm + 0, usm + 8192, acc, r0, g, tg, 64 * cb);
        gn_relu_split_store(acc, xh, xl, sred, gd, bd, r0, g, tg, cb);

        // GEMM2 (+ qc[hi] + cc[wi] preloaded) + GN(g_c1)
        {
            int h0 = sh[r0], w0i = sw[r0];
            int h1 = sh[r0 + 8], w1i = sw[r0 + 8];
            const float2* pq0 = (h0 >= 0) ? (const float2*)(g_qc + (size_t)h0 * 128) : 0;
            const float2* pc0 = (h0 >= 0) ? (const float2*)(g_cc + (size_t)w0i * 128) : 0;
            const float2* pq1 = (h1 >= 0) ? (const float2*)(g_qc + (size_t)h1 * 128) : 0;
            const float2* pc1 = (h1 >= 0) ? (const float2*)(g_cc + (size_t)w1i * 128) : 0;
#pragma unroll
            for (int t = 0; t < 8; t++) {
                int ci = (64 * cb + 8 * t + 2 * tg) >> 1;
                if (h0 >= 0) {
                    float2 a2 = __ldg(pq0 + ci), b2 = __ldg(pc0 + ci);
                    acc[t][0] = a2.x + b2.x; acc[t][1] = a2.y + b2.y;
                } else { acc[t][0] = acc[t][1] = 0.f; }
                if (h1 >= 0) {
                    float2 a2 = __ldg(pq1 + ci), b2 = __ldg(pc1 + ci);
                    acc[t][2] = a2.x + b2.x; acc[t][3] = a2.y + b2.y;
                } else { acc[t][2] = acc[t][3] = 0.f; }
            }
        }
        gemm_bf16split(xh, xl, usm + 16384, usm + 24576, acc, r0, g, tg, 64 * cb);
        gn_relu_split_store(acc, xh, xl, sred, gc1, bc1, r0, g, tg, cb);

        // GEMM3 + scatter
#pragma unroll
        for (int t = 0; t < 8; t++) { acc[t][0] = acc[t][1] = acc[t][2] = acc[t][3] = 0.f; }
        gemm_bf16split(xh, xl, usm + 32768, usm + 40960, acc, r0, g, tg, 64 * cb);
        {
            int h0 = sh[r0], h1 = sh[r0 + 8];
#pragma unroll
            for (int t = 0; t < 8; t++) {
                int col0 = 64 * cb + 8 * t + 2 * tg;
                if (h0 >= 0) {
                    atomicAdd(g_acc + (size_t)h0 * 128 + col0, acc[t][0]);
                    atomicAdd(g_acc + (size_t)h0 * 128 + col0 + 1, acc[t][1]);
                }
                if (h1 >= 0) {
                    atomicAdd(g_acc + (size_t)h1 * 128 + col0, acc[t][2]);
                    atomicAdd(g_acc + (size_t)h1 * 128 + col0 + 1, acc[t][3]);
                }
            }
        }
        __syncthreads();
    }
}

// ============================================================
// K1 (MMA): per-agent precompute
//   g_acc = agts @ Wagt ; t = agts @ Wq ; x = relu(gn(t)) ; g_qc = x @ Wmid
// smem words: mats 3*16384 = 49152 ; xh @49152 (4096) ; xl @53248 (4096) ; sred @57344 (256)
// ============================================================
__global__ __launch_bounds__(256, 1) void k_agent_mma(
    const float* __restrict__ agts,
    const float* __restrict__ Wq, const float* __restrict__ gq, const float* __restrict__ bq,
    const float* __restrict__ Wmid, const float* __restrict__ Wagt)
{
    extern __shared__ uint usm[];
    uint* xh = usm + 49152;
    uint* xl = usm + 53248;
    float* sred = (float*)(usm + 57344);
    const int tid = threadIdx.x;

    load_weight(Wq,   usm + 0,     usm + 8192,  tid);
    load_weight(Wagt, usm + 16384, usm + 24576, tid);
    load_weight(Wmid, usm + 32768, usm + 40960, tid);
    __syncthreads();

    const int lane = tid & 31;
    const int wid = tid >> 5;
    const int g = lane >> 2;
    const int tg = lane & 3;
    const int stripe = wid >> 1;
    const int cb = wid & 1;
    const int r0 = 16 * stripe + g;

    const int NT = (NA + 63) / 64;
    for (int tile = blockIdx.x; tile < NT; tile += gridDim.x) {
        const int row0 = tile * 64;
        load_split_rows(agts, row0, NA, xh, xl, tid);
        __syncthreads();

        float acc[8][4];
        // Wagt pass -> g_acc (raw X still needed afterwards, store first)
#pragma unroll
        for (int t = 0; t < 8; t++) { acc[t][0] = acc[t][1] = acc[t][2] = acc[t][3] = 0.f; }
        gemm_bf16split(xh, xl, usm + 16384, usm + 24576, acc, r0, g, tg, 64 * cb);
        store_frag(g_acc, acc, row0, NA, r0, tg, cb);

        // Wq pass -> GN(g_q) + relu -> xs
#pragma unroll
        for (int t = 0; t < 8; t++) { acc[t][0] = acc[t][1] = acc[t][2] = acc[t][3] = 0.f; }
        gemm_bf16split(xh, xl, usm + 0, usm + 8192, acc, r0, g, tg, 64 * cb);
        gn_relu_split_store(acc, xh, xl, sred, gq, bq, r0, g, tg, cb);

        // Wmid pass -> g_qc
#pragma unroll
        for (int t = 0; t < 8; t++) { acc[t][0] = acc[t][1] = acc[t][2] = acc[t][3] = 0.f; }
        gemm_bf16split(xh, xl, usm + 32768, usm + 40960, acc, r0, g, tg, 64 * cb);
        store_frag(g_qc, acc, row0, NA, r0, tg, cb);
        __syncthreads();
    }
}

// ============================================================
// K2 (MMA): g_cc = ctx @ Wctx
// smem words: mat 16384 ; xh @16384 ; xl @20480  (= 98304 B, 2 CTAs/SM)
// ============================================================
__global__ __launch_bounds__(256, 2) void k_ctx_mma(
    const float* __restrict__ ctx, const float* __restrict__ Wctx)
{
    extern __shared__ uint usm[];
    uint* xh = usm + 16384;
    uint* xl = usm + 20480;
    const int tid = threadIdx.x;

    load_weight(Wctx, usm + 0, usm + 8192, tid);
    __syncthreads();

    const int lane = tid & 31;
    const int wid = tid >> 5;
    const int g = lane >> 2;
    const int tg = lane & 3;
    const int stripe = wid >> 1;
    const int cb = wid & 1;
    const int r0 = 16 * stripe + g;

    const int NT = (NC + 63) / 64;
    for (int tile = blockIdx.x; tile < NT; tile += gridDim.x) {
        const int row0 = tile * 64;
        load_split_rows(ctx, row0, NC, xh, xl, tid);
        __syncthreads();

        float acc[8][4];
#pragma unroll
        for (int t = 0; t < 8; t++) { acc[t][0] = acc[t][1] = acc[t][2] = acc[t][3] = 0.f; }
        gemm_bf16split(xh, xl, usm + 0, usm + 8192, acc, r0, g, tg, 64 * cb);
        store_frag(g_cc, acc, row0, NC, r0, tg, cb);
        __syncthreads();
    }
}

// ============================================================
// K4 (MMA): out = relu(gn(relu(gn(g_acc)) @ Wlin) + agts)
// smem words: mat 16384 ; xh @16384 ; xl @20480 ; sred @24576 (256) = 99328 B
// ============================================================
__global__ __launch_bounds__(256, 2) void k_final_mma(
    const float* __restrict__ agts,
    const float* __restrict__ gnw, const float* __restrict__ bnw,
    const float* __restrict__ Wlin, const float* __restrict__ gl, const float* __restrict__ bl,
    float* __restrict__ out)
{
    extern __shared__ uint usm[];
    uint* xh = usm + 16384;
    uint* xl = usm + 20480;
    float* sred = (float*)(usm + 24576);
    const int tid = threadIdx.x;

    load_weight(Wlin, usm + 0, usm + 8192, tid);
    __syncthreads();

    const int lane = tid & 31;
    const int wid = tid >> 5;
    const int g = lane >> 2;
    const int tg = lane & 3;
    const int stripe = wid >> 1;
    const int cb = wid & 1;
    const int r0 = 16 * stripe + g;
    // phase-A mapping: 4 threads per row
    const int arow = tid >> 2;     // 0..63
    const int apart = tid & 3;     // 0..3 (32 cols each)

    const int NT = (NA + 63) / 64;
    for (int tile = blockIdx.x; tile < NT; tile += gridDim.x) {
        const int row0 = tile * 64;

        // ---- phase A: SIMT GN(g_n)+relu on g_acc rows -> split X smem ----
        {
            int rowg = row0 + arow;
            float v[32];
            if (rowg < NA) {
                const float4* p = (const float4*)(g_acc + (size_t)rowg * 128 + apart * 32);
#pragma unroll
                for (int q = 0; q < 8; q++) {
                    float4 f = __ldg(p + q);
                    v[4 * q] = f.x; v[4 * q + 1] = f.y; v[4 * q + 2] = f.z; v[4 * q + 3] = f.w;
                }
            } else {
#pragma unroll
                for (int q = 0; q < 32; q++) v[q] = 0.f;
            }
            float s = 0.f, qq = 0.f;
#pragma unroll
            for (int q = 0; q < 32; q++) { s += v[q]; qq += v[q] * v[q]; }
            s += __shfl_xor_sync(0xffffffffu, s, 1);
            qq += __shfl_xor_sync(0xffffffffu, qq, 1);
            s += __shfl_xor_sync(0xffffffffu, s, 2);
            qq += __shfl_xor_sync(0xffffffffu, qq, 2);
            float mu = s * 0.0078125f;
            float rs = rsqrtf(qq * 0.0078125f - mu * mu + 1e-5f);
            int sw4 = (arow & 7) << 2;
#pragma unroll
            for (int j = 0; j < 16; j++) {
                int c = apart * 32 + 2 * j;
                float e0 = fmaxf((v[2 * j] - mu) * rs * __ldg(gnw + c) + __ldg(bnw + c), 0.f);
                float e1 = fmaxf((v[2 * j + 1] - mu) * rs * __ldg(gnw + c + 1) + __ldg(bnw + c + 1), 0.f);
                int kw = apart * 16 + j;
                split_store(xh, xl, arow * 64 + (kw ^ sw4), e0, e1);
            }
        }
        __syncthreads();

        // ---- GEMM Wlin ----
        float acc[8][4];
#pragma unroll
        for (int t = 0; t < 8; t++) { acc[t][0] = acc[t][1] = acc[t][2] = acc[t][3] = 0.f; }
        gemm_bf16split(xh, xl, usm + 0, usm + 8192, acc, r0, g, tg, 64 * cb);

        // ---- GN(g_lin) (no relu) + residual + relu -> out ----
        {
            float s0 = 0, q0 = 0, s1 = 0, q1 = 0;
#pragma unroll
            for (int t = 0; t < 8; t++) {
                s0 += acc[t][0] + acc[t][1];
                q0 += acc[t][0] * acc[t][0] + acc[t][1] * acc[t][1];
                s1 += acc[t][2] + acc[t][3];
                q1 += acc[t][2] * acc[t][2] + acc[t][3] * acc[t][3];
            }
#pragma unroll
            for (int o = 1; o <= 2; o <<= 1) {
                s0 += __shfl_xor_sync(0xffffffffu, s0, o);
                q0 += __shfl_xor_sync(0xffffffffu, q0, o);
                s1 += __shfl_xor_sync(0xffffffffu, s1, o);
                q1 += __shfl_xor_sync(0xffffffffu, q1, o);
            }
            if (tg == 0) {
                sred[r0 * 4 + cb * 2 + 0] = s0;
                sred[r0 * 4 + cb * 2 + 1] = q0;
                sred[(r0 + 8) * 4 + cb * 2 + 0] = s1;
                sred[(r0 + 8) * 4 + cb * 2 + 1] = q1;
            }
            __syncthreads();
            float sa = sred[r0 * 4 + 0] + sred[r0 * 4 + 2];
            float qa = sred[r0 * 4 + 1] + sred[r0 * 4 + 3];
            float sb = sred[(r0 + 8) * 4 + 0] + sred[(r0 + 8) * 4 + 2];
            float qb = sred[(r0 + 8) * 4 + 1] + sred[(r0 + 8) * 4 + 3];
            float mu0 = sa * 0.0078125f;
            float rs0 = rsqrtf(qa * 0.0078125f - mu0 * mu0 + 1e-5f);
            float mu1 = sb * 0.0078125f;
            float rs1 = rsqrtf(qb * 0.0078125f - mu1 * mu1 + 1e-5f);
            int rowA = row0 + r0, rowB = row0 + r0 + 8;
#pragma unroll
            for (int t = 0; t < 8; t++) {
                int col0 = 64 * cb + 8 * t + 2 * tg;
                float ga = __ldg(gl + col0), gb = __ldg(gl + col0 + 1);
                float ba = __ldg(bl + col0), bb = __ldg(bl + col0 + 1);
                if (rowA < NA) {
                    float2 res = __ldg((const float2*)(agts + (size_t)rowA * 128) + (col0 >> 1));
                    float y0 = fmaxf((acc[t][0] - mu0) * rs0 * ga + ba + res.x, 0.f);
                    float y1 = fmaxf((acc[t][1] - mu0) * rs0 * gb + bb + res.y, 0.f);
                    *(float2*)(out + (size_t)rowA * 128 + col0) = make_float2(y0, y1);
                }
                if (rowB < NA) {
                    float2 res = __ldg((const float2*)(agts + (size_t)rowB * 128) + (col0 >> 1));
                    float y2 = fmaxf((acc[t][2] - mu1) * rs1 * ga + ba + res.x, 0.f);
                    float y3 = fmaxf((acc[t][3] - mu1) * rs1 * gb + bb + res.y, 0.f);
                    *(float2*)(out + (size_t)rowB * 128 + col0) = make_float2(y2, y3);
                }
            }
        }
        __syncthreads();
    }
}

// ================= host =================
extern "C" void kernel_launch(void* const* d_in, const int* in_sizes, int n_in,
                              void* d_out, int out_size)
{
    const float* agts    = (const float*)d_in[0];
    const float* ctx     = (const float*)d_in[1];
    const float* actr    = (const float*)d_in[2];
    const float* cctr    = (const float*)d_in[3];
    const float* W_dist1 = (const float*)d_in[4];
    const float* b_dist1 = (const float*)d_in[5];
    const float* W_dist2 = (const float*)d_in[6];
    const float* g_dist  = (const float*)d_in[7];
    const float* b_dist  = (const float*)d_in[8];
    const float* W_q     = (const float*)d_in[9];
    const float* g_q     = (const float*)d_in[10];
    const float* b_q     = (const float*)d_in[11];
    const float* W_c1    = (const float*)d_in[12];
    const float* g_c1    = (const float*)d_in[13];
    const float* b_c1    = (const float*)d_in[14];
    const float* W_c2    = (const float*)d_in[15];
    const float* W_agt   = (const float*)d_in[16];
    const float* g_n     = (const float*)d_in[17];
    const float* b_n     = (const float*)d_in[18];
    const float* W_lin   = (const float*)d_in[19];
    const float* g_lin   = (const float*)d_in[20];
    const float* b_lin   = (const float*)d_in[21];
    const int*   hi      = (const int*)d_in[22];
    const int*   wi      = (const int*)d_in[23];
    float* out = (float*)d_out;

    const int S1 = 57600 * 4;   // k_agent_mma  (230400 B)
    const int S2 = 24576 * 4;   // k_ctx_mma    (98304 B)
    const int S3 = 231424;      // k_edge_mma
    const int S4 = 24832 * 4;   // k_final_mma  (99328 B)
    cudaFuncSetAttribute(k_agent_mma, cudaFuncAttributeMaxDynamicSharedMemorySize, S1);
    cudaFuncSetAttribute(k_ctx_mma,   cudaFuncAttributeMaxDynamicSharedMemorySize, S2);
    cudaFuncSetAttribute(k_edge_mma,  cudaFuncAttributeMaxDynamicSharedMemorySize, S3);
    cudaFuncSetAttribute(k_final_mma, cudaFuncAttributeMaxDynamicSharedMemorySize, S4);

    k_agent_mma<<<152, 256, S1>>>(agts, W_q, g_q, b_q, W_c1 + 128 * 128, W_agt);
    k_ctx_mma  <<<304, 256, S2>>>(ctx, W_c1 + 256 * 128);
    k_edge_mma <<<152, 256, S3>>>(actr, cctr, hi, wi,
                                  W_dist1, b_dist1, W_dist2, g_dist, b_dist,
                                  W_c1, g_c1, b_c1, W_c2);
    k_final_mma<<<304, 256, S4>>>(agts, g_n, b_n, W_lin, g_lin, b_lin, out);
}

// round 10
// speedup vs baseline: 3.6312x; 1.0156x over previous
#include <cuda_runtime.h>
#include <cuda_bf16.h>

typedef unsigned int uint;

#define NA 100000
#define NC 150000
#define NE 500000

// ---- device scratch ----
__device__ float g_qc[NA * 128];
__device__ float g_cc[NC * 128];
__device__ float g_acc[NA * 128];

// ============================================================
// bf16 split helpers
// ============================================================
__device__ __forceinline__ unsigned short bfb(__nv_bfloat16 h) {
    return ((__nv_bfloat16_raw)h).x;
}

// split (a,b) fp32 pair into hi/lo bf16x2 words and store
__device__ __forceinline__ void split_store(uint* xh, uint* xl, int idx, float a, float b) {
    __nv_bfloat16 ah = __float2bfloat16(a), bh = __float2bfloat16(b);
    float ra = a - __bfloat162float(ah);
    float rb = b - __bfloat162float(bh);
    __nv_bfloat16 al = __float2bfloat16(ra), bl = __float2bfloat16(rb);
    xh[idx] = (uint)bfb(ah) | ((uint)bfb(bh) << 16);
    xl[idx] = (uint)bfb(al) | ((uint)bfb(bl) << 16);
}

__device__ __forceinline__ void mma16816(float c[4], uint a0, uint a1, uint a2, uint a3,
                                         uint b0, uint b1) {
    asm volatile(
        "mma.sync.aligned.m16n8k16.row.col.f32.bf16.bf16.f32 "
        "{%0,%1,%2,%3}, {%4,%5,%6,%7}, {%8,%9}, {%0,%1,%2,%3};\n"
        : "+f"(c[0]), "+f"(c[1]), "+f"(c[2]), "+f"(c[3])
        : "r"(a0), "r"(a1), "r"(a2), "r"(a3), "r"(b0), "r"(b1));
}

// D[64 x 128] += X[64 x 128] @ W[128 x 128], bf16-split (hi*hi + hi*lo + lo*hi)
// This warp: rows r0..r0+7, r0+8..r0+15 ; cols nbase .. nbase+8*TT-1
template<int TT>
__device__ __forceinline__ void gemm_bf16split(
    const uint* __restrict__ xh, const uint* __restrict__ xl,
    const uint* __restrict__ wh, const uint* __restrict__ wl,
    float acc[TT][4], int r0, int g, int tg, int nbase)
{
    const int g4 = g << 2;
    const int ra = r0 * 64, rb = (r0 + 8) * 64;
#pragma unroll
    for (int ks = 0; ks < 8; ks++) {
        int kz0 = (tg + 8 * ks) ^ g4;
        int kz1 = kz0 ^ 4;
        uint ah0 = xh[ra + kz0], ah1 = xh[rb + kz0], ah2 = xh[ra + kz1], ah3 = xh[rb + kz1];
        uint al0 = xl[ra + kz0], al1 = xl[rb + kz0], al2 = xl[ra + kz1], al3 = xl[rb + kz1];
#pragma unroll
        for (int t = 0; t < TT; t++) {
            int nw = (nbase + 8 * t + g) * 64;
            uint bh0 = wh[nw + kz0], bh1 = wh[nw + kz1];
            uint bl0 = wl[nw + kz0], bl1 = wl[nw + kz1];
            mma16816(acc[t], ah0, ah1, ah2, ah3, bh0, bh1);
            mma16816(acc[t], ah0, ah1, ah2, ah3, bl0, bl1);
            mma16816(acc[t], al0, al1, al2, al3, bh0, bh1);
        }
    }
}

// One-time: transpose + bf16-split a 128x128 weight matrix into smem (XOR swizzled)
__device__ __forceinline__ void load_weight(const float* __restrict__ S, uint* dh, uint* dl, int tid) {
    for (int idx = tid; idx < 8192; idx += blockDim.x) {
        int kp = idx >> 7, n = idx & 127;
        split_store(dh, dl, n * 64 + (kp ^ ((n & 7) << 2)),
                    S[(2 * kp) * 128 + n], S[(2 * kp + 1) * 128 + n]);
    }
}

// Load 64 contiguous rows [row0, row0+64) of src[limit x 128] into split X smem
__device__ __forceinline__ void load_split_rows(const float* __restrict__ src, int row0, int limit,
                                                uint* xh, uint* xl, int tid) {
    for (int idx = tid; idx < 4096; idx += blockDim.x) {
        int e = idx >> 6, kw = idx & 63;
        int row = row0 + e;
        float2 v = make_float2(0.f, 0.f);
        if (row < limit) v = __ldg((const float2*)(src + (size_t)row * 128) + kw);
        split_store(xh, xl, e * 64 + (kw ^ ((e & 7) << 2)), v.x, v.y);
    }
}

// GroupNorm(1,128) + relu + split-store back to X smem. NQ = 16/TT column partials per row.
// Contains 2 __syncthreads (uniform across block).
template<int TT>
__device__ __forceinline__ void gn_relu_split_store(
    float acc[TT][4], uint* xh, uint* xl, float* sred,
    const float* __restrict__ gamma, const float* __restrict__ beta,
    int r0, int g, int tg, int cq)
{
    const int NQ = 16 / TT;
    float s0 = 0, q0 = 0, s1 = 0, q1 = 0;
#pragma unroll
    for (int t = 0; t < TT; t++) {
        s0 += acc[t][0] + acc[t][1];
        q0 += acc[t][0] * acc[t][0] + acc[t][1] * acc[t][1];
        s1 += acc[t][2] + acc[t][3];
        q1 += acc[t][2] * acc[t][2] + acc[t][3] * acc[t][3];
    }
#pragma unroll
    for (int o = 1; o <= 2; o <<= 1) {
        s0 += __shfl_xor_sync(0xffffffffu, s0, o);
        q0 += __shfl_xor_sync(0xffffffffu, q0, o);
        s1 += __shfl_xor_sync(0xffffffffu, s1, o);
        q1 += __shfl_xor_sync(0xffffffffu, q1, o);
    }
    if (tg == 0) {
        sred[(r0 * NQ + cq) * 2 + 0] = s0;
        sred[(r0 * NQ + cq) * 2 + 1] = q0;
        sred[((r0 + 8) * NQ + cq) * 2 + 0] = s1;
        sred[((r0 + 8) * NQ + cq) * 2 + 1] = q1;
    }
    __syncthreads();
    float sa = 0.f, qa = 0.f, sb = 0.f, qb = 0.f;
#pragma unroll
    for (int q = 0; q < NQ; q++) {
        sa += sred[(r0 * NQ + q) * 2 + 0];
        qa += sred[(r0 * NQ + q) * 2 + 1];
        sb += sred[((r0 + 8) * NQ + q) * 2 + 0];
        qb += sred[((r0 + 8) * NQ + q) * 2 + 1];
    }
    float mu0 = sa * 0.0078125f;
    float rs0 = rsqrtf(qa * 0.0078125f - mu0 * mu0 + 1e-5f);
    float mu1 = sb * 0.0078125f;
    float rs1 = rsqrtf(qb * 0.0078125f - mu1 * mu1 + 1e-5f);
    const int g4 = g << 2;
#pragma unroll
    for (int t = 0; t < TT; t++) {
        int col0 = 8 * TT * cq + 8 * t + 2 * tg;
        float ga = __ldg(gamma + col0), gb = __ldg(gamma + col0 + 1);
        float ba = __ldg(beta + col0), bb = __ldg(beta + col0 + 1);
        float e0 = fmaxf((acc[t][0] - mu0) * rs0 * ga + ba, 0.f);
        float e1 = fmaxf((acc[t][1] - mu0) * rs0 * gb + bb, 0.f);
        float e2 = fmaxf((acc[t][2] - mu1) * rs1 * ga + ba, 0.f);
        float e3 = fmaxf((acc[t][3] - mu1) * rs1 * gb + bb, 0.f);
        int cw = 4 * TT * cq + 4 * t + tg;
        split_store(xh, xl, r0 * 64 + (cw ^ g4), e0, e1);
        split_store(xh, xl, (r0 + 8) * 64 + (cw ^ g4), e2, e3);
    }
    __syncthreads();
}

// Store fragment accumulators (raw fp32) to dst rows, guarded.
template<int TT>
__device__ __forceinline__ void store_frag(float* __restrict__ dst, float acc[TT][4],
                                           int row0g, int limit, int r0, int tg, int cq) {
    int rowA = row0g + r0, rowB = row0g + r0 + 8;
#pragma unroll
    for (int t = 0; t < TT; t++) {
        int col0 = 8 * TT * cq + 8 * t + 2 * tg;
        if (rowA < limit)
            *(float2*)(dst + (size_t)rowA * 128 + col0) = make_float2(acc[t][0], acc[t][1]);
        if (rowB < limit)
            *(float2*)(dst + (size_t)rowB * 128 + col0) = make_float2(acc[t][2], acc[t][3]);
    }
}

// ============================================================
// K3 (MMA): per-edge fused 3-layer MLP + scatter — 512 threads, 16 warps
// smem words: weights 49152 ; xh @49152 (4096) ; xl @53248 (4096)
//   sh @57344 (64) ; sw @57408 (64) ; sred @57472 (512, overlays sdx/sdy)
//   total 57984 words = 231936 B
// ============================================================
__global__ __launch_bounds__(512, 1) void k_edge_mma(
    const float* __restrict__ actr, const float* __restrict__ cctr,
    const int* __restrict__ hi, const int* __restrict__ wi,
    const float* __restrict__ W1, const float* __restrict__ b1,
    const float* __restrict__ W2, const float* __restrict__ gd, const float* __restrict__ bd,
    const float* __restrict__ Wc1d, const float* __restrict__ gc1, const float* __restrict__ bc1,
    const float* __restrict__ Wc2)
{
    extern __shared__ uint usm[];
    uint* xh = usm + 49152;
    uint* xl = usm + 53248;
    int* sh = (int*)(usm + 57344);
    int* sw = (int*)(usm + 57408);
    float* sred = (float*)(usm + 57472);   // 512 words
    float* sdx = sred;                     // overlay: dead after X1 build
    float* sdy = sred + 64;

    const int tid = threadIdx.x;

    load_weight(W2,   usm + 0,     usm + 8192,  tid);
    load_weight(Wc1d, usm + 16384, usm + 24576, tid);
    load_weight(Wc2,  usm + 32768, usm + 40960, tid);
    __syncthreads();

    const int lane = tid & 31;
    const int wid = tid >> 5;
    const int g = lane >> 2;
    const int tg = lane & 3;
    const int stripe = wid >> 2;   // 0..3
    const int cq = wid & 3;        // 0..3 col quarter
    const int r0 = 16 * stripe + g;

    const int NT = (NE + 63) / 64;
    for (int tile = blockIdx.x; tile < NT; tile += gridDim.x) {
        const int base = tile * 64;

        if (tid < 64) {
            int eg = base + tid;
            if (eg < NE) {
                int h = hi[eg], w = wi[eg];
                sh[tid] = h; sw[tid] = w;
                sdx[tid] = actr[2 * h] - cctr[2 * w];
                sdy[tid] = actr[2 * h + 1] - cctr[2 * w + 1];
            } else {
                sh[tid] = -1; sw[tid] = 0; sdx[tid] = 0.f; sdy[tid] = 0.f;
            }
        }
        __syncthreads();

        // X1 = relu(dist @ W1 + b1)
        for (int idx = tid; idx < 4096; idx += 512) {
            int e = idx >> 6, kw = idx & 63;
            float v0 = 0.f, v1 = 0.f;
            if (sh[e] >= 0) {
                int j0 = kw * 2;
                float dx = sdx[e], dy = sdy[e];
                v0 = fmaxf(fmaf(dx, __ldg(W1 + j0), fmaf(dy, __ldg(W1 + 128 + j0), __ldg(b1 + j0))), 0.f);
                v1 = fmaxf(fmaf(dx, __ldg(W1 + j0 + 1), fmaf(dy, __ldg(W1 + 128 + j0 + 1), __ldg(b1 + j0 + 1))), 0.f);
            }
            split_store(xh, xl, e * 64 + (kw ^ ((e & 7) << 2)), v0, v1);
        }
        __syncthreads();

        float acc[4][4];

        // GEMM1 + GN(g_dist)
#pragma unroll
        for (int t = 0; t < 4; t++) { acc[t][0] = acc[t][1] = acc[t][2] = acc[t][3] = 0.f; }
        gemm_bf16split<4>(xh, xl, usm + 0, usm + 8192, acc, r0, g, tg, 32 * cq);
        gn_relu_split_store<4>(acc, xh, xl, sred, gd, bd, r0, g, tg, cq);

        // GEMM2 (+ qc[hi] + cc[wi] preloaded) + GN(g_c1)
        {
            int h0 = sh[r0], w0i = sw[r0];
            int h1 = sh[r0 + 8], w1i = sw[r0 + 8];
            const float2* pq0 = (h0 >= 0) ? (const float2*)(g_qc + (size_t)h0 * 128) : 0;
            const float2* pc0 = (h0 >= 0) ? (const float2*)(g_cc + (size_t)w0i * 128) : 0;
            const float2* pq1 = (h1 >= 0) ? (const float2*)(g_qc + (size_t)h1 * 128) : 0;
            const float2* pc1 = (h1 >= 0) ? (const float2*)(g_cc + (size_t)w1i * 128) : 0;
#pragma unroll
            for (int t = 0; t < 4; t++) {
                int ci = (32 * cq + 8 * t + 2 * tg) >> 1;
                if (h0 >= 0) {
                    float2 a2 = __ldg(pq0 + ci), b2 = __ldg(pc0 + ci);
                    acc[t][0] = a2.x + b2.x; acc[t][1] = a2.y + b2.y;
                } else { acc[t][0] = acc[t][1] = 0.f; }
                if (h1 >= 0) {
                    float2 a2 = __ldg(pq1 + ci), b2 = __ldg(pc1 + ci);
                    acc[t][2] = a2.x + b2.x; acc[t][3] = a2.y + b2.y;
                } else { acc[t][2] = acc[t][3] = 0.f; }
            }
        }
        gemm_bf16split<4>(xh, xl, usm + 16384, usm + 24576, acc, r0, g, tg, 32 * cq);
        gn_relu_split_store<4>(acc, xh, xl, sred, gc1, bc1, r0, g, tg, cq);

        // GEMM3 + scatter
#pragma unroll
        for (int t = 0; t < 4; t++) { acc[t][0] = acc[t][1] = acc[t][2] = acc[t][3] = 0.f; }
        gemm_bf16split<4>(xh, xl, usm + 32768, usm + 40960, acc, r0, g, tg, 32 * cq);
        {
            int h0 = sh[r0], h1 = sh[r0 + 8];
#pragma unroll
            for (int t = 0; t < 4; t++) {
                int col0 = 32 * cq + 8 * t + 2 * tg;
                if (h0 >= 0) {
                    atomicAdd(g_acc + (size_t)h0 * 128 + col0, acc[t][0]);
                    atomicAdd(g_acc + (size_t)h0 * 128 + col0 + 1, acc[t][1]);
                }
                if (h1 >= 0) {
                    atomicAdd(g_acc + (size_t)h1 * 128 + col0, acc[t][2]);
                    atomicAdd(g_acc + (size_t)h1 * 128 + col0 + 1, acc[t][3]);
                }
            }
        }
        __syncthreads();
    }
}

// ============================================================
// K1 (MMA): per-agent precompute — 512 threads, 16 warps
// smem words: mats 49152 ; xh @49152 ; xl @53248 ; sred @57344 (512)
//   total 57856 words = 231424 B
// ============================================================
__global__ __launch_bounds__(512, 1) void k_agent_mma(
    const float* __restrict__ agts,
    const float* __restrict__ Wq, const float* __restrict__ gq, const float* __restrict__ bq,
    const float* __restrict__ Wmid, const float* __restrict__ Wagt)
{
    extern __shared__ uint usm[];
    uint* xh = usm + 49152;
    uint* xl = usm + 53248;
    float* sred = (float*)(usm + 57344);
    const int tid = threadIdx.x;

    load_weight(Wq,   usm + 0,     usm + 8192,  tid);
    load_weight(Wagt, usm + 16384, usm + 24576, tid);
    load_weight(Wmid, usm + 32768, usm + 40960, tid);
    __syncthreads();

    const int lane = tid & 31;
    const int wid = tid >> 5;
    const int g = lane >> 2;
    const int tg = lane & 3;
    const int stripe = wid >> 2;
    const int cq = wid & 3;
    const int r0 = 16 * stripe + g;

    const int NT = (NA + 63) / 64;
    for (int tile = blockIdx.x; tile < NT; tile += gridDim.x) {
        const int row0 = tile * 64;
        load_split_rows(agts, row0, NA, xh, xl, tid);
        __syncthreads();

        float acc[4][4];
        // Wagt pass -> g_acc
#pragma unroll
        for (int t = 0; t < 4; t++) { acc[t][0] = acc[t][1] = acc[t][2] = acc[t][3] = 0.f; }
        gemm_bf16split<4>(xh, xl, usm + 16384, usm + 24576, acc, r0, g, tg, 32 * cq);
        store_frag<4>(g_acc, acc, row0, NA, r0, tg, cq);

        // Wq pass -> GN(g_q) + relu -> X
#pragma unroll
        for (int t = 0; t < 4; t++) { acc[t][0] = acc[t][1] = acc[t][2] = acc[t][3] = 0.f; }
        gemm_bf16split<4>(xh, xl, usm + 0, usm + 8192, acc, r0, g, tg, 32 * cq);
        gn_relu_split_store<4>(acc, xh, xl, sred, gq, bq, r0, g, tg, cq);

        // Wmid pass -> g_qc
#pragma unroll
        for (int t = 0; t < 4; t++) { acc[t][0] = acc[t][1] = acc[t][2] = acc[t][3] = 0.f; }
        gemm_bf16split<4>(xh, xl, usm + 32768, usm + 40960, acc, r0, g, tg, 32 * cq);
        store_frag<4>(g_qc, acc, row0, NA, r0, tg, cq);
        __syncthreads();
    }
}

// ============================================================
// K2 (MMA): g_cc = ctx @ Wctx — 256 threads, 2 CTAs/SM (unchanged)
// ============================================================
__global__ __launch_bounds__(256, 2) void k_ctx_mma(
    const float* __restrict__ ctx, const float* __restrict__ Wctx)
{
    extern __shared__ uint usm[];
    uint* xh = usm + 16384;
    uint* xl = usm + 20480;
    const int tid = threadIdx.x;

    load_weight(Wctx, usm + 0, usm + 8192, tid);
    __syncthreads();

    const int lane = tid & 31;
    const int wid = tid >> 5;
    const int g = lane >> 2;
    const int tg = lane & 3;
    const int stripe = wid >> 1;
    const int cb = wid & 1;
    const int r0 = 16 * stripe + g;

    const int NT = (NC + 63) / 64;
    for (int tile = blockIdx.x; tile < NT; tile += gridDim.x) {
        const int row0 = tile * 64;
        load_split_rows(ctx, row0, NC, xh, xl, tid);
        __syncthreads();

        float acc[8][4];
#pragma unroll
        for (int t = 0; t < 8; t++) { acc[t][0] = acc[t][1] = acc[t][2] = acc[t][3] = 0.f; }
        gemm_bf16split<8>(xh, xl, usm + 0, usm + 8192, acc, r0, g, tg, 64 * cb);
        store_frag<8>(g_cc, acc, row0, NC, r0, tg, cb);
        __syncthreads();
    }
}

// ============================================================
// K4 (MMA): out = relu(gn(relu(gn(g_acc)) @ Wlin) + agts) — unchanged from R9
// ============================================================
__global__ __launch_bounds__(256, 2) void k_final_mma(
    const float* __restrict__ agts,
    const float* __restrict__ gnw, const float* __restrict__ bnw,
    const float* __restrict__ Wlin, const float* __restrict__ gl, const float* __restrict__ bl,
    float* __restrict__ out)
{
    extern __shared__ uint usm[];
    uint* xh = usm + 16384;
    uint* xl = usm + 20480;
    float* sred = (float*)(usm + 24576);
    const int tid = threadIdx.x;

    load_weight(Wlin, usm + 0, usm + 8192, tid);
    __syncthreads();

    const int lane = tid & 31;
    const int wid = tid >> 5;
    const int g = lane >> 2;
    const int tg = lane & 3;
    const int stripe = wid >> 1;
    const int cb = wid & 1;
    const int r0 = 16 * stripe + g;
    const int arow = tid >> 2;
    const int apart = tid & 3;

    const int NT = (NA + 63) / 64;
    for (int tile = blockIdx.x; tile < NT; tile += gridDim.x) {
        const int row0 = tile * 64;

        // phase A: SIMT GN(g_n)+relu on g_acc rows -> split X smem
        {
            int rowg = row0 + arow;
            float v[32];
            if (rowg < NA) {
                const float4* p = (const float4*)(g_acc + (size_t)rowg * 128 + apart * 32);
#pragma unroll
                for (int q = 0; q < 8; q++) {
                    float4 f = __ldg(p + q);
                    v[4 * q] = f.x; v[4 * q + 1] = f.y; v[4 * q + 2] = f.z; v[4 * q + 3] = f.w;
                }
            } else {
#pragma unroll
                for (int q = 0; q < 32; q++) v[q] = 0.f;
            }
            float s = 0.f, qq = 0.f;
#pragma unroll
            for (int q = 0; q < 32; q++) { s += v[q]; qq += v[q] * v[q]; }
            s += __shfl_xor_sync(0xffffffffu, s, 1);
            qq += __shfl_xor_sync(0xffffffffu, qq, 1);
            s += __shfl_xor_sync(0xffffffffu, s, 2);
            qq += __shfl_xor_sync(0xffffffffu, qq, 2);
            float mu = s * 0.0078125f;
            float rs = rsqrtf(qq * 0.0078125f - mu * mu + 1e-5f);
            int sw4 = (arow & 7) << 2;
#pragma unroll
            for (int j = 0; j < 16; j++) {
                int c = apart * 32 + 2 * j;
                float e0 = fmaxf((v[2 * j] - mu) * rs * __ldg(gnw + c) + __ldg(bnw + c), 0.f);
                float e1 = fmaxf((v[2 * j + 1] - mu) * rs * __ldg(gnw + c + 1) + __ldg(bnw + c + 1), 0.f);
                int kw = apart * 16 + j;
                split_store(xh, xl, arow * 64 + (kw ^ sw4), e0, e1);
            }
        }
        __syncthreads();

        // GEMM Wlin
        float acc[8][4];
#pragma unroll
        for (int t = 0; t < 8; t++) { acc[t][0] = acc[t][1] = acc[t][2] = acc[t][3] = 0.f; }
        gemm_bf16split<8>(xh, xl, usm + 0, usm + 8192, acc, r0, g, tg, 64 * cb);

        // GN(g_lin) (no relu) + residual + relu -> out
        {
            float s0 = 0, q0 = 0, s1 = 0, q1 = 0;
#pragma unroll
            for (int t = 0; t < 8; t++) {
                s0 += acc[t][0] + acc[t][1];
                q0 += acc[t][0] * acc[t][0] + acc[t][1] * acc[t][1];
                s1 += acc[t][2] + acc[t][3];
                q1 += acc[t][2] * acc[t][2] + acc[t][3] * acc[t][3];
            }
#pragma unroll
            for (int o = 1; o <= 2; o <<= 1) {
                s0 += __shfl_xor_sync(0xffffffffu, s0, o);
                q0 += __shfl_xor_sync(0xffffffffu, q0, o);
                s1 += __shfl_xor_sync(0xffffffffu, s1, o);
                q1 += __shfl_xor_sync(0xffffffffu, q1, o);
            }
            if (tg == 0) {
                sred[(r0 * 2 + cb) * 2 + 0] = s0;
                sred[(r0 * 2 + cb) * 2 + 1] = q0;
                sred[((r0 + 8) * 2 + cb) * 2 + 0] = s1;
                sred[((r0 + 8) * 2 + cb) * 2 + 1] = q1;
            }
            __syncthreads();
            float sa = sred[(r0 * 2) * 2 + 0] + sred[(r0 * 2 + 1) * 2 + 0];
            float qa = sred[(r0 * 2) * 2 + 1] + sred[(r0 * 2 + 1) * 2 + 1];
            float sb = sred[((r0 + 8) * 2) * 2 + 0] + sred[((r0 + 8) * 2 + 1) * 2 + 0];
            float qb = sred[((r0 + 8) * 2) * 2 + 1] + sred[((r0 + 8) * 2 + 1) * 2 + 1];
            float mu0 = sa * 0.0078125f;
            float rs0 = rsqrtf(qa * 0.0078125f - mu0 * mu0 + 1e-5f);
            float mu1 = sb * 0.0078125f;
            float rs1 = rsqrtf(qb * 0.0078125f - mu1 * mu1 + 1e-5f);
            int rowA = row0 + r0, rowB = row0 + r0 + 8;
#pragma unroll
            for (int t = 0; t < 8; t++) {
                int col0 = 64 * cb + 8 * t + 2 * tg;
                float ga = __ldg(gl + col0), gb = __ldg(gl + col0 + 1);
                float ba = __ldg(bl + col0), bb = __ldg(bl + col0 + 1);
                if (rowA < NA) {
                    float2 res = __ldg((const float2*)(agts + (size_t)rowA * 128) + (col0 >> 1));
                    float y0 = fmaxf((acc[t][0] - mu0) * rs0 * ga + ba + res.x, 0.f);
                    float y1 = fmaxf((acc[t][1] - mu0) * rs0 * gb + bb + res.y, 0.f);
                    *(float2*)(out + (size_t)rowA * 128 + col0) = make_float2(y0, y1);
                }
                if (rowB < NA) {
                    float2 res = __ldg((const float2*)(agts + (size_t)rowB * 128) + (col0 >> 1));
                    float y2 = fmaxf((acc[t][2] - mu1) * rs1 * ga + ba + res.x, 0.f);
                    float y3 = fmaxf((acc[t][3] - mu1) * rs1 * gb + bb + res.y, 0.f);
                    *(float2*)(out + (size_t)rowB * 128 + col0) = make_float2(y2, y3);
                }
            }
        }
        __syncthreads();
    }
}

// ================= host =================
extern "C" void kernel_launch(void* const* d_in, const int* in_sizes, int n_in,
                              void* d_out, int out_size)
{
    const float* agts    = (const float*)d_in[0];
    const float* ctx     = (const float*)d_in[1];
    const float* actr    = (const float*)d_in[2];
    const float* cctr    = (const float*)d_in[3];
    const float* W_dist1 = (const float*)d_in[4];
    const float* b_dist1 = (const float*)d_in[5];
    const float* W_dist2 = (const float*)d_in[6];
    const float* g_dist  = (const float*)d_in[7];
    const float* b_dist  = (const float*)d_in[8];
    const float* W_q     = (const float*)d_in[9];
    const float* g_q     = (const float*)d_in[10];
    const float* b_q     = (const float*)d_in[11];
    const float* W_c1    = (const float*)d_in[12];
    const float* g_c1    = (const float*)d_in[13];
    const float* b_c1    = (const float*)d_in[14];
    const float* W_c2    = (const float*)d_in[15];
    const float* W_agt   = (const float*)d_in[16];
    const float* g_n     = (const float*)d_in[17];
    const float* b_n     = (const float*)d_in[18];
    const float* W_lin   = (const float*)d_in[19];
    const float* g_lin   = (const float*)d_in[20];
    const float* b_lin   = (const float*)d_in[21];
    const int*   hi      = (const int*)d_in[22];
    const int*   wi      = (const int*)d_in[23];
    float* out = (float*)d_out;

    const int S1 = 57856 * 4;   // k_agent_mma  (231424 B)
    const int S2 = 24576 * 4;   // k_ctx_mma    (98304 B)
    const int S3 = 57984 * 4;   // k_edge_mma   (231936 B)
    const int S4 = 24832 * 4;   // k_final_mma  (99328 B)
    cudaFuncSetAttribute(k_agent_mma, cudaFuncAttributeMaxDynamicSharedMemorySize, S1);
    cudaFuncSetAttribute(k_ctx_mma,   cudaFuncAttributeMaxDynamicSharedMemorySize, S2);
    cudaFuncSetAttribute(k_edge_mma,  cudaFuncAttributeMaxDynamicSharedMemorySize, S3);
    cudaFuncSetAttribute(k_final_mma, cudaFuncAttributeMaxDynamicSharedMemorySize, S4);

    k_agent_mma<<<152, 512, S1>>>(agts, W_q, g_q, b_q, W_c1 + 128 * 128, W_agt);
    k_ctx_mma  <<<304, 256, S2>>>(ctx, W_c1 + 256 * 128);
    k_edge_mma <<<152, 512, S3>>>(actr, cctr, hi, wi,
                                  W_dist1, b_dist1, W_dist2, g_dist, b_dist,
                                  W_c1, g_c1, b_c1, W_c2);
    k_final_mma<<<304, 256, S4>>>(agts, g_n, b_n, W_lin, g_lin, b_lin, out);
}

// round 13
// speedup vs baseline: 3.6648x; 1.0093x over previous
#include <cuda_runtime.h>
#include <cuda_bf16.h>

typedef unsigned int uint;

#define NA 100000
#define NC 150000
#define NE 500000

// ---- device scratch ----
__device__ float g_qc[NA * 128];
__device__ float g_cc[NC * 128];
__device__ float g_acc[NA * 128];

// ============================================================
// bf16 split helpers
// ============================================================
__device__ __forceinline__ unsigned short bfb(__nv_bfloat16 h) {
    return ((__nv_bfloat16_raw)h).x;
}

// split (a,b) fp32 pair into hi/lo bf16x2 words and store
__device__ __forceinline__ void split_store(uint* xh, uint* xl, int idx, float a, float b) {
    __nv_bfloat16 ah = __float2bfloat16(a), bh = __float2bfloat16(b);
    float ra = a - __bfloat162float(ah);
    float rb = b - __bfloat162float(bh);
    __nv_bfloat16 al = __float2bfloat16(ra), bl = __float2bfloat16(rb);
    xh[idx] = (uint)bfb(ah) | ((uint)bfb(bh) << 16);
    xl[idx] = (uint)bfb(al) | ((uint)bfb(bl) << 16);
}

__device__ __forceinline__ void mma16816(float c[4], uint a0, uint a1, uint a2, uint a3,
                                         uint b0, uint b1) {
    asm volatile(
        "mma.sync.aligned.m16n8k16.row.col.f32.bf16.bf16.f32 "
        "{%0,%1,%2,%3}, {%4,%5,%6,%7}, {%8,%9}, {%0,%1,%2,%3};\n"
        : "+f"(c[0]), "+f"(c[1]), "+f"(c[2]), "+f"(c[3])
        : "r"(a0), "r"(a1), "r"(a2), "r"(a3), "r"(b0), "r"(b1));
}

// D[64 x 128] += X[64 x 128] @ W[128 x 128], bf16-split (hi*hi + hi*lo + lo*hi)
// This warp: rows r0..r0+7, r0+8..r0+15 ; cols nbase .. nbase+8*TT-1
template<int TT>
__device__ __forceinline__ void gemm_bf16split(
    const uint* __restrict__ xh, const uint* __restrict__ xl,
    const uint* __restrict__ wh, const uint* __restrict__ wl,
    float acc[TT][4], int r0, int g, int tg, int nbase)
{
    const int g4 = g << 2;
    const int ra = r0 * 64, rb = (r0 + 8) * 64;
#pragma unroll
    for (int ks = 0; ks < 8; ks++) {
        int kz0 = (tg + 8 * ks) ^ g4;
        int kz1 = kz0 ^ 4;
        uint ah0 = xh[ra + kz0], ah1 = xh[rb + kz0], ah2 = xh[ra + kz1], ah3 = xh[rb + kz1];
        uint al0 = xl[ra + kz0], al1 = xl[rb + kz0], al2 = xl[ra + kz1], al3 = xl[rb + kz1];
#pragma unroll
        for (int t = 0; t < TT; t++) {
            int nw = (nbase + 8 * t + g) * 64;
            uint bh0 = wh[nw + kz0], bh1 = wh[nw + kz1];
            uint bl0 = wl[nw + kz0], bl1 = wl[nw + kz1];
            mma16816(acc[t], ah0, ah1, ah2, ah3, bh0, bh1);
            mma16816(acc[t], ah0, ah1, ah2, ah3, bl0, bl1);
            mma16816(acc[t], al0, al1, al2, al3, bh0, bh1);
        }
    }
}

// One-time: transpose + bf16-split a 128x128 weight matrix into smem (XOR swizzled)
__device__ __forceinline__ void load_weight(const float* __restrict__ S, uint* dh, uint* dl, int tid) {
    for (int idx = tid; idx < 8192; idx += blockDim.x) {
        int kp = idx >> 7, n = idx & 127;
        split_store(dh, dl, n * 64 + (kp ^ ((n & 7) << 2)),
                    S[(2 * kp) * 128 + n], S[(2 * kp + 1) * 128 + n]);
    }
}

// Load 64 contiguous rows [row0, row0+64) of src[limit x 128] into split X smem
__device__ __forceinline__ void load_split_rows(const float* __restrict__ src, int row0, int limit,
                                                uint* xh, uint* xl, int tid) {
    for (int idx = tid; idx < 4096; idx += blockDim.x) {
        int e = idx >> 6, kw = idx & 63;
        int row = row0 + e;
        float2 v = make_float2(0.f, 0.f);
        if (row < limit) v = __ldg((const float2*)(src + (size_t)row * 128) + kw);
        split_store(xh, xl, e * 64 + (kw ^ ((e & 7) << 2)), v.x, v.y);
    }
}

// GroupNorm(1,128) + relu + split-store back to X smem. NQ = 16/TT column partials per row.
// Contains 2 __syncthreads (uniform across block).
template<int TT>
__device__ __forceinline__ void gn_relu_split_store(
    float acc[TT][4], uint* xh, uint* xl, float* sred,
    const float* __restrict__ gamma, const float* __restrict__ beta,
    int r0, int g, int tg, int cq)
{
    const int NQ = 16 / TT;
    float s0 = 0, q0 = 0, s1 = 0, q1 = 0;
#pragma unroll
    for (int t = 0; t < TT; t++) {
        s0 += acc[t][0] + acc[t][1];
        q0 += acc[t][0] * acc[t][0] + acc[t][1] * acc[t][1];
        s1 += acc[t][2] + acc[t][3];
        q1 += acc[t][2] * acc[t][2] + acc[t][3] * acc[t][3];
    }
#pragma unroll
    for (int o = 1; o <= 2; o <<= 1) {
        s0 += __shfl_xor_sync(0xffffffffu, s0, o);
        q0 += __shfl_xor_sync(0xffffffffu, q0, o);
        s1 += __shfl_xor_sync(0xffffffffu, s1, o);
        q1 += __shfl_xor_sync(0xffffffffu, q1, o);
    }
    if (tg == 0) {
        sred[(r0 * NQ + cq) * 2 + 0] = s0;
        sred[(r0 * NQ + cq) * 2 + 1] = q0;
        sred[((r0 + 8) * NQ + cq) * 2 + 0] = s1;
        sred[((r0 + 8) * NQ + cq) * 2 + 1] = q1;
    }
    __syncthreads();
    float sa = 0.f, qa = 0.f, sb = 0.f, qb = 0.f;
#pragma unroll
    for (int q = 0; q < NQ; q++) {
        sa += sred[(r0 * NQ + q) * 2 + 0];
        qa += sred[(r0 * NQ + q) * 2 + 1];
        sb += sred[((r0 + 8) * NQ + q) * 2 + 0];
        qb += sred[((r0 + 8) * NQ + q) * 2 + 1];
    }
    float mu0 = sa * 0.0078125f;
    float rs0 = rsqrtf(qa * 0.0078125f - mu0 * mu0 + 1e-5f);
    float mu1 = sb * 0.0078125f;
    float rs1 = rsqrtf(qb * 0.0078125f - mu1 * mu1 + 1e-5f);
    const int g4 = g << 2;
#pragma unroll
    for (int t = 0; t < TT; t++) {
        int col0 = 8 * TT * cq + 8 * t + 2 * tg;
        float ga = __ldg(gamma + col0), gb = __ldg(gamma + col0 + 1);
        float ba = __ldg(beta + col0), bb = __ldg(beta + col0 + 1);
        float e0 = fmaxf((acc[t][0] - mu0) * rs0 * ga + ba, 0.f);
        float e1 = fmaxf((acc[t][1] - mu0) * rs0 * gb + bb, 0.f);
        float e2 = fmaxf((acc[t][2] - mu1) * rs1 * ga + ba, 0.f);
        float e3 = fmaxf((acc[t][3] - mu1) * rs1 * gb + bb, 0.f);
        int cw = 4 * TT * cq + 4 * t + tg;
        split_store(xh, xl, r0 * 64 + (cw ^ g4), e0, e1);
        split_store(xh, xl, (r0 + 8) * 64 + (cw ^ g4), e2, e3);
    }
    __syncthreads();
}

// Store fragment accumulators (raw fp32) to dst rows via lane-pair shfl -> STG.128.
// Even tg lane writes row A's 4-col quad; odd tg lane writes row B's quad.
template<int TT>
__device__ __forceinline__ void store_frag(float* __restrict__ dst, float acc[TT][4],
                                           int row0g, int limit, int r0, int tg, int cq) {
    int rowA = row0g + r0, rowB = row0g + r0 + 8;
#pragma unroll
    for (int t = 0; t < TT; t++) {
        float s0 = (tg & 1) ? acc[t][0] : acc[t][2];
        float s1 = (tg & 1) ? acc[t][1] : acc[t][3];
        float p0 = __shfl_xor_sync(0xffffffffu, s0, 1);
        float p1 = __shfl_xor_sync(0xffffffffu, s1, 1);
        if ((tg & 1) == 0) {
            int col0 = 8 * TT * cq + 8 * t + 2 * tg;
            if (rowA < limit)
                *(float4*)(dst + (size_t)rowA * 128 + col0) = make_float4(acc[t][0], acc[t][1], p0, p1);
        } else {
            int col0 = 8 * TT * cq + 8 * t + 2 * (tg - 1);
            if (rowB < limit)
                *(float4*)(dst + (size_t)rowB * 128 + col0) = make_float4(p0, p1, acc[t][2], acc[t][3]);
        }
    }
}

// ============================================================
// K3 (MMA): per-edge fused 3-layer MLP + scatter — 512 threads, 16 warps
// smem words: weights 49152 ; xh @49152 (4096) ; xl @53248 (4096)
//   sh @57344 (64) ; sw @57408 (64) ; sred @57472 (512, overlays sdx/sdy)
//   total 57984 words = 231936 B
// ============================================================
__global__ __launch_bounds__(512, 1) void k_edge_mma(
    const float* __restrict__ actr, const float* __restrict__ cctr,
    const int* __restrict__ hi, const int* __restrict__ wi,
    const float* __restrict__ W1, const float* __restrict__ b1,
    const float* __restrict__ W2, const float* __restrict__ gd, const float* __restrict__ bd,
    const float* __restrict__ Wc1d, const float* __restrict__ gc1, const float* __restrict__ bc1,
    const float* __restrict__ Wc2)
{
    extern __shared__ uint usm[];
    uint* xh = usm + 49152;
    uint* xl = usm + 53248;
    int* sh = (int*)(usm + 57344);
    int* sw = (int*)(usm + 57408);
    float* sred = (float*)(usm + 57472);   // 512 words
    float* sdx = sred;                     // overlay: dead after X1 build
    float* sdy = sred + 64;

    const int tid = threadIdx.x;

    load_weight(W2,   usm + 0,     usm + 8192,  tid);
    load_weight(Wc1d, usm + 16384, usm + 24576, tid);
    load_weight(Wc2,  usm + 32768, usm + 40960, tid);
    __syncthreads();

    const int lane = tid & 31;
    const int wid = tid >> 5;
    const int g = lane >> 2;
    const int tg = lane & 3;
    const int stripe = wid >> 2;   // 0..3
    const int cq = wid & 3;        // 0..3 col quarter
    const int r0 = 16 * stripe + g;

    const int NT = (NE + 63) / 64;
    for (int tile = blockIdx.x; tile < NT; tile += gridDim.x) {
        const int base = tile * 64;

        if (tid < 64) {
            int eg = base + tid;
            if (eg < NE) {
                int h = hi[eg], w = wi[eg];
                sh[tid] = h; sw[tid] = w;
                sdx[tid] = actr[2 * h] - cctr[2 * w];
                sdy[tid] = actr[2 * h + 1] - cctr[2 * w + 1];
            } else {
                sh[tid] = -1; sw[tid] = 0; sdx[tid] = 0.f; sdy[tid] = 0.f;
            }
        }
        __syncthreads();

        // X1 = relu(dist @ W1 + b1)
        for (int idx = tid; idx < 4096; idx += 512) {
            int e = idx >> 6, kw = idx & 63;
            float v0 = 0.f, v1 = 0.f;
            if (sh[e] >= 0) {
                int j0 = kw * 2;
                float dx = sdx[e], dy = sdy[e];
                v0 = fmaxf(fmaf(dx, __ldg(W1 + j0), fmaf(dy, __ldg(W1 + 128 + j0), __ldg(b1 + j0))), 0.f);
                v1 = fmaxf(fmaf(dx, __ldg(W1 + j0 + 1), fmaf(dy, __ldg(W1 + 128 + j0 + 1), __ldg(b1 + j0 + 1))), 0.f);
            }
            split_store(xh, xl, e * 64 + (kw ^ ((e & 7) << 2)), v0, v1);
        }
        __syncthreads();

        float acc[4][4];

        // GEMM1 + GN(g_dist)
#pragma unroll
        for (int t = 0; t < 4; t++) { acc[t][0] = acc[t][1] = acc[t][2] = acc[t][3] = 0.f; }
        gemm_bf16split<4>(xh, xl, usm + 0, usm + 8192, acc, r0, g, tg, 32 * cq);
        gn_relu_split_store<4>(acc, xh, xl, sred, gd, bd, r0, g, tg, cq);

        // GEMM2 (+ qc[hi] + cc[wi] preloaded) + GN(g_c1)
        {
            int h0 = sh[r0], w0i = sw[r0];
            int h1 = sh[r0 + 8], w1i = sw[r0 + 8];
            const float2* pq0 = (h0 >= 0) ? (const float2*)(g_qc + (size_t)h0 * 128) : 0;
            const float2* pc0 = (h0 >= 0) ? (const float2*)(g_cc + (size_t)w0i * 128) : 0;
            const float2* pq1 = (h1 >= 0) ? (const float2*)(g_qc + (size_t)h1 * 128) : 0;
            const float2* pc1 = (h1 >= 0) ? (const float2*)(g_cc + (size_t)w1i * 128) : 0;
#pragma unroll
            for (int t = 0; t < 4; t++) {
                int ci = (32 * cq + 8 * t + 2 * tg) >> 1;
                if (h0 >= 0) {
                    float2 a2 = __ldg(pq0 + ci), b2 = __ldg(pc0 + ci);
                    acc[t][0] = a2.x + b2.x; acc[t][1] = a2.y + b2.y;
                } else { acc[t][0] = acc[t][1] = 0.f; }
                if (h1 >= 0) {
                    float2 a2 = __ldg(pq1 + ci), b2 = __ldg(pc1 + ci);
                    acc[t][2] = a2.x + b2.x; acc[t][3] = a2.y + b2.y;
                } else { acc[t][2] = acc[t][3] = 0.f; }
            }
        }
        gemm_bf16split<4>(xh, xl, usm + 16384, usm + 24576, acc, r0, g, tg, 32 * cq);
        gn_relu_split_store<4>(acc, xh, xl, sred, gc1, bc1, r0, g, tg, cq);

        // GEMM3 + scatter (lane-pair shfl -> red.global.add.v4.f32)
#pragma unroll
        for (int t = 0; t < 4; t++) { acc[t][0] = acc[t][1] = acc[t][2] = acc[t][3] = 0.f; }
        gemm_bf16split<4>(xh, xl, usm + 32768, usm + 40960, acc, r0, g, tg, 32 * cq);
        {
            int h0 = sh[r0], h1 = sh[r0 + 8];
#pragma unroll
            for (int t = 0; t < 4; t++) {
                float s0 = (tg & 1) ? acc[t][0] : acc[t][2];
                float s1 = (tg & 1) ? acc[t][1] : acc[t][3];
                float p0 = __shfl_xor_sync(0xffffffffu, s0, 1);
                float p1 = __shfl_xor_sync(0xffffffffu, s1, 1);
                if ((tg & 1) == 0) {
                    if (h0 >= 0) {
                        float* p = g_acc + (size_t)h0 * 128 + 32 * cq + 8 * t + 2 * tg;
                        asm volatile("red.global.add.v4.f32 [%0], {%1, %2, %3, %4};"
                                     :: "l"(p), "f"(acc[t][0]), "f"(acc[t][1]), "f"(p0), "f"(p1)
                                     : "memory");
                    }
                } else {
                    if (h1 >= 0) {
                        float* p = g_acc + (size_t)h1 * 128 + 32 * cq + 8 * t + 2 * (tg - 1);
                        asm volatile("red.global.add.v4.f32 [%0], {%1, %2, %3, %4};"
                                     :: "l"(p), "f"(p0), "f"(p1), "f"(acc[t][2]), "f"(acc[t][3])
                                     : "memory");
                    }
                }
            }
        }
        __syncthreads();
    }
}

// ============================================================
// K1 (MMA): per-agent precompute — 512 threads, 16 warps
// ============================================================
__global__ __launch_bounds__(512, 1) void k_agent_mma(
    const float* __restrict__ agts,
    const float* __restrict__ Wq, const float* __restrict__ gq, const float* __restrict__ bq,
    const float* __restrict__ Wmid, const float* __restrict__ Wagt)
{
    extern __shared__ uint usm[];
    uint* xh = usm + 49152;
    uint* xl = usm + 53248;
    float* sred = (float*)(usm + 57344);
    const int tid = threadIdx.x;

    load_weight(Wq,   usm + 0,     usm + 8192,  tid);
    load_weight(Wagt, usm + 16384, usm + 24576, tid);
    load_weight(Wmid, usm + 32768, usm + 40960, tid);
    __syncthreads();

    const int lane = tid & 31;
    const int wid = tid >> 5;
    const int g = lane >> 2;
    const int tg = lane & 3;
    const int stripe = wid >> 2;
    const int cq = wid & 3;
    const int r0 = 16 * stripe + g;

    const int NT = (NA + 63) / 64;
    for (int tile = blockIdx.x; tile < NT; tile += gridDim.x) {
        const int row0 = tile * 64;
        load_split_rows(agts, row0, NA, xh, xl, tid);
        __syncthreads();

        float acc[4][4];
        // Wagt pass -> g_acc
#pragma unroll
        for (int t = 0; t < 4; t++) { acc[t][0] = acc[t][1] = acc[t][2] = acc[t][3] = 0.f; }
        gemm_bf16split<4>(xh, xl, usm + 16384, usm + 24576, acc, r0, g, tg, 32 * cq);
        store_frag<4>(g_acc, acc, row0, NA, r0, tg, cq);

        // Wq pass -> GN(g_q) + relu -> X
#pragma unroll
        for (int t = 0; t < 4; t++) { acc[t][0] = acc[t][1] = acc[t][2] = acc[t][3] = 0.f; }
        gemm_bf16split<4>(xh, xl, usm + 0, usm + 8192, acc, r0, g, tg, 32 * cq);
        gn_relu_split_store<4>(acc, xh, xl, sred, gq, bq, r0, g, tg, cq);

        // Wmid pass -> g_qc
#pragma unroll
        for (int t = 0; t < 4; t++) { acc[t][0] = acc[t][1] = acc[t][2] = acc[t][3] = 0.f; }
        gemm_bf16split<4>(xh, xl, usm + 32768, usm + 40960, acc, r0, g, tg, 32 * cq);
        store_frag<4>(g_qc, acc, row0, NA, r0, tg, cq);
        __syncthreads();
    }
}

// ============================================================
// K2 (MMA): g_cc = ctx @ Wctx — 256 threads, 2 CTAs/SM
// ============================================================
__global__ __launch_bounds__(256, 2) void k_ctx_mma(
    const float* __restrict__ ctx, const float* __restrict__ Wctx)
{
    extern __shared__ uint usm[];
    uint* xh = usm + 16384;
    uint* xl = usm + 20480;
    const int tid = threadIdx.x;

    load_weight(Wctx, usm + 0, usm + 8192, tid);
    __syncthreads();

    const int lane = tid & 31;
    const int wid = tid >> 5;
    const int g = lane >> 2;
    const int tg = lane & 3;
    const int stripe = wid >> 1;
    const int cb = wid & 1;
    const int r0 = 16 * stripe + g;

    const int NT = (NC + 63) / 64;
    for (int tile = blockIdx.x; tile < NT; tile += gridDim.x) {
        const int row0 = tile * 64;
        load_split_rows(ctx, row0, NC, xh, xl, tid);
        __syncthreads();

        float acc[8][4];
#pragma unroll
        for (int t = 0; t < 8; t++) { acc[t][0] = acc[t][1] = acc[t][2] = acc[t][3] = 0.f; }
        gemm_bf16split<8>(xh, xl, usm + 0, usm + 8192, acc, r0, g, tg, 64 * cb);
        store_frag<8>(g_cc, acc, row0, NC, r0, tg, cb);
        __syncthreads();
    }
}

// ============================================================
// K4 (MMA): out = relu(gn(relu(gn(g_acc)) @ Wlin) + agts) — unchanged
// ============================================================
__global__ __launch_bounds__(256, 2) void k_final_mma(
    const float* __restrict__ agts,
    const float* __restrict__ gnw, const float* __restrict__ bnw,
    const float* __restrict__ Wlin, const float* __restrict__ gl, const float* __restrict__ bl,
    float* __restrict__ out)
{
    extern __shared__ uint usm[];
    uint* xh = usm + 16384;
    uint* xl = usm + 20480;
    float* sred = (float*)(usm + 24576);
    const int tid = threadIdx.x;

    load_weight(Wlin, usm + 0, usm + 8192, tid);
    __syncthreads();

    const int lane = tid & 31;
    const int wid = tid >> 5;
    const int g = lane >> 2;
    const int tg = lane & 3;
    const int stripe = wid >> 1;
    const int cb = wid & 1;
    const int r0 = 16 * stripe + g;
    const int arow = tid >> 2;
    const int apart = tid & 3;

    const int NT = (NA + 63) / 64;
    for (int tile = blockIdx.x; tile < NT; tile += gridDim.x) {
        const int row0 = tile * 64;

        // phase A: SIMT GN(g_n)+relu on g_acc rows -> split X smem
        {
            int rowg = row0 + arow;
            float v[32];
            if (rowg < NA) {
                const float4* p = (const float4*)(g_acc + (size_t)rowg * 128 + apart * 32);
#pragma unroll
                for (int q = 0; q < 8; q++) {
                    float4 f = __ldg(p + q);
                    v[4 * q] = f.x; v[4 * q + 1] = f.y; v[4 * q + 2] = f.z; v[4 * q + 3] = f.w;
                }
            } else {
#pragma unroll
                for (int q = 0; q < 32; q++) v[q] = 0.f;
            }
            float s = 0.f, qq = 0.f;
#pragma unroll
            for (int q = 0; q < 32; q++) { s += v[q]; qq += v[q] * v[q]; }
            s += __shfl_xor_sync(0xffffffffu, s, 1);
            qq += __shfl_xor_sync(0xffffffffu, qq, 1);
            s += __shfl_xor_sync(0xffffffffu, s, 2);
            qq += __shfl_xor_sync(0xffffffffu, qq, 2);
            float mu = s * 0.0078125f;
            float rs = rsqrtf(qq * 0.0078125f - mu * mu + 1e-5f);
            int sw4 = (arow & 7) << 2;
#pragma unroll
            for (int j = 0; j < 16; j++) {
                int c = apart * 32 + 2 * j;
                float e0 = fmaxf((v[2 * j] - mu) * rs * __ldg(gnw + c) + __ldg(bnw + c), 0.f);
                float e1 = fmaxf((v[2 * j + 1] - mu) * rs * __ldg(gnw + c + 1) + __ldg(bnw + c + 1), 0.f);
                int kw = apart * 16 + j;
                split_store(xh, xl, arow * 64 + (kw ^ sw4), e0, e1);
            }
        }
        __syncthreads();

        // GEMM Wlin
        float acc[8][4];
#pragma unroll
        for (int t = 0; t < 8; t++) { acc[t][0] = acc[t][1] = acc[t][2] = acc[t][3] = 0.f; }
        gemm_bf16split<8>(xh, xl, usm + 0, usm + 8192, acc, r0, g, tg, 64 * cb);

        // GN(g_lin) (no relu) + residual + relu -> out
        {
            float s0 = 0, q0 = 0, s1 = 0, q1 = 0;
#pragma unroll
            for (int t = 0; t < 8; t++) {
                s0 += acc[t][0] + acc[t][1];
                q0 += acc[t][0] * acc[t][0] + acc[t][1] * acc[t][1];
                s1 += acc[t][2] + acc[t][3];
                q1 += acc[t][2] * acc[t][2] + acc[t][3] * acc[t][3];
            }
#pragma unroll
            for (int o = 1; o <= 2; o <<= 1) {
                s0 += __shfl_xor_sync(0xffffffffu, s0, o);
                q0 += __shfl_xor_sync(0xffffffffu, q0, o);
                s1 += __shfl_xor_sync(0xffffffffu, s1, o);
                q1 += __shfl_xor_sync(0xffffffffu, q1, o);
            }
            if (tg == 0) {
                sred[(r0 * 2 + cb) * 2 + 0] = s0;
                sred[(r0 * 2 + cb) * 2 + 1] = q0;
                sred[((r0 + 8) * 2 + cb) * 2 + 0] = s1;
                sred[((r0 + 8) * 2 + cb) * 2 + 1] = q1;
            }
            __syncthreads();
            float sa = sred[(r0 * 2) * 2 + 0] + sred[(r0 * 2 + 1) * 2 + 0];
            float qa = sred[(r0 * 2) * 2 + 1] + sred[(r0 * 2 + 1) * 2 + 1];
            float sb = sred[((r0 + 8) * 2) * 2 + 0] + sred[((r0 + 8) * 2 + 1) * 2 + 0];
            float qb = sred[((r0 + 8) * 2) * 2 + 1] + sred[((r0 + 8) * 2 + 1) * 2 + 1];
            float mu0 = sa * 0.0078125f;
            float rs0 = rsqrtf(qa * 0.0078125f - mu0 * mu0 + 1e-5f);
            float mu1 = sb * 0.0078125f;
            float rs1 = rsqrtf(qb * 0.0078125f - mu1 * mu1 + 1e-5f);
            int rowA = row0 + r0, rowB = row0 + r0 + 8;
#pragma unroll
            for (int t = 0; t < 8; t++) {
                int col0 = 64 * cb + 8 * t + 2 * tg;
                float ga = __ldg(gl + col0), gb = __ldg(gl + col0 + 1);
                float ba = __ldg(bl + col0), bb = __ldg(bl + col0 + 1);
                if (rowA < NA) {
                    float2 res = __ldg((const float2*)(agts + (size_t)rowA * 128) + (col0 >> 1));
                    float y0 = fmaxf((acc[t][0] - mu0) * rs0 * ga + ba + res.x, 0.f);
                    float y1 = fmaxf((acc[t][1] - mu0) * rs0 * gb + bb + res.y, 0.f);
                    *(float2*)(out + (size_t)rowA * 128 + col0) = make_float2(y0, y1);
                }
                if (rowB < NA) {
                    float2 res = __ldg((const float2*)(agts + (size_t)rowB * 128) + (col0 >> 1));
                    float y2 = fmaxf((acc[t][2] - mu1) * rs1 * ga + ba + res.x, 0.f);
                    float y3 = fmaxf((acc[t][3] - mu1) * rs1 * gb + bb + res.y, 0.f);
                    *(float2*)(out + (size_t)rowB * 128 + col0) = make_float2(y2, y3);
                }
            }
        }
        __syncthreads();
    }
}

// ================= host =================
extern "C" void kernel_launch(void* const* d_in, const int* in_sizes, int n_in,
                              void* d_out, int out_size)
{
    const float* agts    = (const float*)d_in[0];
    const float* ctx     = (const float*)d_in[1];
    const float* actr    = (const float*)d_in[2];
    const float* cctr    = (const float*)d_in[3];
    const float* W_dist1 = (const float*)d_in[4];
    const float* b_dist1 = (const float*)d_in[5];
    const float* W_dist2 = (const float*)d_in[6];
    const float* g_dist  = (const float*)d_in[7];
    const float* b_dist  = (const float*)d_in[8];
    const float* W_q     = (const float*)d_in[9];
    const float* g_q     = (const float*)d_in[10];
    const float* b_q     = (const float*)d_in[11];
    const float* W_c1    = (const float*)d_in[12];
    const float* g_c1    = (const float*)d_in[13];
    const float* b_c1    = (const float*)d_in[14];
    const float* W_c2    = (const float*)d_in[15];
    const float* W_agt   = (const float*)d_in[16];
    const float* g_n     = (const float*)d_in[17];
    const float* b_n     = (const float*)d_in[18];
    const float* W_lin   = (const float*)d_in[19];
    const float* g_lin   = (const float*)d_in[20];
    const float* b_lin   = (const float*)d_in[21];
    const int*   hi      = (const int*)d_in[22];
    const int*   wi      = (const int*)d_in[23];
    float* out = (float*)d_out;

    const int S1 = 57856 * 4;   // k_agent_mma  (231424 B)
    const int S2 = 24576 * 4;   // k_ctx_mma    (98304 B)
    const int S3 = 57984 * 4;   // k_edge_mma   (231936 B)
    const int S4 = 24832 * 4;   // k_final_mma  (99328 B)
    cudaFuncSetAttribute(k_agent_mma, cudaFuncAttributeMaxDynamicSharedMemorySize, S1);
    cudaFuncSetAttribute(k_ctx_mma,   cudaFuncAttributeMaxDynamicSharedMemorySize, S2);
    cudaFuncSetAttribute(k_edge_mma,  cudaFuncAttributeMaxDynamicSharedMemorySize, S3);
    cudaFuncSetAttribute(k_final_mma, cudaFuncAttributeMaxDynamicSharedMemorySize, S4);

    k_agent_mma<<<152, 512, S1>>>(agts, W_q, g_q, b_q, W_c1 + 128 * 128, W_agt);
    k_ctx_mma  <<<304, 256, S2>>>(ctx, W_c1 + 256 * 128);
    k_edge_mma <<<152, 512, S3>>>(actr, cctr, hi, wi,
                                  W_dist1, b_dist1, W_dist2, g_dist, b_dist,
                                  W_c1, g_c1, b_c1, W_c2);
    k_final_mma<<<304, 256, S4>>>(agts, g_n, b_n, W_lin, g_lin, b_lin, out);
}

// round 15
// speedup vs baseline: 4.6297x; 1.2633x over previous
#include <cuda_runtime.h>
#include <cuda_fp16.h>

typedef unsigned int uint;

#define NA 100000
#define NC 150000
#define NE 500000

// ---- device scratch ----
__device__ float g_qc[NA * 128];
__device__ float g_cc[NC * 128];
__device__ float g_acc[NA * 128];

// ============================================================
// fp16 split helpers: X = xh + xl (both fp16), W = fp16 single
// ============================================================
__device__ __forceinline__ void split_store_h(uint* xh, uint* xl, int idx, float a, float b) {
    __half ah = __float2half_rn(a), bh = __float2half_rn(b);
    float ra = a - __half2float(ah);
    float rb = b - __half2float(bh);
    __half al = __float2half_rn(ra), bl = __float2half_rn(rb);
    xh[idx] = (uint)__half_as_ushort(ah) | ((uint)__half_as_ushort(bh) << 16);
    xl[idx] = (uint)__half_as_ushort(al) | ((uint)__half_as_ushort(bl) << 16);
}

__device__ __forceinline__ void mma16816h(float c[4], uint a0, uint a1, uint a2, uint a3,
                                          uint b0, uint b1) {
    asm volatile(
        "mma.sync.aligned.m16n8k16.row.col.f32.f16.f16.f32 "
        "{%0,%1,%2,%3}, {%4,%5,%6,%7}, {%8,%9}, {%0,%1,%2,%3};\n"
        : "+f"(c[0]), "+f"(c[1]), "+f"(c[2]), "+f"(c[3])
        : "r"(a0), "r"(a1), "r"(a2), "r"(a3), "r"(b0), "r"(b1));
}

// D[64 x 128] += X[64 x 128] @ W[128 x 128], fp16 2-term (xh*W + xl*W)
// This warp: rows r0..r0+7, r0+8..r0+15 ; cols nbase .. nbase+8*TT-1
template<int TT>
__device__ __forceinline__ void gemm_f16split(
    const uint* __restrict__ xh, const uint* __restrict__ xl,
    const uint* __restrict__ wh,
    float acc[TT][4], int r0, int g, int tg, int nbase)
{
    const int g4 = g << 2;
    const int ra = r0 * 64, rb = (r0 + 8) * 64;
#pragma unroll
    for (int ks = 0; ks < 8; ks++) {
        int kz0 = (tg + 8 * ks) ^ g4;
        int kz1 = kz0 ^ 4;
        uint ah0 = xh[ra + kz0], ah1 = xh[rb + kz0], ah2 = xh[ra + kz1], ah3 = xh[rb + kz1];
        uint al0 = xl[ra + kz0], al1 = xl[rb + kz0], al2 = xl[ra + kz1], al3 = xl[rb + kz1];
#pragma unroll
        for (int t = 0; t < TT; t++) {
            int nw = (nbase + 8 * t + g) * 64;
            uint b0 = wh[nw + kz0], b1 = wh[nw + kz1];
            mma16816h(acc[t], ah0, ah1, ah2, ah3, b0, b1);
            mma16816h(acc[t], al0, al1, al2, al3, b0, b1);
        }
    }
}

// One-time: transpose a 128x128 fp32 weight matrix into fp16 smem (XOR swizzled)
__device__ __forceinline__ void load_weight_h(const float* __restrict__ S, uint* dh, int tid) {
    for (int idx = tid; idx < 8192; idx += blockDim.x) {
        int kp = idx >> 7, n = idx & 127;
        __half h0 = __float2half_rn(S[(2 * kp) * 128 + n]);
        __half h1 = __float2half_rn(S[(2 * kp + 1) * 128 + n]);
        dh[n * 64 + (kp ^ ((n & 7) << 2))] =
            (uint)__half_as_ushort(h0) | ((uint)__half_as_ushort(h1) << 16);
    }
}

// Load 64 contiguous rows [row0, row0+64) of src[limit x 128] into split X smem
__device__ __forceinline__ void load_split_rows(const float* __restrict__ src, int row0, int limit,
                                                uint* xh, uint* xl, int tid) {
    for (int idx = tid; idx < 4096; idx += blockDim.x) {
        int e = idx >> 6, kw = idx & 63;
        int row = row0 + e;
        float2 v = make_float2(0.f, 0.f);
        if (row < limit) v = __ldg((const float2*)(src + (size_t)row * 128) + kw);
        split_store_h(xh, xl, e * 64 + (kw ^ ((e & 7) << 2)), v.x, v.y);
    }
}

// GroupNorm(1,128) + relu + split-store back to X smem. NQ = 16/TT column partials per row.
// Contains 2 __syncthreads (uniform across block).
template<int TT>
__device__ __forceinline__ void gn_relu_split_store(
    float acc[TT][4], uint* xh, uint* xl, float* sred,
    const float* __restrict__ gamma, const float* __restrict__ beta,
    int r0, int g, int tg, int cq)
{
    const int NQ = 16 / TT;
    float s0 = 0, q0 = 0, s1 = 0, q1 = 0;
#pragma unroll
    for (int t = 0; t < TT; t++) {
        s0 += acc[t][0] + acc[t][1];
        q0 += acc[t][0] * acc[t][0] + acc[t][1] * acc[t][1];
        s1 += acc[t][2] + acc[t][3];
        q1 += acc[t][2] * acc[t][2] + acc[t][3] * acc[t][3];
    }
#pragma unroll
    for (int o = 1; o <= 2; o <<= 1) {
        s0 += __shfl_xor_sync(0xffffffffu, s0, o);
        q0 += __shfl_xor_sync(0xffffffffu, q0, o);
        s1 += __shfl_xor_sync(0xffffffffu, s1, o);
        q1 += __shfl_xor_sync(0xffffffffu, q1, o);
    }
    if (tg == 0) {
        sred[(r0 * NQ + cq) * 2 + 0] = s0;
        sred[(r0 * NQ + cq) * 2 + 1] = q0;
        sred[((r0 + 8) * NQ + cq) * 2 + 0] = s1;
        sred[((r0 + 8) * NQ + cq) * 2 + 1] = q1;
    }
    __syncthreads();
    float sa = 0.f, qa = 0.f, sb = 0.f, qb = 0.f;
#pragma unroll
    for (int q = 0; q < NQ; q++) {
        sa += sred[(r0 * NQ + q) * 2 + 0];
        qa += sred[(r0 * NQ + q) * 2 + 1];
        sb += sred[((r0 + 8) * NQ + q) * 2 + 0];
        qb += sred[((r0 + 8) * NQ + q) * 2 + 1];
    }
    float mu0 = sa * 0.0078125f;
    float rs0 = rsqrtf(qa * 0.0078125f - mu0 * mu0 + 1e-5f);
    float mu1 = sb * 0.0078125f;
    float rs1 = rsqrtf(qb * 0.0078125f - mu1 * mu1 + 1e-5f);
    const int g4 = g << 2;
#pragma unroll
    for (int t = 0; t < TT; t++) {
        int col0 = 8 * TT * cq + 8 * t + 2 * tg;
        float ga = __ldg(gamma + col0), gb = __ldg(gamma + col0 + 1);
        float ba = __ldg(beta + col0), bb = __ldg(beta + col0 + 1);
        float e0 = fmaxf((acc[t][0] - mu0) * rs0 * ga + ba, 0.f);
        float e1 = fmaxf((acc[t][1] - mu0) * rs0 * gb + bb, 0.f);
        float e2 = fmaxf((acc[t][2] - mu1) * rs1 * ga + ba, 0.f);
        float e3 = fmaxf((acc[t][3] - mu1) * rs1 * gb + bb, 0.f);
        int cw = 4 * TT * cq + 4 * t + tg;
        split_store_h(xh, xl, r0 * 64 + (cw ^ g4), e0, e1);
        split_store_h(xh, xl, (r0 + 8) * 64 + (cw ^ g4), e2, e3);
    }
    __syncthreads();
}

// Store fragment accumulators (raw fp32) to dst rows via lane-pair shfl -> STG.128.
template<int TT>
__device__ __forceinline__ void store_frag(float* __restrict__ dst, float acc[TT][4],
                                           int row0g, int limit, int r0, int tg, int cq) {
    int rowA = row0g + r0, rowB = row0g + r0 + 8;
#pragma unroll
    for (int t = 0; t < TT; t++) {
        float s0 = (tg & 1) ? acc[t][0] : acc[t][2];
        float s1 = (tg & 1) ? acc[t][1] : acc[t][3];
        float p0 = __shfl_xor_sync(0xffffffffu, s0, 1);
        float p1 = __shfl_xor_sync(0xffffffffu, s1, 1);
        if ((tg & 1) == 0) {
            int col0 = 8 * TT * cq + 8 * t + 2 * tg;
            if (rowA < limit)
                *(float4*)(dst + (size_t)rowA * 128 + col0) = make_float4(acc[t][0], acc[t][1], p0, p1);
        } else {
            int col0 = 8 * TT * cq + 8 * t + 2 * (tg - 1);
            if (rowB < limit)
                *(float4*)(dst + (size_t)rowB * 128 + col0) = make_float4(p0, p1, acc[t][2], acc[t][3]);
        }
    }
}

// ============================================================
// K3: per-edge fused 3-layer MLP + scatter — 512 threads, 16 warps
// smem words: W2 @0 (8192) ; Wc1d @8192 ; Wc2 @16384 ; xh @24576 (4096)
//   xl @28672 (4096) ; sh @32768 (64) ; sw @32832 (64) ; sred @32896 (512)
//   total 33408 words = 133632 B
// ============================================================
__global__ __launch_bounds__(512, 1) void k_edge_mma(
    const float* __restrict__ actr, const float* __restrict__ cctr,
    const int* __restrict__ hi, const int* __restrict__ wi,
    const float* __restrict__ W1, const float* __restrict__ b1,
    const float* __restrict__ W2, const float* __restrict__ gd, const float* __restrict__ bd,
    const float* __restrict__ Wc1d, const float* __restrict__ gc1, const float* __restrict__ bc1,
    const float* __restrict__ Wc2)
{
    extern __shared__ uint usm[];
    uint* xh = usm + 24576;
    uint* xl = usm + 28672;
    int* sh = (int*)(usm + 32768);
    int* sw = (int*)(usm + 32832);
    float* sred = (float*)(usm + 32896);   // 512 words
    float* sdx = sred;                     // overlay: dead after X1 build
    float* sdy = sred + 64;

    const int tid = threadIdx.x;

    load_weight_h(W2,   usm + 0,     tid);
    load_weight_h(Wc1d, usm + 8192,  tid);
    load_weight_h(Wc2,  usm + 16384, tid);
    __syncthreads();

    const int lane = tid & 31;
    const int wid = tid >> 5;
    const int g = lane >> 2;
    const int tg = lane & 3;
    const int stripe = wid >> 2;   // 0..3
    const int cq = wid & 3;        // 0..3 col quarter
    const int r0 = 16 * stripe + g;

    const int NT = (NE + 63) / 64;
    for (int tile = blockIdx.x; tile < NT; tile += gridDim.x) {
        const int base = tile * 64;

        if (tid < 64) {
            int eg = base + tid;
            if (eg < NE) {
                int h = hi[eg], w = wi[eg];
                sh[tid] = h; sw[tid] = w;
                sdx[tid] = actr[2 * h] - cctr[2 * w];
                sdy[tid] = actr[2 * h + 1] - cctr[2 * w + 1];
            } else {
                sh[tid] = -1; sw[tid] = 0; sdx[tid] = 0.f; sdy[tid] = 0.f;
            }
        }
        __syncthreads();

        // X1 = relu(dist @ W1 + b1)
        for (int idx = tid; idx < 4096; idx += 512) {
            int e = idx >> 6, kw = idx & 63;
            float v0 = 0.f, v1 = 0.f;
            if (sh[e] >= 0) {
                int j0 = kw * 2;
                float dx = sdx[e], dy = sdy[e];
                v0 = fmaxf(fmaf(dx, __ldg(W1 + j0), fmaf(dy, __ldg(W1 + 128 + j0), __ldg(b1 + j0))), 0.f);
                v1 = fmaxf(fmaf(dx, __ldg(W1 + j0 + 1), fmaf(dy, __ldg(W1 + 128 + j0 + 1), __ldg(b1 + j0 + 1))), 0.f);
            }
            split_store_h(xh, xl, e * 64 + (kw ^ ((e & 7) << 2)), v0, v1);
        }
        __syncthreads();

        float acc[4][4];

        // GEMM1 + GN(g_dist)
#pragma unroll
        for (int t = 0; t < 4; t++) { acc[t][0] = acc[t][1] = acc[t][2] = acc[t][3] = 0.f; }
        gemm_f16split<4>(xh, xl, usm + 0, acc, r0, g, tg, 32 * cq);
        gn_relu_split_store<4>(acc, xh, xl, sred, gd, bd, r0, g, tg, cq);

        // GEMM2 (+ qc[hi] + cc[wi] preloaded) + GN(g_c1)
        {
            int h0 = sh[r0], w0i = sw[r0];
            int h1 = sh[r0 + 8], w1i = sw[r0 + 8];
            const float2* pq0 = (h0 >= 0) ? (const float2*)(g_qc + (size_t)h0 * 128) : 0;
            const float2* pc0 = (h0 >= 0) ? (const float2*)(g_cc + (size_t)w0i * 128) : 0;
            const float2* pq1 = (h1 >= 0) ? (const float2*)(g_qc + (size_t)h1 * 128) : 0;
            const float2* pc1 = (h1 >= 0) ? (const float2*)(g_cc + (size_t)w1i * 128) : 0;
#pragma unroll
            for (int t = 0; t < 4; t++) {
                int ci = (32 * cq + 8 * t + 2 * tg) >> 1;
                if (h0 >= 0) {
                    float2 a2 = __ldg(pq0 + ci), b2 = __ldg(pc0 + ci);
                    acc[t][0] = a2.x + b2.x; acc[t][1] = a2.y + b2.y;
                } else { acc[t][0] = acc[t][1] = 0.f; }
                if (h1 >= 0) {
                    float2 a2 = __ldg(pq1 + ci), b2 = __ldg(pc1 + ci);
                    acc[t][2] = a2.x + b2.x; acc[t][3] = a2.y + b2.y;
                } else { acc[t][2] = acc[t][3] = 0.f; }
            }
        }
        gemm_f16split<4>(xh, xl, usm + 8192, acc, r0, g, tg, 32 * cq);
        gn_relu_split_store<4>(acc, xh, xl, sred, gc1, bc1, r0, g, tg, cq);

        // GEMM3 + scatter (lane-pair shfl -> red.global.add.v4.f32)
#pragma unroll
        for (int t = 0; t < 4; t++) { acc[t][0] = acc[t][1] = acc[t][2] = acc[t][3] = 0.f; }
        gemm_f16split<4>(xh, xl, usm + 16384, acc, r0, g, tg, 32 * cq);
        {
            int h0 = sh[r0], h1 = sh[r0 + 8];
#pragma unroll
            for (int t = 0; t < 4; t++) {
                float s0 = (tg & 1) ? acc[t][0] : acc[t][2];
                float s1 = (tg & 1) ? acc[t][1] : acc[t][3];
                float p0 = __shfl_xor_sync(0xffffffffu, s0, 1);
                float p1 = __shfl_xor_sync(0xffffffffu, s1, 1);
                if ((tg & 1) == 0) {
                    if (h0 >= 0) {
                        float* p = g_acc + (size_t)h0 * 128 + 32 * cq + 8 * t + 2 * tg;
                        asm volatile("red.global.add.v4.f32 [%0], {%1, %2, %3, %4};"
                                     :: "l"(p), "f"(acc[t][0]), "f"(acc[t][1]), "f"(p0), "f"(p1)
                                     : "memory");
                    }
                } else {
                    if (h1 >= 0) {
                        float* p = g_acc + (size_t)h1 * 128 + 32 * cq + 8 * t + 2 * (tg - 1);
                        asm volatile("red.global.add.v4.f32 [%0], {%1, %2, %3, %4};"
                                     :: "l"(p), "f"(p0), "f"(p1), "f"(acc[t][2]), "f"(acc[t][3])
                                     : "memory");
                    }
                }
            }
        }
        __syncthreads();
    }
}

// ============================================================
// K1: per-agent precompute — 512 threads, 16 warps
// smem words: Wq @0 ; Wagt @8192 ; Wmid @16384 ; xh @24576 ; xl @28672 ; sred @32768 (512)
//   total 33280 words = 133120 B
// ============================================================
__global__ __launch_bounds__(512, 1) void k_agent_mma(
    const float* __restrict__ agts,
    const float* __restrict__ Wq, const float* __restrict__ gq, const float* __restrict__ bq,
    const float* __restrict__ Wmid, const float* __restrict__ Wagt)
{
    extern __shared__ uint usm[];
    uint* xh = usm + 24576;
    uint* xl = usm + 28672;
    float* sred = (float*)(usm + 32768);
    const int tid = threadIdx.x;

    load_weight_h(Wq,   usm + 0,     tid);
    load_weight_h(Wagt, usm + 8192,  tid);
    load_weight_h(Wmid, usm + 16384, tid);
    __syncthreads();

    const int lane = tid & 31;
    const int wid = tid >> 5;
    const int g = lane >> 2;
    const int tg = lane & 3;
    const int stripe = wid >> 2;
    const int cq = wid & 3;
    const int r0 = 16 * stripe + g;

    const int NT = (NA + 63) / 64;
    for (int tile = blockIdx.x; tile < NT; tile += gridDim.x) {
        const int row0 = tile * 64;
        load_split_rows(agts, row0, NA, xh, xl, tid);
        __syncthreads();

        float acc[4][4];
        // Wagt pass -> g_acc
#pragma unroll
        for (int t = 0; t < 4; t++) { acc[t][0] = acc[t][1] = acc[t][2] = acc[t][3] = 0.f; }
        gemm_f16split<4>(xh, xl, usm + 8192, acc, r0, g, tg, 32 * cq);
        store_frag<4>(g_acc, acc, row0, NA, r0, tg, cq);

        // Wq pass -> GN(g_q) + relu -> X
#pragma unroll
        for (int t = 0; t < 4; t++) { acc[t][0] = acc[t][1] = acc[t][2] = acc[t][3] = 0.f; }
        gemm_f16split<4>(xh, xl, usm + 0, acc, r0, g, tg, 32 * cq);
        gn_relu_split_store<4>(acc, xh, xl, sred, gq, bq, r0, g, tg, cq);

        // Wmid pass -> g_qc
#pragma unroll
        for (int t = 0; t < 4; t++) { acc[t][0] = acc[t][1] = acc[t][2] = acc[t][3] = 0.f; }
        gemm_f16split<4>(xh, xl, usm + 16384, acc, r0, g, tg, 32 * cq);
        store_frag<4>(g_qc, acc, row0, NA, r0, tg, cq);
        __syncthreads();
    }
}

// ============================================================
// K2: g_cc = ctx @ Wctx — 256 threads, 2 CTAs/SM
// smem words: W @0 (8192) ; xh @8192 ; xl @12288 -> 16384 words = 65536 B
// ============================================================
__global__ __launch_bounds__(256, 2) void k_ctx_mma(
    const float* __restrict__ ctx, const float* __restrict__ Wctx)
{
    extern __shared__ uint usm[];
    uint* xh = usm + 8192;
    uint* xl = usm + 12288;
    const int tid = threadIdx.x;

    load_weight_h(Wctx, usm + 0, tid);
    __syncthreads();

    const int lane = tid & 31;
    const int wid = tid >> 5;
    const int g = lane >> 2;
    const int tg = lane & 3;
    const int stripe = wid >> 1;
    const int cb = wid & 1;
    const int r0 = 16 * stripe + g;

    const int NT = (NC + 63) / 64;
    for (int tile = blockIdx.x; tile < NT; tile += gridDim.x) {
        const int row0 = tile * 64;
        load_split_rows(ctx, row0, NC, xh, xl, tid);
        __syncthreads();

        float acc[8][4];
#pragma unroll
        for (int t = 0; t < 8; t++) { acc[t][0] = acc[t][1] = acc[t][2] = acc[t][3] = 0.f; }
        gemm_f16split<8>(xh, xl, usm + 0, acc, r0, g, tg, 64 * cb);
        store_frag<8>(g_cc, acc, row0, NC, r0, tg, cb);
        __syncthreads();
    }
}

// ============================================================
// K4: out = relu(gn(relu(gn(g_acc)) @ Wlin) + agts) — 256 threads, 2 CTAs/SM
// smem words: W @0 (8192) ; xh @8192 ; xl @12288 ; sred @16384 (256) -> 16640 words = 66560 B
// ============================================================
__global__ __launch_bounds__(256, 2) void k_final_mma(
    const float* __restrict__ agts,
    const float* __restrict__ gnw, const float* __restrict__ bnw,
    const float* __restrict__ Wlin, const float* __restrict__ gl, const float* __restrict__ bl,
    float* __restrict__ out)
{
    extern __shared__ uint usm[];
    uint* xh = usm + 8192;
    uint* xl = usm + 12288;
    float* sred = (float*)(usm + 16384);
    const int tid = threadIdx.x;

    load_weight_h(Wlin, usm + 0, tid);
    __syncthreads();

    const int lane = tid & 31;
    const int wid = tid >> 5;
    const int g = lane >> 2;
    const int tg = lane & 3;
    const int stripe = wid >> 1;
    const int cb = wid & 1;
    const int r0 = 16 * stripe + g;
    const int arow = tid >> 2;
    const int apart = tid & 3;

    const int NT = (NA + 63) / 64;
    for (int tile = blockIdx.x; tile < NT; tile += gridDim.x) {
        const int row0 = tile * 64;

        // phase A: SIMT GN(g_n)+relu on g_acc rows -> split X smem
        {
            int rowg = row0 + arow;
            float v[32];
            if (rowg < NA) {
                const float4* p = (const float4*)(g_acc + (size_t)rowg * 128 + apart * 32);
#pragma unroll
                for (int q = 0; q < 8; q++) {
                    float4 f = __ldg(p + q);
                    v[4 * q] = f.x; v[4 * q + 1] = f.y; v[4 * q + 2] = f.z; v[4 * q + 3] = f.w;
                }
            } else {
#pragma unroll
                for (int q = 0; q < 32; q++) v[q] = 0.f;
            }
            float s = 0.f, qq = 0.f;
#pragma unroll
            for (int q = 0; q < 32; q++) { s += v[q]; qq += v[q] * v[q]; }
            s += __shfl_xor_sync(0xffffffffu, s, 1);
            qq += __shfl_xor_sync(0xffffffffu, qq, 1);
            s += __shfl_xor_sync(0xffffffffu, s, 2);
            qq += __shfl_xor_sync(0xffffffffu, qq, 2);
            float mu = s * 0.0078125f;
            float rs = rsqrtf(qq * 0.0078125f - mu * mu + 1e-5f);
            int sw4 = (arow & 7) << 2;
#pragma unroll
            for (int j = 0; j < 16; j++) {
                int c = apart * 32 + 2 * j;
                float e0 = fmaxf((v[2 * j] - mu) * rs * __ldg(gnw + c) + __ldg(bnw + c), 0.f);
                float e1 = fmaxf((v[2 * j + 1] - mu) * rs * __ldg(gnw + c + 1) + __ldg(bnw + c + 1), 0.f);
                int kw = apart * 16 + j;
                split_store_h(xh, xl, arow * 64 + (kw ^ sw4), e0, e1);
            }
        }
        __syncthreads();

        // GEMM Wlin
        float acc[8][4];
#pragma unroll
        for (int t = 0; t < 8; t++) { acc[t][0] = acc[t][1] = acc[t][2] = acc[t][3] = 0.f; }
        gemm_f16split<8>(xh, xl, usm + 0, acc, r0, g, tg, 64 * cb);

        // GN(g_lin) (no relu) + residual + relu -> out
        {
            float s0 = 0, q0 = 0, s1 = 0, q1 = 0;
#pragma unroll
            for (int t = 0; t < 8; t++) {
                s0 += acc[t][0] + acc[t][1];
                q0 += acc[t][0] * acc[t][0] + acc[t][1] * acc[t][1];
                s1 += acc[t][2] + acc[t][3];
                q1 += acc[t][2] * acc[t][2] + acc[t][3] * acc[t][3];
            }
#pragma unroll
            for (int o = 1; o <= 2; o <<= 1) {
                s0 += __shfl_xor_sync(0xffffffffu, s0, o);
                q0 += __shfl_xor_sync(0xffffffffu, q0, o);
                s1 += __shfl_xor_sync(0xffffffffu, s1, o);
                q1 += __shfl_xor_sync(0xffffffffu, q1, o);
            }
            if (tg == 0) {
                sred[(r0 * 2 + cb) * 2 + 0] = s0;
                sred[(r0 * 2 + cb) * 2 + 1] = q0;
                sred[((r0 + 8) * 2 + cb) * 2 + 0] = s1;
                sred[((r0 + 8) * 2 + cb) * 2 + 1] = q1;
            }
            __syncthreads();
            float sa = sred[(r0 * 2) * 2 + 0] + sred[(r0 * 2 + 1) * 2 + 0];
            float qa = sred[(r0 * 2) * 2 + 1] + sred[(r0 * 2 + 1) * 2 + 1];
            float sb = sred[((r0 + 8) * 2) * 2 + 0] + sred[((r0 + 8) * 2 + 1) * 2 + 0];
            float qb = sred[((r0 + 8) * 2) * 2 + 1] + sred[((r0 + 8) * 2 + 1) * 2 + 1];
            float mu0 = sa * 0.0078125f;
            float rs0 = rsqrtf(qa * 0.0078125f - mu0 * mu0 + 1e-5f);
            float mu1 = sb * 0.0078125f;
            float rs1 = rsqrtf(qb * 0.0078125f - mu1 * mu1 + 1e-5f);
            int rowA = row0 + r0, rowB = row0 + r0 + 8;
#pragma unroll
            for (int t = 0; t < 8; t++) {
                int col0 = 64 * cb + 8 * t + 2 * tg;
                float ga = __ldg(gl + col0), gb = __ldg(gl + col0 + 1);
                float ba = __ldg(bl + col0), bb = __ldg(bl + col0 + 1);
                if (rowA < NA) {
                    float2 res = __ldg((const float2*)(agts + (size_t)rowA * 128) + (col0 >> 1));
                    float y0 = fmaxf((acc[t][0] - mu0) * rs0 * ga + ba + res.x, 0.f);
                    float y1 = fmaxf((acc[t][1] - mu0) * rs0 * gb + bb + res.y, 0.f);
                    *(float2*)(out + (size_t)rowA * 128 + col0) = make_float2(y0, y1);
                }
                if (rowB < NA) {
                    float2 res = __ldg((const float2*)(agts + (size_t)rowB * 128) + (col0 >> 1));
                    float y2 = fmaxf((acc[t][2] - mu1) * rs1 * ga + ba + res.x, 0.f);
                    float y3 = fmaxf((acc[t][3] - mu1) * rs1 * gb + bb + res.y, 0.f);
                    *(float2*)(out + (size_t)rowB * 128 + col0) = make_float2(y2, y3);
                }
            }
        }
        __syncthreads();
    }
}

// ================= host =================
extern "C" void kernel_launch(void* const* d_in, const int* in_sizes, int n_in,
                              void* d_out, int out_size)
{
    const float* agts    = (const float*)d_in[0];
    const float* ctx     = (const float*)d_in[1];
    const float* actr    = (const float*)d_in[2];
    const float* cctr    = (const float*)d_in[3];
    const float* W_dist1 = (const float*)d_in[4];
    const float* b_dist1 = (const float*)d_in[5];
    const float* W_dist2 = (const float*)d_in[6];
    const float* g_dist  = (const float*)d_in[7];
    const float* b_dist  = (const float*)d_in[8];
    const float* W_q     = (const float*)d_in[9];
    const float* g_q     = (const float*)d_in[10];
    const float* b_q     = (const float*)d_in[11];
    const float* W_c1    = (const float*)d_in[12];
    const float* g_c1    = (const float*)d_in[13];
    const float* b_c1    = (const float*)d_in[14];
    const float* W_c2    = (const float*)d_in[15];
    const float* W_agt   = (const float*)d_in[16];
    const float* g_n     = (const float*)d_in[17];
    const float* b_n     = (const float*)d_in[18];
    const float* W_lin   = (const float*)d_in[19];
    const float* g_lin   = (const float*)d_in[20];
    const float* b_lin   = (const float*)d_in[21];
    const int*   hi      = (const int*)d_in[22];
    const int*   wi      = (const int*)d_in[23];
    float* out = (float*)d_out;

    const int S1 = 33280 * 4;   // k_agent_mma (133120 B)
    const int S2 = 16384 * 4;   // k_ctx_mma   (65536 B)
    const int S3 = 33408 * 4;   // k_edge_mma  (133632 B)
    const int S4 = 16640 * 4;   // k_final_mma (66560 B)
    cudaFuncSetAttribute(k_agent_mma, cudaFuncAttributeMaxDynamicSharedMemorySize, S1);
    cudaFuncSetAttribute(k_ctx_mma,   cudaFuncAttributeMaxDynamicSharedMemorySize, S2);
    cudaFuncSetAttribute(k_edge_mma,  cudaFuncAttributeMaxDynamicSharedMemorySize, S3);
    cudaFuncSetAttribute(k_final_mma, cudaFuncAttributeMaxDynamicSharedMemorySize, S4);

    k_agent_mma<<<152, 512, S1>>>(agts, W_q, g_q, b_q, W_c1 + 128 * 128, W_agt);
    k_ctx_mma  <<<304, 256, S2>>>(ctx, W_c1 + 256 * 128);
    k_edge_mma <<<152, 512, S3>>>(actr, cctr, hi, wi,
                                  W_dist1, b_dist1, W_dist2, g_dist, b_dist,
                                  W_c1, g_c1, b_c1, W_c2);
    k_final_mma<<<304, 256, S4>>>(agts, g_n, b_n, W_lin, g_lin, b_lin, out);
}

// round 16
// speedup vs baseline: 5.1347x; 1.1091x over previous
#include <cuda_runtime.h>
#include <cuda_fp16.h>

typedef unsigned int uint;

#define NA 100000
#define NC 150000
#define NE 500000

// ---- device scratch ----
__device__ float g_qc[NA * 128];
__device__ float g_cc[NC * 128];
__device__ float g_acc[NA * 128];

// group barrier (named): 256 threads per group
#define GBAR(bid) asm volatile("bar.sync %0, 256;" :: "r"(bid) : "memory")

// ============================================================
// fp16 split helpers: X = xh + xl (both fp16), W = fp16 single
// ============================================================
__device__ __forceinline__ void split_store_h(uint* xh, uint* xl, int idx, float a, float b) {
    __half ah = __float2half_rn(a), bh = __float2half_rn(b);
    float ra = a - __half2float(ah);
    float rb = b - __half2float(bh);
    __half al = __float2half_rn(ra), bl = __float2half_rn(rb);
    xh[idx] = (uint)__half_as_ushort(ah) | ((uint)__half_as_ushort(bh) << 16);
    xl[idx] = (uint)__half_as_ushort(al) | ((uint)__half_as_ushort(bl) << 16);
}

__device__ __forceinline__ void mma16816h(float c[4], uint a0, uint a1, uint a2, uint a3,
                                          uint b0, uint b1) {
    asm volatile(
        "mma.sync.aligned.m16n8k16.row.col.f32.f16.f16.f32 "
        "{%0,%1,%2,%3}, {%4,%5,%6,%7}, {%8,%9}, {%0,%1,%2,%3};\n"
        : "+f"(c[0]), "+f"(c[1]), "+f"(c[2]), "+f"(c[3])
        : "r"(a0), "r"(a1), "r"(a2), "r"(a3), "r"(b0), "r"(b1));
}

// D[64 x 128] += X[64 x 128] @ W[128 x 128], fp16 2-term (xh*W + xl*W)
// This warp: rows r0..r0+7, r0+8..r0+15 ; cols nbase .. nbase+8*TT-1
template<int TT>
__device__ __forceinline__ void gemm_f16split(
    const uint* __restrict__ xh, const uint* __restrict__ xl,
    const uint* __restrict__ wh,
    float acc[TT][4], int r0, int g, int tg, int nbase)
{
    const int g4 = g << 2;
    const int ra = r0 * 64, rb = (r0 + 8) * 64;
#pragma unroll
    for (int ks = 0; ks < 8; ks++) {
        int kz0 = (tg + 8 * ks) ^ g4;
        int kz1 = kz0 ^ 4;
        uint ah0 = xh[ra + kz0], ah1 = xh[rb + kz0], ah2 = xh[ra + kz1], ah3 = xh[rb + kz1];
        uint al0 = xl[ra + kz0], al1 = xl[rb + kz0], al2 = xl[ra + kz1], al3 = xl[rb + kz1];
#pragma unroll
        for (int t = 0; t < TT; t++) {
            int nw = (nbase + 8 * t + g) * 64;
            uint b0 = wh[nw + kz0], b1 = wh[nw + kz1];
            mma16816h(acc[t], ah0, ah1, ah2, ah3, b0, b1);
            mma16816h(acc[t], al0, al1, al2, al3, b0, b1);
        }
    }
}

// One-time: transpose a 128x128 fp32 weight matrix into fp16 smem (XOR swizzled)
__device__ __forceinline__ void load_weight_h(const float* __restrict__ S, uint* dh, int tid) {
    for (int idx = tid; idx < 8192; idx += blockDim.x) {
        int kp = idx >> 7, n = idx & 127;
        __half h0 = __float2half_rn(S[(2 * kp) * 128 + n]);
        __half h1 = __float2half_rn(S[(2 * kp + 1) * 128 + n]);
        dh[n * 64 + (kp ^ ((n & 7) << 2))] =
            (uint)__half_as_ushort(h0) | ((uint)__half_as_ushort(h1) << 16);
    }
}

// GroupNorm(1,128) + relu + split-store back to X smem (group-local, named barrier).
// TT=8 -> NQ=2 column partials per row. Contains 2 GBAR(bid).
__device__ __forceinline__ void gn_relu_split_store_g(
    float acc[8][4], uint* xh, uint* xl, float* sred,
    const float* __restrict__ gamma, const float* __restrict__ beta,
    int r0, int g, int tg, int cb, int bid)
{
    float s0 = 0, q0 = 0, s1 = 0, q1 = 0;
#pragma unroll
    for (int t = 0; t < 8; t++) {
        s0 += acc[t][0] + acc[t][1];
        q0 += acc[t][0] * acc[t][0] + acc[t][1] * acc[t][1];
        s1 += acc[t][2] + acc[t][3];
        q1 += acc[t][2] * acc[t][2] + acc[t][3] * acc[t][3];
    }
#pragma unroll
    for (int o = 1; o <= 2; o <<= 1) {
        s0 += __shfl_xor_sync(0xffffffffu, s0, o);
        q0 += __shfl_xor_sync(0xffffffffu, q0, o);
        s1 += __shfl_xor_sync(0xffffffffu, s1, o);
        q1 += __shfl_xor_sync(0xffffffffu, q1, o);
    }
    if (tg == 0) {
        sred[(r0 * 2 + cb) * 2 + 0] = s0;
        sred[(r0 * 2 + cb) * 2 + 1] = q0;
        sred[((r0 + 8) * 2 + cb) * 2 + 0] = s1;
        sred[((r0 + 8) * 2 + cb) * 2 + 1] = q1;
    }
    GBAR(bid);
    float sa = sred[(r0 * 2) * 2 + 0] + sred[(r0 * 2 + 1) * 2 + 0];
    float qa = sred[(r0 * 2) * 2 + 1] + sred[(r0 * 2 + 1) * 2 + 1];
    float sb = sred[((r0 + 8) * 2) * 2 + 0] + sred[((r0 + 8) * 2 + 1) * 2 + 0];
    float qb = sred[((r0 + 8) * 2) * 2 + 1] + sred[((r0 + 8) * 2 + 1) * 2 + 1];
    float mu0 = sa * 0.0078125f;
    float rs0 = rsqrtf(qa * 0.0078125f - mu0 * mu0 + 1e-5f);
    float mu1 = sb * 0.0078125f;
    float rs1 = rsqrtf(qb * 0.0078125f - mu1 * mu1 + 1e-5f);
    const int g4 = g << 2;
#pragma unroll
    for (int t = 0; t < 8; t++) {
        int col0 = 64 * cb + 8 * t + 2 * tg;
        float ga = __ldg(gamma + col0), gb = __ldg(gamma + col0 + 1);
        float ba = __ldg(beta + col0), bb = __ldg(beta + col0 + 1);
        float e0 = fmaxf((acc[t][0] - mu0) * rs0 * ga + ba, 0.f);
        float e1 = fmaxf((acc[t][1] - mu0) * rs0 * gb + bb, 0.f);
        float e2 = fmaxf((acc[t][2] - mu1) * rs1 * ga + ba, 0.f);
        float e3 = fmaxf((acc[t][3] - mu1) * rs1 * gb + bb, 0.f);
        int cw = 32 * cb + 4 * t + tg;
        split_store_h(xh, xl, r0 * 64 + (cw ^ g4), e0, e1);
        split_store_h(xh, xl, (r0 + 8) * 64 + (cw ^ g4), e2, e3);
    }
    GBAR(bid);
}

// Store fragment accumulators (raw fp32) to dst rows via lane-pair shfl -> STG.128.
__device__ __forceinline__ void store_frag8(float* __restrict__ dst, float acc[8][4],
                                            int row0g, int limit, int r0, int tg, int cb) {
    int rowA = row0g + r0, rowB = row0g + r0 + 8;
#pragma unroll
    for (int t = 0; t < 8; t++) {
        float s0 = (tg & 1) ? acc[t][0] : acc[t][2];
        float s1 = (tg & 1) ? acc[t][1] : acc[t][3];
        float p0 = __shfl_xor_sync(0xffffffffu, s0, 1);
        float p1 = __shfl_xor_sync(0xffffffffu, s1, 1);
        if ((tg & 1) == 0) {
            int col0 = 64 * cb + 8 * t + 2 * tg;
            if (rowA < limit)
                *(float4*)(dst + (size_t)rowA * 128 + col0) = make_float4(acc[t][0], acc[t][1], p0, p1);
        } else {
            int col0 = 64 * cb + 8 * t + 2 * (tg - 1);
            if (rowB < limit)
                *(float4*)(dst + (size_t)rowB * 128 + col0) = make_float4(p0, p1, acc[t][2], acc[t][3]);
        }
    }
}

// ============================================================
// K3: per-edge fused 3-layer MLP + scatter — 512 threads = 2 independent
// 256-thread groups sharing smem weights, each with its own tile + barriers.
// smem words: W2 @0 ; Wc1d @8192 ; Wc2 @16384 ; per-group (gid 0/1):
//   xh @24576+gid*8192 (4096) ; xl @+4096 ; sh @40960+gid*64 ; sw @41088+gid*64
//   sred @41216+gid*256 (256; sdx/sdy overlay first 128)
//   total 41728 words = 166912 B
// ============================================================
__global__ __launch_bounds__(512, 1) void k_edge_mma(
    const float* __restrict__ actr, const float* __restrict__ cctr,
    const int* __restrict__ hi, const int* __restrict__ wi,
    const float* __restrict__ W1, const float* __restrict__ b1,
    const float* __restrict__ W2, const float* __restrict__ gd, const float* __restrict__ bd,
    const float* __restrict__ Wc1d, const float* __restrict__ gc1, const float* __restrict__ bc1,
    const float* __restrict__ Wc2)
{
    extern __shared__ uint usm[];
    const int tid = threadIdx.x;

    load_weight_h(W2,   usm + 0,     tid);
    load_weight_h(Wc1d, usm + 8192,  tid);
    load_weight_h(Wc2,  usm + 16384, tid);
    __syncthreads();

    const int gid = tid >> 8;          // group 0/1
    const int gtid = tid & 255;
    const int bid = gid + 1;           // named barrier id
    uint* xh = usm + 24576 + gid * 8192;
    uint* xl = xh + 4096;
    int* sh = (int*)(usm + 40960 + gid * 64);
    int* sw = (int*)(usm + 41088 + gid * 64);
    float* sred = (float*)(usm + 41216 + gid * 256);
    float* sdx = sred;                 // overlay: dead after X1 build
    float* sdy = sred + 64;

    const int lane = gtid & 31;
    const int wid = gtid >> 5;         // 0..7 within group
    const int g = lane >> 2;
    const int tg = lane & 3;
    const int stripe = wid >> 1;       // 0..3
    const int cb = wid & 1;            // col half
    const int r0 = 16 * stripe + g;

    const int NT = (NE + 63) / 64;
    for (int tile = blockIdx.x * 2 + gid; tile < NT; tile += gridDim.x * 2) {
        const int base = tile * 64;

        if (gtid < 64) {
            int eg = base + gtid;
            if (eg < NE) {
                int h = hi[eg], w = wi[eg];
                sh[gtid] = h; sw[gtid] = w;
                sdx[gtid] = actr[2 * h] - cctr[2 * w];
                sdy[gtid] = actr[2 * h + 1] - cctr[2 * w + 1];
            } else {
                sh[gtid] = -1; sw[gtid] = 0; sdx[gtid] = 0.f; sdy[gtid] = 0.f;
            }
        }
        GBAR(bid);

        // X1 = relu(dist @ W1 + b1)
        for (int idx = gtid; idx < 4096; idx += 256) {
            int e = idx >> 6, kw = idx & 63;
            float v0 = 0.f, v1 = 0.f;
            if (sh[e] >= 0) {
                int j0 = kw * 2;
                float dx = sdx[e], dy = sdy[e];
                v0 = fmaxf(fmaf(dx, __ldg(W1 + j0), fmaf(dy, __ldg(W1 + 128 + j0), __ldg(b1 + j0))), 0.f);
                v1 = fmaxf(fmaf(dx, __ldg(W1 + j0 + 1), fmaf(dy, __ldg(W1 + 128 + j0 + 1), __ldg(b1 + j0 + 1))), 0.f);
            }
            split_store_h(xh, xl, e * 64 + (kw ^ ((e & 7) << 2)), v0, v1);
        }
        GBAR(bid);

        float acc[8][4];

        // GEMM1 + GN(g_dist)
#pragma unroll
        for (int t = 0; t < 8; t++) { acc[t][0] = acc[t][1] = acc[t][2] = acc[t][3] = 0.f; }
        gemm_f16split<8>(xh, xl, usm + 0, acc, r0, g, tg, 64 * cb);
        gn_relu_split_store_g(acc, xh, xl, sred, gd, bd, r0, g, tg, cb, bid);

        // GEMM2 (+ qc[hi] + cc[wi] preloaded) + GN(g_c1)
        {
            int h0 = sh[r0], w0i = sw[r0];
            int h1 = sh[r0 + 8], w1i = sw[r0 + 8];
            const float2* pq0 = (h0 >= 0) ? (const float2*)(g_qc + (size_t)h0 * 128) : 0;
            const float2* pc0 = (h0 >= 0) ? (const float2*)(g_cc + (size_t)w0i * 128) : 0;
            const float2* pq1 = (h1 >= 0) ? (const float2*)(g_qc + (size_t)h1 * 128) : 0;
            const float2* pc1 = (h1 >= 0) ? (const float2*)(g_cc + (size_t)w1i * 128) : 0;
#pragma unroll
            for (int t = 0; t < 8; t++) {
                int ci = (64 * cb + 8 * t + 2 * tg) >> 1;
                if (h0 >= 0) {
                    float2 a2 = __ldg(pq0 + ci), b2 = __ldg(pc0 + ci);
                    acc[t][0] = a2.x + b2.x; acc[t][1] = a2.y + b2.y;
                } else { acc[t][0] = acc[t][1] = 0.f; }
                if (h1 >= 0) {
                    float2 a2 = __ldg(pq1 + ci), b2 = __ldg(pc1 + ci);
                    acc[t][2] = a2.x + b2.x; acc[t][3] = a2.y + b2.y;
                } else { acc[t][2] = acc[t][3] = 0.f; }
            }
        }
        gemm_f16split<8>(xh, xl, usm + 8192, acc, r0, g, tg, 64 * cb);
        gn_relu_split_store_g(acc, xh, xl, sred, gc1, bc1, r0, g, tg, cb, bid);

        // GEMM3 + scatter (lane-pair shfl -> red.global.add.v4.f32)
#pragma unroll
        for (int t = 0; t < 8; t++) { acc[t][0] = acc[t][1] = acc[t][2] = acc[t][3] = 0.f; }
        gemm_f16split<8>(xh, xl, usm + 16384, acc, r0, g, tg, 64 * cb);
        {
            int h0 = sh[r0], h1 = sh[r0 + 8];
#pragma unroll
            for (int t = 0; t < 8; t++) {
                float s0 = (tg & 1) ? acc[t][0] : acc[t][2];
                float s1 = (tg & 1) ? acc[t][1] : acc[t][3];
                float p0 = __shfl_xor_sync(0xffffffffu, s0, 1);
                float p1 = __shfl_xor_sync(0xffffffffu, s1, 1);
                if ((tg & 1) == 0) {
                    if (h0 >= 0) {
                        float* p = g_acc + (size_t)h0 * 128 + 64 * cb + 8 * t + 2 * tg;
                        asm volatile("red.global.add.v4.f32 [%0], {%1, %2, %3, %4};"
                                     :: "l"(p), "f"(acc[t][0]), "f"(acc[t][1]), "f"(p0), "f"(p1)
                                     : "memory");
                    }
                } else {
                    if (h1 >= 0) {
                        float* p = g_acc + (size_t)h1 * 128 + 64 * cb + 8 * t + 2 * (tg - 1);
                        asm volatile("red.global.add.v4.f32 [%0], {%1, %2, %3, %4};"
                                     :: "l"(p), "f"(p0), "f"(p1), "f"(acc[t][2]), "f"(acc[t][3])
                                     : "memory");
                    }
                }
            }
        }
        GBAR(bid);
    }
}

// ============================================================
// K1: per-agent precompute — 512 threads = 2 groups sharing weights
// smem words: Wq @0 ; Wagt @8192 ; Wmid @16384 ; per-group:
//   xh @24576+gid*8192 ; xl @+4096 ; sred @40960+gid*256
//   total 41472 words = 165888 B
// ============================================================
__global__ __launch_bounds__(512, 1) void k_agent_mma(
    const float* __restrict__ agts,
    const float* __restrict__ Wq, const float* __restrict__ gq, const float* __restrict__ bq,
    const float* __restrict__ Wmid, const float* __restrict__ Wagt)
{
    extern __shared__ uint usm[];
    const int tid = threadIdx.x;

    load_weight_h(Wq,   usm + 0,     tid);
    load_weight_h(Wagt, usm + 8192,  tid);
    load_weight_h(Wmid, usm + 16384, tid);
    __syncthreads();

    const int gid = tid >> 8;
    const int gtid = tid & 255;
    const int bid = gid + 1;
    uint* xh = usm + 24576 + gid * 8192;
    uint* xl = xh + 4096;
    float* sred = (float*)(usm + 40960 + gid * 256);

    const int lane = gtid & 31;
    const int wid = gtid >> 5;
    const int g = lane >> 2;
    const int tg = lane & 3;
    const int stripe = wid >> 1;
    const int cb = wid & 1;
    const int r0 = 16 * stripe + g;

    const int NT = (NA + 63) / 64;
    for (int tile = blockIdx.x * 2 + gid; tile < NT; tile += gridDim.x * 2) {
        const int row0 = tile * 64;
        // load 64 rows into split X (group-local)
        for (int idx = gtid; idx < 4096; idx += 256) {
            int e = idx >> 6, kw = idx & 63;
            int row = row0 + e;
            float2 v = make_float2(0.f, 0.f);
            if (row < NA) v = __ldg((const float2*)(agts + (size_t)row * 128) + kw);
            split_store_h(xh, xl, e * 64 + (kw ^ ((e & 7) << 2)), v.x, v.y);
        }
        GBAR(bid);

        float acc[8][4];
        // Wagt pass -> g_acc
#pragma unroll
        for (int t = 0; t < 8; t++) { acc[t][0] = acc[t][1] = acc[t][2] = acc[t][3] = 0.f; }
        gemm_f16split<8>(xh, xl, usm + 8192, acc, r0, g, tg, 64 * cb);
        store_frag8(g_acc, acc, row0, NA, r0, tg, cb);

        // Wq pass -> GN(g_q) + relu -> X
#pragma unroll
        for (int t = 0; t < 8; t++) { acc[t][0] = acc[t][1] = acc[t][2] = acc[t][3] = 0.f; }
        gemm_f16split<8>(xh, xl, usm + 0, acc, r0, g, tg, 64 * cb);
        gn_relu_split_store_g(acc, xh, xl, sred, gq, bq, r0, g, tg, cb, bid);

        // Wmid pass -> g_qc
#pragma unroll
        for (int t = 0; t < 8; t++) { acc[t][0] = acc[t][1] = acc[t][2] = acc[t][3] = 0.f; }
        gemm_f16split<8>(xh, xl, usm + 16384, acc, r0, g, tg, 64 * cb);
        store_frag8(g_qc, acc, row0, NA, r0, tg, cb);
        GBAR(bid);
    }
}

// ============================================================
// K2: g_cc = ctx @ Wctx — 256 threads, 2 CTAs/SM
// ============================================================
__global__ __launch_bounds__(256, 2) void k_ctx_mma(
    const float* __restrict__ ctx, const float* __restrict__ Wctx)
{
    extern __shared__ uint usm[];
    uint* xh = usm + 8192;
    uint* xl = usm + 12288;
    const int tid = threadIdx.x;

    load_weight_h(Wctx, usm + 0, tid);
    __syncthreads();

    const int lane = tid & 31;
    const int wid = tid >> 5;
    const int g = lane >> 2;
    const int tg = lane & 3;
    const int stripe = wid >> 1;
    const int cb = wid & 1;
    const int r0 = 16 * stripe + g;

    const int NT = (NC + 63) / 64;
    for (int tile = blockIdx.x; tile < NT; tile += gridDim.x) {
        const int row0 = tile * 64;
        for (int idx = tid; idx < 4096; idx += 256) {
            int e = idx >> 6, kw = idx & 63;
            int row = row0 + e;
            float2 v = make_float2(0.f, 0.f);
            if (row < NC) v = __ldg((const float2*)(ctx + (size_t)row * 128) + kw);
            split_store_h(xh, xl, e * 64 + (kw ^ ((e & 7) << 2)), v.x, v.y);
        }
        __syncthreads();

        float acc[8][4];
#pragma unroll
        for (int t = 0; t < 8; t++) { acc[t][0] = acc[t][1] = acc[t][2] = acc[t][3] = 0.f; }
        gemm_f16split<8>(xh, xl, usm + 0, acc, r0, g, tg, 64 * cb);
        store_frag8(g_cc, acc, row0, NC, r0, tg, cb);
        __syncthreads();
    }
}

// ============================================================
// K4: out = relu(gn(relu(gn(g_acc)) @ Wlin) + agts) — 256 threads, 2 CTAs/SM
// ============================================================
__global__ __launch_bounds__(256, 2) void k_final_mma(
    const float* __restrict__ agts,
    const float* __restrict__ gnw, const float* __restrict__ bnw,
    const float* __restrict__ Wlin, const float* __restrict__ gl, const float* __restrict__ bl,
    float* __restrict__ out)
{
    extern __shared__ uint usm[];
    uint* xh = usm + 8192;
    uint* xl = usm + 12288;
    float* sred = (float*)(usm + 16384);
    const int tid = threadIdx.x;

    load_weight_h(Wlin, usm + 0, tid);
    __syncthreads();

    const int lane = tid & 31;
    const int wid = tid >> 5;
    const int g = lane >> 2;
    const int tg = lane & 3;
    const int stripe = wid >> 1;
    const int cb = wid & 1;
    const int r0 = 16 * stripe + g;
    const int arow = tid >> 2;
    const int apart = tid & 3;

    const int NT = (NA + 63) / 64;
    for (int tile = blockIdx.x; tile < NT; tile += gridDim.x) {
        const int row0 = tile * 64;

        // phase A: SIMT GN(g_n)+relu on g_acc rows -> split X smem
        {
            int rowg = row0 + arow;
            float v[32];
            if (rowg < NA) {
                const float4* p = (const float4*)(g_acc + (size_t)rowg * 128 + apart * 32);
#pragma unroll
                for (int q = 0; q < 8; q++) {
                    float4 f = __ldg(p + q);
                    v[4 * q] = f.x; v[4 * q + 1] = f.y; v[4 * q + 2] = f.z; v[4 * q + 3] = f.w;
                }
            } else {
#pragma unroll
                for (int q = 0; q < 32; q++) v[q] = 0.f;
            }
            float s = 0.f, qq = 0.f;
#pragma unroll
            for (int q = 0; q < 32; q++) { s += v[q]; qq += v[q] * v[q]; }
            s += __shfl_xor_sync(0xffffffffu, s, 1);
            qq += __shfl_xor_sync(0xffffffffu, qq, 1);
            s += __shfl_xor_sync(0xffffffffu, s, 2);
            qq += __shfl_xor_sync(0xffffffffu, qq, 2);
            float mu = s * 0.0078125f;
            float rs = rsqrtf(qq * 0.0078125f - mu * mu + 1e-5f);
            int sw4 = (arow & 7) << 2;
#pragma unroll
            for (int j = 0; j < 16; j++) {
                int c = apart * 32 + 2 * j;
                float e0 = fmaxf((v[2 * j] - mu) * rs * __ldg(gnw + c) + __ldg(bnw + c), 0.f);
                float e1 = fmaxf((v[2 * j + 1] - mu) * rs * __ldg(gnw + c + 1) + __ldg(bnw + c + 1), 0.f);
                int kw = apart * 16 + j;
                split_store_h(xh, xl, arow * 64 + (kw ^ sw4), e0, e1);
            }
        }
        __syncthreads();

        // GEMM Wlin
        float acc[8][4];
#pragma unroll
        for (int t = 0; t < 8; t++) { acc[t][0] = acc[t][1] = acc[t][2] = acc[t][3] = 0.f; }
        gemm_f16split<8>(xh, xl, usm + 0, acc, r0, g, tg, 64 * cb);

        // GN(g_lin) (no relu) + residual + relu -> out
        {
            float s0 = 0, q0 = 0, s1 = 0, q1 = 0;
#pragma unroll
            for (int t = 0; t < 8; t++) {
                s0 += acc[t][0] + acc[t][1];
                q0 += acc[t][0] * acc[t][0] + acc[t][1] * acc[t][1];
                s1 += acc[t][2] + acc[t][3];
                q1 += acc[t][2] * acc[t][2] + acc[t][3] * acc[t][3];
            }
#pragma unroll
            for (int o = 1; o <= 2; o <<= 1) {
                s0 += __shfl_xor_sync(0xffffffffu, s0, o);
                q0 += __shfl_xor_sync(0xffffffffu, q0, o);
                s1 += __shfl_xor_sync(0xffffffffu, s1, o);
                q1 += __shfl_xor_sync(0xffffffffu, q1, o);
            }
            if (tg == 0) {
                sred[(r0 * 2 + cb) * 2 + 0] = s0;
                sred[(r0 * 2 + cb) * 2 + 1] = q0;
                sred[((r0 + 8) * 2 + cb) * 2 + 0] = s1;
                sred[((r0 + 8) * 2 + cb) * 2 + 1] = q1;
            }
            __syncthreads();
            float sa = sred[(r0 * 2) * 2 + 0] + sred[(r0 * 2 + 1) * 2 + 0];
            float qa = sred[(r0 * 2) * 2 + 1] + sred[(r0 * 2 + 1) * 2 + 1];
            float sb = sred[((r0 + 8) * 2) * 2 + 0] + sred[((r0 + 8) * 2 + 1) * 2 + 0];
            float qb = sred[((r0 + 8) * 2) * 2 + 1] + sred[((r0 + 8) * 2 + 1) * 2 + 1];
            float mu0 = sa * 0.0078125f;
            float rs0 = rsqrtf(qa * 0.0078125f - mu0 * mu0 + 1e-5f);
            float mu1 = sb * 0.0078125f;
            float rs1 = rsqrtf(qb * 0.0078125f - mu1 * mu1 + 1e-5f);
            int rowA = row0 + r0, rowB = row0 + r0 + 8;
#pragma unroll
            for (int t = 0; t < 8; t++) {
                int col0 = 64 * cb + 8 * t + 2 * tg;
                float ga = __ldg(gl + col0), gb = __ldg(gl + col0 + 1);
                float ba = __ldg(bl + col0), bb = __ldg(bl + col0 + 1);
                if (rowA < NA) {
                    float2 res = __ldg((const float2*)(agts + (size_t)rowA * 128) + (col0 >> 1));
                    float y0 = fmaxf((acc[t][0] - mu0) * rs0 * ga + ba + res.x, 0.f);
                    float y1 = fmaxf((acc[t][1] - mu0) * rs0 * gb + bb + res.y, 0.f);
                    *(float2*)(out + (size_t)rowA * 128 + col0) = make_float2(y0, y1);
                }
                if (rowB < NA) {
                    float2 res = __ldg((const float2*)(agts + (size_t)rowB * 128) + (col0 >> 1));
                    float y2 = fmaxf((acc[t][2] - mu1) * rs1 * ga + ba + res.x, 0.f);
                    float y3 = fmaxf((acc[t][3] - mu1) * rs1 * gb + bb + res.y, 0.f);
                    *(float2*)(out + (size_t)rowB * 128 + col0) = make_float2(y2, y3);
                }
            }
        }
        __syncthreads();
    }
}

// ================= host =================
extern "C" void kernel_launch(void* const* d_in, const int* in_sizes, int n_in,
                              void* d_out, int out_size)
{
    const float* agts    = (const float*)d_in[0];
    const float* ctx     = (const float*)d_in[1];
    const float* actr    = (const float*)d_in[2];
    const float* cctr    = (const float*)d_in[3];
    const float* W_dist1 = (const float*)d_in[4];
    const float* b_dist1 = (const float*)d_in[5];
    const float* W_dist2 = (const float*)d_in[6];
    const float* g_dist  = (const float*)d_in[7];
    const float* b_dist  = (const float*)d_in[8];
    const float* W_q     = (const float*)d_in[9];
    const float* g_q     = (const float*)d_in[10];
    const float* b_q     = (const float*)d_in[11];
    const float* W_c1    = (const float*)d_in[12];
    const float* g_c1    = (const float*)d_in[13];
    const float* b_c1    = (const float*)d_in[14];
    const float* W_c2    = (const float*)d_in[15];
    const float* W_agt   = (const float*)d_in[16];
    const float* g_n     = (const float*)d_in[17];
    const float* b_n     = (const float*)d_in[18];
    const float* W_lin   = (const float*)d_in[19];
    const float* g_lin   = (const float*)d_in[20];
    const float* b_lin   = (const float*)d_in[21];
    const int*   hi      = (const int*)d_in[22];
    const int*   wi      = (const int*)d_in[23];
    float* out = (float*)d_out;

    const int S1 = 41472 * 4;   // k_agent_mma (165888 B)
    const int S2 = 16384 * 4;   // k_ctx_mma   (65536 B)
    const int S3 = 41728 * 4;   // k_edge_mma  (166912 B)
    const int S4 = 16640 * 4;   // k_final_mma (66560 B)
    cudaFuncSetAttribute(k_agent_mma, cudaFuncAttributeMaxDynamicSharedMemorySize, S1);
    cudaFuncSetAttribute(k_ctx_mma,   cudaFuncAttributeMaxDynamicSharedMemorySize, S2);
    cudaFuncSetAttribute(k_edge_mma,  cudaFuncAttributeMaxDynamicSharedMemorySize, S3);
    cudaFuncSetAttribute(k_final_mma, cudaFuncAttributeMaxDynamicSharedMemorySize, S4);

    k_agent_mma<<<152, 512, S1>>>(agts, W_q, g_q, b_q, W_c1 + 128 * 128, W_agt);
    k_ctx_mma  <<<304, 256, S2>>>(ctx, W_c1 + 256 * 128);
    k_edge_mma <<<152, 512, S3>>>(actr, cctr, hi, wi,
                                  W_dist1, b_dist1, W_dist2, g_dist, b_dist,
                                  W_c1, g_c1, b_c1, W_c2);
    k_final_mma<<<304, 256, S4>>>(agts, g_n, b_n, W_lin, g_lin, b_lin, out);
}

// round 17
// speedup vs baseline: 5.1554x; 1.0040x over previous
#include <cuda_runtime.h>
#include <cuda_fp16.h>

typedef unsigned int uint;

#define NA 100000
#define NC 150000
#define NE 500000

// ---- device scratch ----
__device__ float g_qc[NA * 128];
__device__ float g_cc[NC * 128];
__device__ float g_acc[NA * 128];

// group barrier (named): 256 threads per group
#define GBAR(bid) asm volatile("bar.sync %0, 256;" :: "r"(bid) : "memory")

// ============================================================
// fp16 split helpers: X = xh + xl (both fp16), W = fp16 single
// ============================================================
__device__ __forceinline__ void split_store_h(uint* xh, uint* xl, int idx, float a, float b) {
    __half ah = __float2half_rn(a), bh = __float2half_rn(b);
    float ra = a - __half2float(ah);
    float rb = b - __half2float(bh);
    __half al = __float2half_rn(ra), bl = __float2half_rn(rb);
    xh[idx] = (uint)__half_as_ushort(ah) | ((uint)__half_as_ushort(bh) << 16);
    xl[idx] = (uint)__half_as_ushort(al) | ((uint)__half_as_ushort(bl) << 16);
}

__device__ __forceinline__ void mma16816h(float c[4], uint a0, uint a1, uint a2, uint a3,
                                          uint b0, uint b1) {
    asm volatile(
        "mma.sync.aligned.m16n8k16.row.col.f32.f16.f16.f32 "
        "{%0,%1,%2,%3}, {%4,%5,%6,%7}, {%8,%9}, {%0,%1,%2,%3};\n"
        : "+f"(c[0]), "+f"(c[1]), "+f"(c[2]), "+f"(c[3])
        : "r"(a0), "r"(a1), "r"(a2), "r"(a3), "r"(b0), "r"(b1));
}

// D[64 x 128] += X[64 x 128] @ W[128 x 128], fp16 2-term (xh*W + xl*W)
template<int TT>
__device__ __forceinline__ void gemm_f16split(
    const uint* __restrict__ xh, const uint* __restrict__ xl,
    const uint* __restrict__ wh,
    float acc[TT][4], int r0, int g, int tg, int nbase)
{
    const int g4 = g << 2;
    const int ra = r0 * 64, rb = (r0 + 8) * 64;
#pragma unroll
    for (int ks = 0; ks < 8; ks++) {
        int kz0 = (tg + 8 * ks) ^ g4;
        int kz1 = kz0 ^ 4;
        uint ah0 = xh[ra + kz0], ah1 = xh[rb + kz0], ah2 = xh[ra + kz1], ah3 = xh[rb + kz1];
        uint al0 = xl[ra + kz0], al1 = xl[rb + kz0], al2 = xl[ra + kz1], al3 = xl[rb + kz1];
#pragma unroll
        for (int t = 0; t < TT; t++) {
            int nw = (nbase + 8 * t + g) * 64;
            uint b0 = wh[nw + kz0], b1 = wh[nw + kz1];
            mma16816h(acc[t], ah0, ah1, ah2, ah3, b0, b1);
            mma16816h(acc[t], al0, al1, al2, al3, b0, b1);
        }
    }
}

// One-time: transpose a 128x128 fp32 weight matrix into fp16 smem (XOR swizzled)
__device__ __forceinline__ void load_weight_h(const float* __restrict__ S, uint* dh, int tid) {
    for (int idx = tid; idx < 8192; idx += blockDim.x) {
        int kp = idx >> 7, n = idx & 127;
        __half h0 = __float2half_rn(S[(2 * kp) * 128 + n]);
        __half h1 = __float2half_rn(S[(2 * kp + 1) * 128 + n]);
        dh[n * 64 + (kp ^ ((n & 7) << 2))] =
            (uint)__half_as_ushort(h0) | ((uint)__half_as_ushort(h1) << 16);
    }
}

// GroupNorm(1,128) + relu + split-store back to X smem (group-local, named barrier).
__device__ __forceinline__ void gn_relu_split_store_g(
    float acc[8][4], uint* xh, uint* xl, float* sred,
    const float* __restrict__ gamma, const float* __restrict__ beta,
    int r0, int g, int tg, int cb, int bid)
{
    float s0 = 0, q0 = 0, s1 = 0, q1 = 0;
#pragma unroll
    for (int t = 0; t < 8; t++) {
        s0 += acc[t][0] + acc[t][1];
        q0 += acc[t][0] * acc[t][0] + acc[t][1] * acc[t][1];
        s1 += acc[t][2] + acc[t][3];
        q1 += acc[t][2] * acc[t][2] + acc[t][3] * acc[t][3];
    }
#pragma unroll
    for (int o = 1; o <= 2; o <<= 1) {
        s0 += __shfl_xor_sync(0xffffffffu, s0, o);
        q0 += __shfl_xor_sync(0xffffffffu, q0, o);
        s1 += __shfl_xor_sync(0xffffffffu, s1, o);
        q1 += __shfl_xor_sync(0xffffffffu, q1, o);
    }
    if (tg == 0) {
        sred[(r0 * 2 + cb) * 2 + 0] = s0;
        sred[(r0 * 2 + cb) * 2 + 1] = q0;
        sred[((r0 + 8) * 2 + cb) * 2 + 0] = s1;
        sred[((r0 + 8) * 2 + cb) * 2 + 1] = q1;
    }
    GBAR(bid);
    float sa = sred[(r0 * 2) * 2 + 0] + sred[(r0 * 2 + 1) * 2 + 0];
    float qa = sred[(r0 * 2) * 2 + 1] + sred[(r0 * 2 + 1) * 2 + 1];
    float sb = sred[((r0 + 8) * 2) * 2 + 0] + sred[((r0 + 8) * 2 + 1) * 2 + 0];
    float qb = sred[((r0 + 8) * 2) * 2 + 1] + sred[((r0 + 8) * 2 + 1) * 2 + 1];
    float mu0 = sa * 0.0078125f;
    float rs0 = rsqrtf(qa * 0.0078125f - mu0 * mu0 + 1e-5f);
    float mu1 = sb * 0.0078125f;
    float rs1 = rsqrtf(qb * 0.0078125f - mu1 * mu1 + 1e-5f);
    const int g4 = g << 2;
#pragma unroll
    for (int t = 0; t < 8; t++) {
        int col0 = 64 * cb + 8 * t + 2 * tg;
        float ga = __ldg(gamma + col0), gb = __ldg(gamma + col0 + 1);
        float ba = __ldg(beta + col0), bb = __ldg(beta + col0 + 1);
        float e0 = fmaxf((acc[t][0] - mu0) * rs0 * ga + ba, 0.f);
        float e1 = fmaxf((acc[t][1] - mu0) * rs0 * gb + bb, 0.f);
        float e2 = fmaxf((acc[t][2] - mu1) * rs1 * ga + ba, 0.f);
        float e3 = fmaxf((acc[t][3] - mu1) * rs1 * gb + bb, 0.f);
        int cw = 32 * cb + 4 * t + tg;
        split_store_h(xh, xl, r0 * 64 + (cw ^ g4), e0, e1);
        split_store_h(xh, xl, (r0 + 8) * 64 + (cw ^ g4), e2, e3);
    }
    GBAR(bid);
}

// Store fragment accumulators (raw fp32) to dst rows via lane-pair shfl -> STG.128.
__device__ __forceinline__ void store_frag8(float* __restrict__ dst, float acc[8][4],
                                            int row0g, int limit, int r0, int tg, int cb) {
    int rowA = row0g + r0, rowB = row0g + r0 + 8;
#pragma unroll
    for (int t = 0; t < 8; t++) {
        float s0 = (tg & 1) ? acc[t][0] : acc[t][2];
        float s1 = (tg & 1) ? acc[t][1] : acc[t][3];
        float p0 = __shfl_xor_sync(0xffffffffu, s0, 1);
        float p1 = __shfl_xor_sync(0xffffffffu, s1, 1);
        if ((tg & 1) == 0) {
            int col0 = 64 * cb + 8 * t + 2 * tg;
            if (rowA < limit)
                *(float4*)(dst + (size_t)rowA * 128 + col0) = make_float4(acc[t][0], acc[t][1], p0, p1);
        } else {
            int col0 = 64 * cb + 8 * t + 2 * (tg - 1);
            if (rowB < limit)
                *(float4*)(dst + (size_t)rowB * 128 + col0) = make_float4(p0, p1, acc[t][2], acc[t][3]);
        }
    }
}

// ============================================================
// K_PRE (fused K1+K2): agent precompute AND ctx precompute in one
// persistent kernel. 512 threads = 2 independent 256-thread groups
// sharing 4 smem weight matrices; combined tile list (agent then ctx).
// smem words: Wq @0 ; Wagt @8192 ; Wmid @16384 ; Wctx @24576 ;
//   per-group: xh @32768+gid*8192 (4096) ; xl @+4096 ; sred @49152+gid*256
//   total 49664 words = 198656 B
// ============================================================
#define NTA ((NA + 63) / 64)
#define NTC ((NC + 63) / 64)

__global__ __launch_bounds__(512, 1) void k_pre_mma(
    const float* __restrict__ agts, const float* __restrict__ ctx,
    const float* __restrict__ Wq, const float* __restrict__ gq, const float* __restrict__ bq,
    const float* __restrict__ Wmid, const float* __restrict__ Wagt,
    const float* __restrict__ Wctx)
{
    extern __shared__ uint usm[];
    const int tid = threadIdx.x;

    load_weight_h(Wq,   usm + 0,     tid);
    load_weight_h(Wagt, usm + 8192,  tid);
    load_weight_h(Wmid, usm + 16384, tid);
    load_weight_h(Wctx, usm + 24576, tid);
    __syncthreads();

    const int gid = tid >> 8;
    const int gtid = tid & 255;
    const int bid = gid + 1;
    uint* xh = usm + 32768 + gid * 8192;
    uint* xl = xh + 4096;
    float* sred = (float*)(usm + 49152 + gid * 256);

    const int lane = gtid & 31;
    const int wid = gtid >> 5;
    const int g = lane >> 2;
    const int tg = lane & 3;
    const int stripe = wid >> 1;
    const int cb = wid & 1;
    const int r0 = 16 * stripe + g;

    const int NT_ALL = NTA + NTC;
    for (int tile = blockIdx.x * 2 + gid; tile < NT_ALL; tile += gridDim.x * 2) {
        float acc[8][4];
        if (tile < NTA) {
            // ---------- agent tile ----------
            const int row0 = tile * 64;
            for (int idx = gtid; idx < 4096; idx += 256) {
                int e = idx >> 6, kw = idx & 63;
                int row = row0 + e;
                float2 v = make_float2(0.f, 0.f);
                if (row < NA) v = __ldg((const float2*)(agts + (size_t)row * 128) + kw);
                split_store_h(xh, xl, e * 64 + (kw ^ ((e & 7) << 2)), v.x, v.y);
            }
            GBAR(bid);

            // Wagt pass -> g_acc
#pragma unroll
            for (int t = 0; t < 8; t++) { acc[t][0] = acc[t][1] = acc[t][2] = acc[t][3] = 0.f; }
            gemm_f16split<8>(xh, xl, usm + 8192, acc, r0, g, tg, 64 * cb);
            store_frag8(g_acc, acc, row0, NA, r0, tg, cb);

            // Wq pass -> GN(g_q) + relu -> X
#pragma unroll
            for (int t = 0; t < 8; t++) { acc[t][0] = acc[t][1] = acc[t][2] = acc[t][3] = 0.f; }
            gemm_f16split<8>(xh, xl, usm + 0, acc, r0, g, tg, 64 * cb);
            gn_relu_split_store_g(acc, xh, xl, sred, gq, bq, r0, g, tg, cb, bid);

            // Wmid pass -> g_qc
#pragma unroll
            for (int t = 0; t < 8; t++) { acc[t][0] = acc[t][1] = acc[t][2] = acc[t][3] = 0.f; }
            gemm_f16split<8>(xh, xl, usm + 16384, acc, r0, g, tg, 64 * cb);
            store_frag8(g_qc, acc, row0, NA, r0, tg, cb);
            GBAR(bid);
        } else {
            // ---------- ctx tile ----------
            const int row0 = (tile - NTA) * 64;
            for (int idx = gtid; idx < 4096; idx += 256) {
                int e = idx >> 6, kw = idx & 63;
                int row = row0 + e;
                float2 v = make_float2(0.f, 0.f);
                if (row < NC) v = __ldg((const float2*)(ctx + (size_t)row * 128) + kw);
                split_store_h(xh, xl, e * 64 + (kw ^ ((e & 7) << 2)), v.x, v.y);
            }
            GBAR(bid);

#pragma unroll
            for (int t = 0; t < 8; t++) { acc[t][0] = acc[t][1] = acc[t][2] = acc[t][3] = 0.f; }
            gemm_f16split<8>(xh, xl, usm + 24576, acc, r0, g, tg, 64 * cb);
            store_frag8(g_cc, acc, row0, NC, r0, tg, cb);
            GBAR(bid);
        }
    }
}

// ============================================================
// K3: per-edge fused 3-layer MLP + scatter — 512 threads = 2 groups
// (unchanged from R16)
// ============================================================
__global__ __launch_bounds__(512, 1) void k_edge_mma(
    const float* __restrict__ actr, const float* __restrict__ cctr,
    const int* __restrict__ hi, const int* __restrict__ wi,
    const float* __restrict__ W1, const float* __restrict__ b1,
    const float* __restrict__ W2, const float* __restrict__ gd, const float* __restrict__ bd,
    const float* __restrict__ Wc1d, const float* __restrict__ gc1, const float* __restrict__ bc1,
    const float* __restrict__ Wc2)
{
    extern __shared__ uint usm[];
    const int tid = threadIdx.x;

    load_weight_h(W2,   usm + 0,     tid);
    load_weight_h(Wc1d, usm + 8192,  tid);
    load_weight_h(Wc2,  usm + 16384, tid);
    __syncthreads();

    const int gid = tid >> 8;
    const int gtid = tid & 255;
    const int bid = gid + 1;
    uint* xh = usm + 24576 + gid * 8192;
    uint* xl = xh + 4096;
    int* sh = (int*)(usm + 40960 + gid * 64);
    int* sw = (int*)(usm + 41088 + gid * 64);
    float* sred = (float*)(usm + 41216 + gid * 256);
    float* sdx = sred;
    float* sdy = sred + 64;

    const int lane = gtid & 31;
    const int wid = gtid >> 5;
    const int g = lane >> 2;
    const int tg = lane & 3;
    const int stripe = wid >> 1;
    const int cb = wid & 1;
    const int r0 = 16 * stripe + g;

    const int NT = (NE + 63) / 64;
    for (int tile = blockIdx.x * 2 + gid; tile < NT; tile += gridDim.x * 2) {
        const int base = tile * 64;

        if (gtid < 64) {
            int eg = base + gtid;
            if (eg < NE) {
                int h = hi[eg], w = wi[eg];
                sh[gtid] = h; sw[gtid] = w;
                sdx[gtid] = actr[2 * h] - cctr[2 * w];
                sdy[gtid] = actr[2 * h + 1] - cctr[2 * w + 1];
            } else {
                sh[gtid] = -1; sw[gtid] = 0; sdx[gtid] = 0.f; sdy[gtid] = 0.f;
            }
        }
        GBAR(bid);

        // X1 = relu(dist @ W1 + b1)
        for (int idx = gtid; idx < 4096; idx += 256) {
            int e = idx >> 6, kw = idx & 63;
            float v0 = 0.f, v1 = 0.f;
            if (sh[e] >= 0) {
                int j0 = kw * 2;
                float dx = sdx[e], dy = sdy[e];
                v0 = fmaxf(fmaf(dx, __ldg(W1 + j0), fmaf(dy, __ldg(W1 + 128 + j0), __ldg(b1 + j0))), 0.f);
                v1 = fmaxf(fmaf(dx, __ldg(W1 + j0 + 1), fmaf(dy, __ldg(W1 + 128 + j0 + 1), __ldg(b1 + j0 + 1))), 0.f);
            }
            split_store_h(xh, xl, e * 64 + (kw ^ ((e & 7) << 2)), v0, v1);
        }
        GBAR(bid);

        float acc[8][4];

        // GEMM1 + GN(g_dist)
#pragma unroll
        for (int t = 0; t < 8; t++) { acc[t][0] = acc[t][1] = acc[t][2] = acc[t][3] = 0.f; }
        gemm_f16split<8>(xh, xl, usm + 0, acc, r0, g, tg, 64 * cb);
        gn_relu_split_store_g(acc, xh, xl, sred, gd, bd, r0, g, tg, cb, bid);

        // GEMM2 (+ qc[hi] + cc[wi] preloaded) + GN(g_c1)
        {
            int h0 = sh[r0], w0i = sw[r0];
            int h1 = sh[r0 + 8], w1i = sw[r0 + 8];
            const float2* pq0 = (h0 >= 0) ? (const float2*)(g_qc + (size_t)h0 * 128) : 0;
            const float2* pc0 = (h0 >= 0) ? (const float2*)(g_cc + (size_t)w0i * 128) : 0;
            const float2* pq1 = (h1 >= 0) ? (const float2*)(g_qc + (size_t)h1 * 128) : 0;
            const float2* pc1 = (h1 >= 0) ? (const float2*)(g_cc + (size_t)w1i * 128) : 0;
#pragma unroll
            for (int t = 0; t < 8; t++) {
                int ci = (64 * cb + 8 * t + 2 * tg) >> 1;
                if (h0 >= 0) {
                    float2 a2 = __ldg(pq0 + ci), b2 = __ldg(pc0 + ci);
                    acc[t][0] = a2.x + b2.x; acc[t][1] = a2.y + b2.y;
                } else { acc[t][0] = acc[t][1] = 0.f; }
                if (h1 >= 0) {
                    float2 a2 = __ldg(pq1 + ci), b2 = __ldg(pc1 + ci);
                    acc[t][2] = a2.x + b2.x; acc[t][3] = a2.y + b2.y;
                } else { acc[t][2] = acc[t][3] = 0.f; }
            }
        }
        gemm_f16split<8>(xh, xl, usm + 8192, acc, r0, g, tg, 64 * cb);
        gn_relu_split_store_g(acc, xh, xl, sred, gc1, bc1, r0, g, tg, cb, bid);

        // GEMM3 + scatter (lane-pair shfl -> red.global.add.v4.f32)
#pragma unroll
        for (int t = 0; t < 8; t++) { acc[t][0] = acc[t][1] = acc[t][2] = acc[t][3] = 0.f; }
        gemm_f16split<8>(xh, xl, usm + 16384, acc, r0, g, tg, 64 * cb);
        {
            int h0 = sh[r0], h1 = sh[r0 + 8];
#pragma unroll
            for (int t = 0; t < 8; t++) {
                float s0 = (tg & 1) ? acc[t][0] : acc[t][2];
                float s1 = (tg & 1) ? acc[t][1] : acc[t][3];
                float p0 = __shfl_xor_sync(0xffffffffu, s0, 1);
                float p1 = __shfl_xor_sync(0xffffffffu, s1, 1);
                if ((tg & 1) == 0) {
                    if (h0 >= 0) {
                        float* p = g_acc + (size_t)h0 * 128 + 64 * cb + 8 * t + 2 * tg;
                        asm volatile("red.global.add.v4.f32 [%0], {%1, %2, %3, %4};"
                                     :: "l"(p), "f"(acc[t][0]), "f"(acc[t][1]), "f"(p0), "f"(p1)
                                     : "memory");
                    }
                } else {
                    if (h1 >= 0) {
                        float* p = g_acc + (size_t)h1 * 128 + 64 * cb + 8 * t + 2 * (tg - 1);
                        asm volatile("red.global.add.v4.f32 [%0], {%1, %2, %3, %4};"
                                     :: "l"(p), "f"(p0), "f"(p1), "f"(acc[t][2]), "f"(acc[t][3])
                                     : "memory");
                    }
                }
            }
        }
        GBAR(bid);
    }
}

// ============================================================
// K4: out = relu(gn(relu(gn(g_acc)) @ Wlin) + agts) — 256 threads, 2 CTAs/SM
// (unchanged)
// ============================================================
__global__ __launch_bounds__(256, 2) void k_final_mma(
    const float* __restrict__ agts,
    const float* __restrict__ gnw, const float* __restrict__ bnw,
    const float* __restrict__ Wlin, const float* __restrict__ gl, const float* __restrict__ bl,
    float* __restrict__ out)
{
    extern __shared__ uint usm[];
    uint* xh = usm + 8192;
    uint* xl = usm + 12288;
    float* sred = (float*)(usm + 16384);
    const int tid = threadIdx.x;

    load_weight_h(Wlin, usm + 0, tid);
    __syncthreads();

    const int lane = tid & 31;
    const int wid = tid >> 5;
    const int g = lane >> 2;
    const int tg = lane & 3;
    const int stripe = wid >> 1;
    const int cb = wid & 1;
    const int r0 = 16 * stripe + g;
    const int arow = tid >> 2;
    const int apart = tid & 3;

    const int NT = (NA + 63) / 64;
    for (int tile = blockIdx.x; tile < NT; tile += gridDim.x) {
        const int row0 = tile * 64;

        // phase A: SIMT GN(g_n)+relu on g_acc rows -> split X smem
        {
            int rowg = row0 + arow;
            float v[32];
            if (rowg < NA) {
                const float4* p = (const float4*)(g_acc + (size_t)rowg * 128 + apart * 32);
#pragma unroll
                for (int q = 0; q < 8; q++) {
                    float4 f = __ldg(p + q);
                    v[4 * q] = f.x; v[4 * q + 1] = f.y; v[4 * q + 2] = f.z; v[4 * q + 3] = f.w;
                }
            } else {
#pragma unroll
                for (int q = 0; q < 32; q++) v[q] = 0.f;
            }
            float s = 0.f, qq = 0.f;
#pragma unroll
            for (int q = 0; q < 32; q++) { s += v[q]; qq += v[q] * v[q]; }
            s += __shfl_xor_sync(0xffffffffu, s, 1);
            qq += __shfl_xor_sync(0xffffffffu, qq, 1);
            s += __shfl_xor_sync(0xffffffffu, s, 2);
            qq += __shfl_xor_sync(0xffffffffu, qq, 2);
            float mu = s * 0.0078125f;
            float rs = rsqrtf(qq * 0.0078125f - mu * mu + 1e-5f);
            int sw4 = (arow & 7) << 2;
#pragma unroll
            for (int j = 0; j < 16; j++) {
                int c = apart * 32 + 2 * j;
                float e0 = fmaxf((v[2 * j] - mu) * rs * __ldg(gnw + c) + __ldg(bnw + c), 0.f);
                float e1 = fmaxf((v[2 * j + 1] - mu) * rs * __ldg(gnw + c + 1) + __ldg(bnw + c + 1), 0.f);
                int kw = apart * 16 + j;
                split_store_h(xh, xl, arow * 64 + (kw ^ sw4), e0, e1);
            }
        }
        __syncthreads();

        // GEMM Wlin
        float acc[8][4];
#pragma unroll
        for (int t = 0; t < 8; t++) { acc[t][0] = acc[t][1] = acc[t][2] = acc[t][3] = 0.f; }
        gemm_f16split<8>(xh, xl, usm + 0, acc, r0, g, tg, 64 * cb);

        // GN(g_lin) (no relu) + residual + relu -> out
        {
            float s0 = 0, q0 = 0, s1 = 0, q1 = 0;
#pragma unroll
            for (int t = 0; t < 8; t++) {
                s0 += acc[t][0] + acc[t][1];
                q0 += acc[t][0] * acc[t][0] + acc[t][1] * acc[t][1];
                s1 += acc[t][2] + acc[t][3];
                q1 += acc[t][2] * acc[t][2] + acc[t][3] * acc[t][3];
            }
#pragma unroll
            for (int o = 1; o <= 2; o <<= 1) {
                s0 += __shfl_xor_sync(0xffffffffu, s0, o);
                q0 += __shfl_xor_sync(0xffffffffu, q0, o);
                s1 += __shfl_xor_sync(0xffffffffu, s1, o);
                q1 += __shfl_xor_sync(0xffffffffu, q1, o);
            }
            if (tg == 0) {
                sred[(r0 * 2 + cb) * 2 + 0] = s0;
                sred[(r0 * 2 + cb) * 2 + 1] = q0;
                sred[((r0 + 8) * 2 + cb) * 2 + 0] = s1;
                sred[((r0 + 8) * 2 + cb) * 2 + 1] = q1;
            }
            __syncthreads();
            float sa = sred[(r0 * 2) * 2 + 0] + sred[(r0 * 2 + 1) * 2 + 0];
            float qa = sred[(r0 * 2) * 2 + 1] + sred[(r0 * 2 + 1) * 2 + 1];
            float sb = sred[((r0 + 8) * 2) * 2 + 0] + sred[((r0 + 8) * 2 + 1) * 2 + 0];
            float qb = sred[((r0 + 8) * 2) * 2 + 1] + sred[((r0 + 8) * 2 + 1) * 2 + 1];
            float mu0 = sa * 0.0078125f;
            float rs0 = rsqrtf(qa * 0.0078125f - mu0 * mu0 + 1e-5f);
            float mu1 = sb * 0.0078125f;
            float rs1 = rsqrtf(qb * 0.0078125f - mu1 * mu1 + 1e-5f);
            int rowA = row0 + r0, rowB = row0 + r0 + 8;
#pragma unroll
            for (int t = 0; t < 8; t++) {
                int col0 = 64 * cb + 8 * t + 2 * tg;
                float ga = __ldg(gl + col0), gb = __ldg(gl + col0 + 1);
                float ba = __ldg(bl + col0), bb = __ldg(bl + col0 + 1);
                if (rowA < NA) {
                    float2 res = __ldg((const float2*)(agts + (size_t)rowA * 128) + (col0 >> 1));
                    float y0 = fmaxf((acc[t][0] - mu0) * rs0 * ga + ba + res.x, 0.f);
                    float y1 = fmaxf((acc[t][1] - mu0) * rs0 * gb + bb + res.y, 0.f);
                    *(float2*)(out + (size_t)rowA * 128 + col0) = make_float2(y0, y1);
                }
                if (rowB < NA) {
                    float2 res = __ldg((const float2*)(agts + (size_t)rowB * 128) + (col0 >> 1));
                    float y2 = fmaxf((acc[t][2] - mu1) * rs1 * ga + ba + res.x, 0.f);
                    float y3 = fmaxf((acc[t][3] - mu1) * rs1 * gb + bb + res.y, 0.f);
                    *(float2*)(out + (size_t)rowB * 128 + col0) = make_float2(y2, y3);
                }
            }
        }
        __syncthreads();
    }
}

// ================= host =================
extern "C" void kernel_launch(void* const* d_in, const int* in_sizes, int n_in,
                              void* d_out, int out_size)
{
    const float* agts    = (const float*)d_in[0];
    const float* ctx     = (const float*)d_in[1];
    const float* actr    = (const float*)d_in[2];
    const float* cctr    = (const float*)d_in[3];
    const float* W_dist1 = (const float*)d_in[4];
    const float* b_dist1 = (const float*)d_in[5];
    const float* W_dist2 = (const float*)d_in[6];
    const float* g_dist  = (const float*)d_in[7];
    const float* b_dist  = (const float*)d_in[8];
    const float* W_q     = (const float*)d_in[9];
    const float* g_q     = (const float*)d_in[10];
    const float* b_q     = (const float*)d_in[11];
    const float* W_c1    = (const float*)d_in[12];
    const float* g_c1    = (const float*)d_in[13];
    const float* b_c1    = (const float*)d_in[14];
    const float* W_c2    = (const float*)d_in[15];
    const float* W_agt   = (const float*)d_in[16];
    const float* g_n     = (const float*)d_in[17];
    const float* b_n     = (const float*)d_in[18];
    const float* W_lin   = (const float*)d_in[19];
    const float* g_lin   = (const float*)d_in[20];
    const float* b_lin   = (const float*)d_in[21];
    const int*   hi      = (const int*)d_in[22];
    const int*   wi      = (const int*)d_in[23];
    float* out = (float*)d_out;

    const int S0 = 49664 * 4;   // k_pre_mma   (198656 B)
    const int S3 = 41728 * 4;   // k_edge_mma  (166912 B)
    const int S4 = 16640 * 4;   // k_final_mma (66560 B)
    cudaFuncSetAttribute(k_pre_mma,   cudaFuncAttributeMaxDynamicSharedMemorySize, S0);
    cudaFuncSetAttribute(k_edge_mma,  cudaFuncAttributeMaxDynamicSharedMemorySize, S3);
    cudaFuncSetAttribute(k_final_mma, cudaFuncAttributeMaxDynamicSharedMemorySize, S4);

    k_pre_mma <<<152, 512, S0>>>(agts, ctx, W_q, g_q, b_q,
                                 W_c1 + 128 * 128, W_agt, W_c1 + 256 * 128);
    k_edge_mma<<<152, 512, S3>>>(actr, cctr, hi, wi,
                                 W_dist1, b_dist1, W_dist2, g_dist, b_dist,
                                 W_c1, g_c1, b_c1, W_c2);
    k_final_mma<<<304, 256, S4>>>(agts, g_n, b_n, W_lin, g_lin, b_lin, out);
}